// round 3
// baseline (speedup 1.0000x reference)
#include <cuda_runtime.h>
#include <math.h>

#define NN 50000
#define NP 4
#define NE 800000
#define D 256
#define DH 128
#define NND (NN * D)
#define NROWS (NP * NN)

// ---------------- scratch (device globals; no allocation allowed) ----------
__device__ float g_xw[NND];            // per-path x@W (reused serially)
__device__ float g_z[NP * NND];        // GCN outputs, all paths
__device__ float g_h[NROWS * DH];      // tanh(Z@W1+b1)
__device__ float g_wlog[NROWS];        // attention logits
__device__ int   g_deg[NN];
__device__ float g_dinv[NN];
__device__ int   g_rowoff[NN + 1];
__device__ int   g_rowcur[NN];
__device__ int   g_srcs[NE];

// ---------------- generic tiled SGEMM: C = op(A@B + bias) ------------------
// BM=64, BN=64, BK=16, 256 threads, 4x4 per thread.
__global__ void k_gemm(const float* __restrict__ A, const float* __restrict__ B,
                       const float* __restrict__ bias, float* __restrict__ C,
                       int M, int N, int K, int tanh_flag) {
    __shared__ float As[64][17];   // As[m][k]
    __shared__ float Bs[16][68];   // Bs[k][n]

    int tid = threadIdx.x;
    int tx = tid & 15;
    int ty = tid >> 4;
    int bm = blockIdx.y * 64;
    int bn = blockIdx.x * 64;

    int arow = tid >> 2;            // 0..63
    int acol = (tid & 3) * 4;       // 0,4,8,12
    int brow = tid >> 4;            // 0..15
    int bcol = (tid & 15) * 4;      // 0..60

    float acc[4][4] = {};

    for (int k0 = 0; k0 < K; k0 += 16) {
        float4 av = make_float4(0.f, 0.f, 0.f, 0.f);
        if (bm + arow < M)
            av = *(const float4*)&A[(size_t)(bm + arow) * K + k0 + acol];
        As[arow][acol + 0] = av.x;
        As[arow][acol + 1] = av.y;
        As[arow][acol + 2] = av.z;
        As[arow][acol + 3] = av.w;

        float4 bv = *(const float4*)&B[(size_t)(k0 + brow) * N + bn + bcol];
        *(float4*)&Bs[brow][bcol] = bv;

        __syncthreads();

#pragma unroll
        for (int kk = 0; kk < 16; kk++) {
            float4 b4 = *(float4*)&Bs[kk][tx * 4];
            float a0 = As[ty * 4 + 0][kk];
            float a1 = As[ty * 4 + 1][kk];
            float a2 = As[ty * 4 + 2][kk];
            float a3 = As[ty * 4 + 3][kk];
            acc[0][0] += a0 * b4.x; acc[0][1] += a0 * b4.y; acc[0][2] += a0 * b4.z; acc[0][3] += a0 * b4.w;
            acc[1][0] += a1 * b4.x; acc[1][1] += a1 * b4.y; acc[1][2] += a1 * b4.z; acc[1][3] += a1 * b4.w;
            acc[2][0] += a2 * b4.x; acc[2][1] += a2 * b4.y; acc[2][2] += a2 * b4.z; acc[2][3] += a2 * b4.w;
            acc[3][0] += a3 * b4.x; acc[3][1] += a3 * b4.y; acc[3][2] += a3 * b4.z; acc[3][3] += a3 * b4.w;
        }
        __syncthreads();
    }

#pragma unroll
    for (int i = 0; i < 4; i++) {
        int row = bm + ty * 4 + i;
        if (row < M) {
#pragma unroll
            for (int j = 0; j < 4; j++) {
                int col = bn + tx * 4 + j;
                float v = acc[i][j];
                if (bias) v += bias[col];
                if (tanh_flag) v = tanhf(v);
                C[(size_t)row * N + col] = v;
            }
        }
    }
}

// ---------------- GCN aggregation pipeline ---------------------------------
__global__ void k_deg_init() {
    int i = blockIdx.x * 256 + threadIdx.x;
    if (i < NN) g_deg[i] = 1;   // self loop
}

__global__ void k_hist(const int* __restrict__ dst) {
    int e = blockIdx.x * 256 + threadIdx.x;
    if (e < NE) atomicAdd(&g_deg[dst[e]], 1);
}

// single-block scan: rowoff = exclusive scan of (deg-1); dinv = rsqrt(deg)
__global__ void k_scan() {
    __shared__ int s[1024];
    int tid = threadIdx.x;
    const int CH = 49;   // 1024*49 >= 50000
    int base = tid * CH;
    int local = 0;
    for (int i = 0; i < CH; i++) {
        int idx = base + i;
        if (idx < NN) local += g_deg[idx] - 1;
    }
    s[tid] = local;
    __syncthreads();
    for (int off = 1; off < 1024; off <<= 1) {
        int v = 0;
        if (tid >= off) v = s[tid - off];
        __syncthreads();
        s[tid] += v;
        __syncthreads();
    }
    int run = s[tid] - local;   // exclusive
    for (int i = 0; i < CH; i++) {
        int idx = base + i;
        if (idx < NN) {
            int d = g_deg[idx];
            g_rowoff[idx] = run;
            g_rowcur[idx] = run;
            g_dinv[idx] = rsqrtf((float)d);
            run += d - 1;
        }
    }
    if (tid == 1023) g_rowoff[NN] = s[1023];
}

__global__ void k_fill(const int* __restrict__ src, const int* __restrict__ dst) {
    int e = blockIdx.x * 256 + threadIdx.x;
    if (e < NE) {
        int d = dst[e];
        int pos = atomicAdd(&g_rowcur[d], 1);
        g_srcs[pos] = src[e];
    }
}

// pull: one warp per dst node; 8 dims per lane; atomic-free accumulate
__global__ void k_pull(const float* __restrict__ bs, int p) {
    int node = blockIdx.x * 8 + (threadIdx.x >> 5);
    if (node >= NN) return;
    int lane = threadIdx.x & 31;

    float di = g_dinv[node];
    const float* xwn = g_xw + (size_t)node * D;
    float acc[8];
#pragma unroll
    for (int k = 0; k < 8; k++) acc[k] = di * di * xwn[k * 32 + lane];

    int beg = g_rowoff[node];
    int end = g_rowoff[node + 1];
    for (int e = beg; e < end; e++) {
        int s = g_srcs[e];
        float nrm = di * g_dinv[s];
        const float* xs = g_xw + (size_t)s * D;
#pragma unroll
        for (int k = 0; k < 8; k++) acc[k] += nrm * xs[k * 32 + lane];
    }

    float* zp = g_z + (size_t)p * NND + (size_t)node * D;
    const float* bp = bs + p * D;
#pragma unroll
    for (int k = 0; k < 8; k++) zp[k * 32 + lane] = acc[k] + bp[k * 32 + lane];
}

// ---------------- attention tail -------------------------------------------
__global__ void k_dot(const float* __restrict__ w2) {
    int row = blockIdx.x * 8 + (threadIdx.x >> 5);
    if (row >= NROWS) return;
    int lane = threadIdx.x & 31;
    const float* h = g_h + (size_t)row * DH;
    float s = h[lane]      * w2[lane]
            + h[lane + 32] * w2[lane + 32]
            + h[lane + 64] * w2[lane + 64]
            + h[lane + 96] * w2[lane + 96];
#pragma unroll
    for (int o = 16; o; o >>= 1) s += __shfl_xor_sync(0xffffffffu, s, o);
    if (lane == 0) g_wlog[row] = s;
}

__global__ void k_combine(float* __restrict__ out) {
    int i = blockIdx.x * 256 + threadIdx.x;
    if (i >= NND) return;
    int node = i >> 8;
    float w0 = g_wlog[node];
    float w1 = g_wlog[NN + node];
    float w2 = g_wlog[2 * NN + node];
    float w3 = g_wlog[3 * NN + node];
    float m = fmaxf(fmaxf(w0, w1), fmaxf(w2, w3));
    float e0 = __expf(w0 - m), e1 = __expf(w1 - m), e2 = __expf(w2 - m), e3 = __expf(w3 - m);
    float inv = 1.0f / (e0 + e1 + e2 + e3);
    out[i] = (e0 * g_z[i] + e1 * g_z[NND + i] + e2 * g_z[2 * NND + i] + e3 * g_z[3 * NND + i]) * inv;
}

// ---------------- launch ----------------------------------------------------
extern "C" void kernel_launch(void* const* d_in, const int* in_sizes, int n_in,
                              void* d_out, int out_size) {
    const float* x    = (const float*)d_in[0];
    const int*   eidx = (const int*)d_in[1];
    const float* Ws   = (const float*)d_in[2];
    const float* bs   = (const float*)d_in[3];
    const float* w1   = (const float*)d_in[4];
    const float* b1   = (const float*)d_in[5];
    const float* w2   = (const float*)d_in[6];
    float* out = (float*)d_out;

    void* p_xw = nullptr; void* p_z = nullptr; void* p_h = nullptr;
    cudaGetSymbolAddress(&p_xw, g_xw);
    cudaGetSymbolAddress(&p_z,  g_z);
    cudaGetSymbolAddress(&p_h,  g_h);

    for (int p = 0; p < NP; p++) {
        const int* src = eidx + (size_t)p * 2 * NE;
        const int* dst = src + NE;

        // xw = x @ W_p   (bias added later in pull)
        k_gemm<<<dim3(D / 64, (NN + 63) / 64), 256>>>(
            x, Ws + (size_t)p * D * D, nullptr, (float*)p_xw, NN, D, D, 0);

        k_deg_init<<<(NN + 255) / 256, 256>>>();
        k_hist<<<(NE + 255) / 256, 256>>>(dst);
        k_scan<<<1, 1024>>>();
        k_fill<<<(NE + 255) / 256, 256>>>(src, dst);
        k_pull<<<(NN + 7) / 8, 256>>>(bs, p);
    }

    // H = tanh(Z @ W1 + b1)   [200000 x 128]
    k_gemm<<<dim3(DH / 64, NROWS / 64), 256>>>(
        (const float*)p_z, w1, b1, (float*)p_h, NROWS, DH, D, 1);

    k_dot<<<(NROWS + 7) / 8, 256>>>(w2);
    k_combine<<<(NND + 255) / 256, 256>>>(out);
}

// round 4
// speedup vs baseline: 1.5163x; 1.5163x over previous
#include <cuda_runtime.h>
#include <math.h>

#define NN 50000
#define NP 4
#define NE 800000
#define D 256
#define DH 128
#define NND (NN * D)
#define NROWS (NP * NN)
#define NG (NP * NN)              // total (path,node) rows = 200000
#define SCAN_BLK 391              // ceil(200000/512)

// ---------------- scratch (device globals; no allocation allowed) ----------
__device__ float g_xw[NP * NND];       // [p][node][256] x@W_p
__device__ float g_z[NP * NND];        // GCN outputs [p][node][256]
__device__ float g_h[NROWS * DH];      // tanh(Z@W1+b1)
__device__ float g_wlog[NROWS];        // attention logits
__device__ int   g_deg[NG];
__device__ float g_dinv[NG];
__device__ int   g_rowoff[NG + 1];
__device__ int   g_rowcur[NG];
__device__ int   g_srcs[NP * NE];
__device__ int   g_part[SCAN_BLK];

// ---------------- SGEMM: 128x128x16, 256 thr, 8x8/thread, double-buffered --
// C[z] = op(A @ B[z] + bias), z strides for batched-B/C. M guarded; N,K must
// be multiples of 128/16 (true here: N in {256,128}, K=256).
__global__ void __launch_bounds__(256, 2) k_gemm(
    const float* __restrict__ A, const float* __restrict__ B,
    const float* __restrict__ bias, float* __restrict__ C,
    int M, int N, int K, long long sB, long long sC, int tanh_flag)
{
    B += (long long)blockIdx.z * sB;
    C += (long long)blockIdx.z * sC;

    __shared__ float As[2][16][132];   // [k][m], padded
    __shared__ float Bs[2][16][132];   // [k][n], padded

    const int tid = threadIdx.x;
    const int tx = tid & 15;
    const int ty = tid >> 4;
    const int bm = blockIdx.y * 128;
    const int bn = blockIdx.x * 128;

    const int arow = tid >> 1;            // 0..127
    const int acol = (tid & 1) * 8;       // 0 or 8
    const int brow = tid >> 5;            // 0..7
    const int bcol = (tid & 31) * 4;      // 0..124

    const bool aval = (bm + arow) < M;
    const float* Ap = A + (long long)(bm + arow) * K + acol;
    const float* Bp = B + (long long)brow * N + bn + bcol;
    const long long bstep8 = 8LL * N;

    float acc[8][8] = {};
    float4 a0 = make_float4(0.f, 0.f, 0.f, 0.f), a1 = a0, b0, b1;

    // preload tile 0
    if (aval) { a0 = *(const float4*)Ap; a1 = *(const float4*)(Ap + 4); }
    b0 = *(const float4*)Bp;
    b1 = *(const float4*)(Bp + bstep8);
    As[0][acol + 0][arow] = a0.x; As[0][acol + 1][arow] = a0.y;
    As[0][acol + 2][arow] = a0.z; As[0][acol + 3][arow] = a0.w;
    As[0][acol + 4][arow] = a1.x; As[0][acol + 5][arow] = a1.y;
    As[0][acol + 6][arow] = a1.z; As[0][acol + 7][arow] = a1.w;
    *(float4*)&Bs[0][brow][bcol] = b0;
    *(float4*)&Bs[0][brow + 8][bcol] = b1;
    __syncthreads();

    const int ntiles = K >> 4;
    for (int t = 0; t < ntiles; t++) {
        const int buf = t & 1;
        if (t + 1 < ntiles) {                       // prefetch next tile -> regs
            const float* Ap2 = Ap + (t + 1) * 16;
            if (aval) { a0 = *(const float4*)Ap2; a1 = *(const float4*)(Ap2 + 4); }
            const float* Bp2 = Bp + (long long)(t + 1) * 16 * N;
            b0 = *(const float4*)Bp2;
            b1 = *(const float4*)(Bp2 + bstep8);
        }
#pragma unroll
        for (int kk = 0; kk < 16; kk++) {
            float a[8], b[8];
            *(float4*)&a[0] = *(const float4*)&As[buf][kk][ty * 8];
            *(float4*)&a[4] = *(const float4*)&As[buf][kk][ty * 8 + 4];
            *(float4*)&b[0] = *(const float4*)&Bs[buf][kk][tx * 8];
            *(float4*)&b[4] = *(const float4*)&Bs[buf][kk][tx * 8 + 4];
#pragma unroll
            for (int i = 0; i < 8; i++)
#pragma unroll
                for (int j = 0; j < 8; j++)
                    acc[i][j] = fmaf(a[i], b[j], acc[i][j]);
        }
        if (t + 1 < ntiles) {                       // stage regs -> other buffer
            const int nb = buf ^ 1;
            As[nb][acol + 0][arow] = a0.x; As[nb][acol + 1][arow] = a0.y;
            As[nb][acol + 2][arow] = a0.z; As[nb][acol + 3][arow] = a0.w;
            As[nb][acol + 4][arow] = a1.x; As[nb][acol + 5][arow] = a1.y;
            As[nb][acol + 6][arow] = a1.z; As[nb][acol + 7][arow] = a1.w;
            *(float4*)&Bs[nb][brow][bcol] = b0;
            *(float4*)&Bs[nb][brow + 8][bcol] = b1;
            __syncthreads();
        }
    }

#pragma unroll
    for (int i = 0; i < 8; i++) {
        int row = bm + ty * 8 + i;
        if (row < M) {
#pragma unroll
            for (int jj = 0; jj < 8; jj += 4) {
                int col = bn + tx * 8 + jj;
                float4 v;
                v.x = acc[i][jj + 0]; v.y = acc[i][jj + 1];
                v.z = acc[i][jj + 2]; v.w = acc[i][jj + 3];
                if (bias) {
                    v.x += bias[col + 0]; v.y += bias[col + 1];
                    v.z += bias[col + 2]; v.w += bias[col + 3];
                }
                if (tanh_flag) {
                    v.x = tanhf(v.x); v.y = tanhf(v.y);
                    v.z = tanhf(v.z); v.w = tanhf(v.w);
                }
                *(float4*)&C[(long long)row * N + col] = v;
            }
        }
    }
}

// ---------------- GCN aggregation pipeline (all 4 paths batched) -----------
__global__ void k_deg_init() {
    int i = blockIdx.x * 256 + threadIdx.x;
    if (i < NG) g_deg[i] = 1;   // self loop
}

__global__ void k_hist(const int* __restrict__ eidx) {
    int e = blockIdx.x * 256 + threadIdx.x;
    if (e < NP * NE) {
        int p = e / NE, i = e - p * NE;
        int dst = eidx[(size_t)p * 2 * NE + NE + i];
        atomicAdd(&g_deg[p * NN + dst], 1);
    }
}

// phase 1: per-block partial sums of (deg-1), 512 elems/block
__global__ void k_scan1() {
    __shared__ int red[8];
    int b = blockIdx.x, tid = threadIdx.x;
    int lane = tid & 31, warp = tid >> 5;
    int i0 = b * 512 + tid * 2;
    int s = 0;
    if (i0 < NG)     s += g_deg[i0] - 1;
    if (i0 + 1 < NG) s += g_deg[i0 + 1] - 1;
#pragma unroll
    for (int o = 16; o; o >>= 1) s += __shfl_xor_sync(0xffffffffu, s, o);
    if (lane == 0) red[warp] = s;
    __syncthreads();
    if (tid == 0) {
        int t = 0;
#pragma unroll
        for (int w = 0; w < 8; w++) t += red[w];
        g_part[b] = t;
    }
}

// phase 2: exclusive scan of the 391 partials (single block)
__global__ void k_scan2() {
    __shared__ int s[512];
    int tid = threadIdx.x;
    int v = (tid < SCAN_BLK) ? g_part[tid] : 0;
    s[tid] = v;
    __syncthreads();
    for (int off = 1; off < 512; off <<= 1) {
        int u = (tid >= off) ? s[tid - off] : 0;
        __syncthreads();
        s[tid] += u;
        __syncthreads();
    }
    if (tid < SCAN_BLK) g_part[tid] = s[tid] - v;   // exclusive
}

// phase 3: intra-block exclusive scan + base; emit rowoff/rowcur/dinv
__global__ void k_scan3() {
    __shared__ int wsum[8];
    int b = blockIdx.x, tid = threadIdx.x;
    int lane = tid & 31, warp = tid >> 5;
    int i0 = b * 512 + tid * 2;
    int d0 = (i0 < NG) ? g_deg[i0] : 1;
    int d1 = (i0 + 1 < NG) ? g_deg[i0 + 1] : 1;
    int v0 = d0 - 1, v1 = d1 - 1;
    int s = v0 + v1;
    int sc = s;                                   // inclusive warp scan
#pragma unroll
    for (int o = 1; o < 32; o <<= 1) {
        int u = __shfl_up_sync(0xffffffffu, sc, o);
        if (lane >= o) sc += u;
    }
    if (lane == 31) wsum[warp] = sc;
    __syncthreads();
    int wbase = 0;
    for (int w = 0; w < warp; w++) wbase += wsum[w];
    int base = g_part[b] + wbase + (sc - s);      // exclusive within grid
    if (i0 < NG) {
        g_rowoff[i0] = base; g_rowcur[i0] = base;
        g_dinv[i0] = rsqrtf((float)d0);
    }
    if (i0 + 1 < NG) {
        g_rowoff[i0 + 1] = base + v0; g_rowcur[i0 + 1] = base + v0;
        g_dinv[i0 + 1] = rsqrtf((float)d1);
    }
    if (b == 0 && tid == 0) g_rowoff[NG] = NP * NE;
}

__global__ void k_fill(const int* __restrict__ eidx) {
    int e = blockIdx.x * 256 + threadIdx.x;
    if (e < NP * NE) {
        int p = e / NE, i = e - p * NE;
        int src = eidx[(size_t)p * 2 * NE + i];
        int dst = eidx[(size_t)p * 2 * NE + NE + i];
        int pos = atomicAdd(&g_rowcur[p * NN + dst], 1);
        g_srcs[pos] = src;
    }
}

// pull: one warp per (path,node); 8 dims per lane; atomic-free accumulate
__global__ void k_pull(const float* __restrict__ bs) {
    int g = blockIdx.x * 8 + (threadIdx.x >> 5);
    if (g >= NG) return;
    int lane = threadIdx.x & 31;
    int p = g / NN, node = g - p * NN;

    float di = g_dinv[g];
    const float* xwp = g_xw + (size_t)p * NND;
    const float* xwn = xwp + (size_t)node * D;
    float acc[8];
#pragma unroll
    for (int k = 0; k < 8; k++) acc[k] = di * di * xwn[k * 32 + lane];

    int beg = g_rowoff[g];
    int end = g_rowoff[g + 1];
    const float* dv = g_dinv + p * NN;
    for (int e = beg; e < end; e++) {
        int s = g_srcs[e];
        float nrm = di * dv[s];
        const float* xs = xwp + (size_t)s * D;
#pragma unroll
        for (int k = 0; k < 8; k++) acc[k] += nrm * xs[k * 32 + lane];
    }

    float* zp = g_z + (size_t)g * D;
    const float* bp = bs + p * D;
#pragma unroll
    for (int k = 0; k < 8; k++) zp[k * 32 + lane] = acc[k] + bp[k * 32 + lane];
}

// ---------------- attention tail -------------------------------------------
__global__ void k_dot(const float* __restrict__ w2) {
    int row = blockIdx.x * 8 + (threadIdx.x >> 5);
    if (row >= NROWS) return;
    int lane = threadIdx.x & 31;
    const float* h = g_h + (size_t)row * DH;
    float s = h[lane]      * w2[lane]
            + h[lane + 32] * w2[lane + 32]
            + h[lane + 64] * w2[lane + 64]
            + h[lane + 96] * w2[lane + 96];
#pragma unroll
    for (int o = 16; o; o >>= 1) s += __shfl_xor_sync(0xffffffffu, s, o);
    if (lane == 0) g_wlog[row] = s;
}

__global__ void k_combine(float* __restrict__ out) {
    int i = blockIdx.x * 256 + threadIdx.x;
    if (i >= NND) return;
    int node = i >> 8;
    float w0 = g_wlog[node];
    float w1 = g_wlog[NN + node];
    float w2 = g_wlog[2 * NN + node];
    float w3 = g_wlog[3 * NN + node];
    float m = fmaxf(fmaxf(w0, w1), fmaxf(w2, w3));
    float e0 = __expf(w0 - m), e1 = __expf(w1 - m), e2 = __expf(w2 - m), e3 = __expf(w3 - m);
    float inv = 1.0f / (e0 + e1 + e2 + e3);
    out[i] = (e0 * g_z[i] + e1 * g_z[NND + i] + e2 * g_z[2 * NND + i] + e3 * g_z[3 * NND + i]) * inv;
}

// ---------------- launch ----------------------------------------------------
extern "C" void kernel_launch(void* const* d_in, const int* in_sizes, int n_in,
                              void* d_out, int out_size) {
    const float* x    = (const float*)d_in[0];
    const int*   eidx = (const int*)d_in[1];
    const float* Ws   = (const float*)d_in[2];
    const float* bs   = (const float*)d_in[3];
    const float* w1   = (const float*)d_in[4];
    const float* b1   = (const float*)d_in[5];
    const float* w2   = (const float*)d_in[6];
    float* out = (float*)d_out;

    void* p_xw = nullptr; void* p_z = nullptr; void* p_h = nullptr;
    cudaGetSymbolAddress(&p_xw, g_xw);
    cudaGetSymbolAddress(&p_z,  g_z);
    cudaGetSymbolAddress(&p_h,  g_h);

    // xw[p] = x @ W_p  (all 4 paths in one batched launch; bias added in pull)
    k_gemm<<<dim3(D / 128, (NN + 127) / 128, NP), 256>>>(
        x, Ws, nullptr, (float*)p_xw, NN, D, D,
        (long long)D * D, (long long)NND, 0);

    // CSR build for all 4 paths at once
    k_deg_init<<<(NG + 255) / 256, 256>>>();
    k_hist<<<(NP * NE + 255) / 256, 256>>>(eidx);
    k_scan1<<<SCAN_BLK, 256>>>();
    k_scan2<<<1, 512>>>();
    k_scan3<<<SCAN_BLK, 256>>>();
    k_fill<<<(NP * NE + 255) / 256, 256>>>(eidx);
    k_pull<<<(NG + 7) / 8, 256>>>(bs);

    // H = tanh(Z @ W1 + b1)   [200000 x 128]
    k_gemm<<<dim3(DH / 128, (NROWS + 127) / 128, 1), 256>>>(
        (const float*)p_z, w1, b1, (float*)p_h, NROWS, DH, D, 0, 0, 1);

    k_dot<<<(NROWS + 7) / 8, 256>>>(w2);
    k_combine<<<(NND + 255) / 256, 256>>>(out);
}

// round 5
// speedup vs baseline: 2.3889x; 1.5755x over previous
#include <cuda_runtime.h>
#include <math.h>
#include <stdint.h>

#define NN 50000
#define NP 4
#define NE 800000
#define D 256
#define DH 128
#define NND (NN * D)
#define NROWS (NP * NN)
#define NG (NP * NN)              // total (path,node) rows = 200000
#define SCAN_BLK 391              // ceil(200000/512)

// ---------------- scratch (device globals; no allocation allowed) ----------
__device__ float g_xw[NP * NND];       // [p][node][256] x@W_p
__device__ float g_z[NP * NND];        // GCN outputs [p][node][256]
__device__ float g_h[NROWS * DH];      // tanh(Z@W1+b1)
__device__ float g_wlog[NROWS];        // attention logits
__device__ int   g_deg[NG];
__device__ float g_dinv[NG];
__device__ int   g_rowoff[NG + 1];
__device__ int   g_rowcur[NG];
__device__ int   g_srcs[NP * NE];
__device__ int   g_part[SCAN_BLK];

// ---------------- tf32 helpers ---------------------------------------------
__device__ __forceinline__ uint32_t f2tf32(float f) {
    uint32_t u;
    asm("cvt.rna.tf32.f32 %0, %1;" : "=r"(u) : "f"(f));
    return u;
}

__device__ __forceinline__ void mma_tf32(float* d, const uint32_t* a,
                                         const uint32_t* b) {
    asm volatile(
        "mma.sync.aligned.m16n8k8.row.col.f32.tf32.tf32.f32 "
        "{%0,%1,%2,%3}, {%4,%5,%6,%7}, {%8,%9}, {%0,%1,%2,%3};\n"
        : "+f"(d[0]), "+f"(d[1]), "+f"(d[2]), "+f"(d[3])
        : "r"(a[0]), "r"(a[1]), "r"(a[2]), "r"(a[3]),
          "r"(b[0]), "r"(b[1]));
}

// ---------------- tf32 tensor-core GEMM: 128x128 block, BK=16 --------------
// C[z] = op(A @ B[z] + bias). 8 warps in 2(M)x4(N); warp tile 64x32;
// per warp 4x4 frags of m16n8k8. A staged as As[m][k] (k-pitch 20,
// conflict-free frag loads), B as Bs[k][n] (n-pitch 136, conflict-free).
// N, K multiples of 128/16; M guarded.
__global__ void __launch_bounds__(256, 2) k_gemm_tc(
    const float* __restrict__ A, const float* __restrict__ B,
    const float* __restrict__ bias, float* __restrict__ C,
    int M, int N, int K, long long sB, long long sC, int tanh_flag)
{
    B += (long long)blockIdx.z * sB;
    C += (long long)blockIdx.z * sC;

    __shared__ uint32_t As[2][128][20];   // [m][k], pitch 20
    __shared__ uint32_t Bs[2][16][136];   // [k][n], pitch 136

    const int tid  = threadIdx.x;
    const int lane = tid & 31;
    const int warp = tid >> 5;
    const int wm = warp & 1;              // 0..1 -> 64 rows each
    const int wn = warp >> 1;             // 0..3 -> 32 cols each
    const int grp = lane >> 2;            // 0..7
    const int tig = lane & 3;             // 0..3
    const int bm = blockIdx.y * 128;
    const int bn = blockIdx.x * 128;

    // A loader: thread -> row tid/2, k-half (tid&1)*8  (2x float4, coalesced)
    const int arow = tid >> 1;
    const int akb  = (tid & 1) * 8;
    const bool aval = (bm + arow) < M;
    const float* Ap = A + (long long)(bm + arow) * K + akb;

    // B loader: thread -> k-row tid/16, n-chunk (tid&15)*8 (2x float4)
    const int brow = tid >> 4;
    const int bnb  = (tid & 15) * 8;
    const float* Bp = B + (long long)brow * N + bn + bnb;

    float acc[4][4][4] = {};
    float4 av0 = make_float4(0.f,0.f,0.f,0.f), av1 = av0, bv0, bv1;

    // preload tile 0
    if (aval) { av0 = *(const float4*)Ap; av1 = *(const float4*)(Ap + 4); }
    bv0 = *(const float4*)Bp;
    bv1 = *(const float4*)(Bp + 4);
    {
        uint4 ua0 = make_uint4(f2tf32(av0.x), f2tf32(av0.y), f2tf32(av0.z), f2tf32(av0.w));
        uint4 ua1 = make_uint4(f2tf32(av1.x), f2tf32(av1.y), f2tf32(av1.z), f2tf32(av1.w));
        *(uint4*)&As[0][arow][akb]     = ua0;
        *(uint4*)&As[0][arow][akb + 4] = ua1;
        uint4 ub0 = make_uint4(f2tf32(bv0.x), f2tf32(bv0.y), f2tf32(bv0.z), f2tf32(bv0.w));
        uint4 ub1 = make_uint4(f2tf32(bv1.x), f2tf32(bv1.y), f2tf32(bv1.z), f2tf32(bv1.w));
        *(uint4*)&Bs[0][brow][bnb]     = ub0;
        *(uint4*)&Bs[0][brow][bnb + 4] = ub1;
    }
    __syncthreads();

    const int ntiles = K >> 4;
    for (int t = 0; t < ntiles; t++) {
        const int buf = t & 1;
        if (t + 1 < ntiles) {                 // prefetch next tile -> regs
            const float* Ap2 = Ap + (t + 1) * 16;
            if (aval) { av0 = *(const float4*)Ap2; av1 = *(const float4*)(Ap2 + 4); }
            const float* Bp2 = Bp + (long long)(t + 1) * 16 * N;
            bv0 = *(const float4*)Bp2;
            bv1 = *(const float4*)(Bp2 + 4);
        }

#pragma unroll
        for (int kb = 0; kb < 16; kb += 8) {
            uint32_t afr[4][4], bfr[4][2];
#pragma unroll
            for (int mi = 0; mi < 4; mi++) {
                const int mb = wm * 64 + mi * 16;
                afr[mi][0] = As[buf][mb + grp][kb + tig];
                afr[mi][1] = As[buf][mb + grp + 8][kb + tig];
                afr[mi][2] = As[buf][mb + grp][kb + tig + 4];
                afr[mi][3] = As[buf][mb + grp + 8][kb + tig + 4];
            }
#pragma unroll
            for (int ni = 0; ni < 4; ni++) {
                const int nb2 = wn * 32 + ni * 8;
                bfr[ni][0] = Bs[buf][kb + tig][nb2 + grp];
                bfr[ni][1] = Bs[buf][kb + tig + 4][nb2 + grp];
            }
#pragma unroll
            for (int mi = 0; mi < 4; mi++)
#pragma unroll
                for (int ni = 0; ni < 4; ni++)
                    mma_tf32(acc[mi][ni], afr[mi], bfr[ni]);
        }

        if (t + 1 < ntiles) {                 // stage regs -> other buffer
            const int nbuf = buf ^ 1;
            uint4 ua0 = make_uint4(f2tf32(av0.x), f2tf32(av0.y), f2tf32(av0.z), f2tf32(av0.w));
            uint4 ua1 = make_uint4(f2tf32(av1.x), f2tf32(av1.y), f2tf32(av1.z), f2tf32(av1.w));
            *(uint4*)&As[nbuf][arow][akb]     = ua0;
            *(uint4*)&As[nbuf][arow][akb + 4] = ua1;
            uint4 ub0 = make_uint4(f2tf32(bv0.x), f2tf32(bv0.y), f2tf32(bv0.z), f2tf32(bv0.w));
            uint4 ub1 = make_uint4(f2tf32(bv1.x), f2tf32(bv1.y), f2tf32(bv1.z), f2tf32(bv1.w));
            *(uint4*)&Bs[nbuf][brow][bnb]     = ub0;
            *(uint4*)&Bs[nbuf][brow][bnb + 4] = ub1;
            __syncthreads();
        }
    }

    // epilogue: c0:(g,2t) c1:(g,2t+1) c2:(g+8,2t) c3:(g+8,2t+1)
#pragma unroll
    for (int mi = 0; mi < 4; mi++) {
        const int r0 = bm + wm * 64 + mi * 16 + grp;
#pragma unroll
        for (int ni = 0; ni < 4; ni++) {
            const int c0 = bn + wn * 32 + ni * 8 + 2 * tig;
            float bx = 0.f, by = 0.f;
            if (bias) { bx = bias[c0]; by = bias[c0 + 1]; }
            if (r0 < M) {
                float2 v;
                v.x = acc[mi][ni][0] + bx;
                v.y = acc[mi][ni][1] + by;
                if (tanh_flag) { v.x = tanhf(v.x); v.y = tanhf(v.y); }
                *(float2*)&C[(long long)r0 * N + c0] = v;
            }
            if (r0 + 8 < M) {
                float2 v;
                v.x = acc[mi][ni][2] + bx;
                v.y = acc[mi][ni][3] + by;
                if (tanh_flag) { v.x = tanhf(v.x); v.y = tanhf(v.y); }
                *(float2*)&C[(long long)(r0 + 8) * N + c0] = v;
            }
        }
    }
}

// ---------------- GCN aggregation pipeline (all 4 paths batched) -----------
__global__ void k_deg_init() {
    int i = blockIdx.x * 256 + threadIdx.x;
    if (i < NG) g_deg[i] = 1;   // self loop
}

__global__ void k_hist(const int* __restrict__ eidx) {
    int e = blockIdx.x * 256 + threadIdx.x;
    if (e < NP * NE) {
        int p = e / NE, i = e - p * NE;
        int dst = eidx[(size_t)p * 2 * NE + NE + i];
        atomicAdd(&g_deg[p * NN + dst], 1);
    }
}

__global__ void k_scan1() {
    __shared__ int red[8];
    int b = blockIdx.x, tid = threadIdx.x;
    int lane = tid & 31, warp = tid >> 5;
    int i0 = b * 512 + tid * 2;
    int s = 0;
    if (i0 < NG)     s += g_deg[i0] - 1;
    if (i0 + 1 < NG) s += g_deg[i0 + 1] - 1;
#pragma unroll
    for (int o = 16; o; o >>= 1) s += __shfl_xor_sync(0xffffffffu, s, o);
    if (lane == 0) red[warp] = s;
    __syncthreads();
    if (tid == 0) {
        int t = 0;
#pragma unroll
        for (int w = 0; w < 8; w++) t += red[w];
        g_part[b] = t;
    }
}

__global__ void k_scan2() {
    __shared__ int s[512];
    int tid = threadIdx.x;
    int v = (tid < SCAN_BLK) ? g_part[tid] : 0;
    s[tid] = v;
    __syncthreads();
    for (int off = 1; off < 512; off <<= 1) {
        int u = (tid >= off) ? s[tid - off] : 0;
        __syncthreads();
        s[tid] += u;
        __syncthreads();
    }
    if (tid < SCAN_BLK) g_part[tid] = s[tid] - v;   // exclusive
}

__global__ void k_scan3() {
    __shared__ int wsum[8];
    int b = blockIdx.x, tid = threadIdx.x;
    int lane = tid & 31, warp = tid >> 5;
    int i0 = b * 512 + tid * 2;
    int d0 = (i0 < NG) ? g_deg[i0] : 1;
    int d1 = (i0 + 1 < NG) ? g_deg[i0 + 1] : 1;
    int v0 = d0 - 1, v1 = d1 - 1;
    int s = v0 + v1;
    int sc = s;
#pragma unroll
    for (int o = 1; o < 32; o <<= 1) {
        int u = __shfl_up_sync(0xffffffffu, sc, o);
        if (lane >= o) sc += u;
    }
    if (lane == 31) wsum[warp] = sc;
    __syncthreads();
    int wbase = 0;
    for (int w = 0; w < warp; w++) wbase += wsum[w];
    int base = g_part[b] + wbase + (sc - s);
    if (i0 < NG) {
        g_rowoff[i0] = base; g_rowcur[i0] = base;
        g_dinv[i0] = rsqrtf((float)d0);
    }
    if (i0 + 1 < NG) {
        g_rowoff[i0 + 1] = base + v0; g_rowcur[i0 + 1] = base + v0;
        g_dinv[i0 + 1] = rsqrtf((float)d1);
    }
    if (b == 0 && tid == 0) g_rowoff[NG] = NP * NE;
}

__global__ void k_fill(const int* __restrict__ eidx) {
    int e = blockIdx.x * 256 + threadIdx.x;
    if (e < NP * NE) {
        int p = e / NE, i = e - p * NE;
        int src = eidx[(size_t)p * 2 * NE + i];
        int dst = eidx[(size_t)p * 2 * NE + NE + i];
        int pos = atomicAdd(&g_rowcur[p * NN + dst], 1);
        g_srcs[pos] = src;
    }
}

// pull: one warp per (path,node); 8 dims per lane
__global__ void k_pull(const float* __restrict__ bs) {
    int g = blockIdx.x * 8 + (threadIdx.x >> 5);
    if (g >= NG) return;
    int lane = threadIdx.x & 31;
    int p = g / NN, node = g - p * NN;

    float di = g_dinv[g];
    const float* xwp = g_xw + (size_t)p * NND;
    const float* xwn = xwp + (size_t)node * D;
    float acc[8];
#pragma unroll
    for (int k = 0; k < 8; k++) acc[k] = di * di * xwn[k * 32 + lane];

    int beg = g_rowoff[g];
    int end = g_rowoff[g + 1];
    const float* dv = g_dinv + p * NN;
    for (int e = beg; e < end; e++) {
        int s = g_srcs[e];
        float nrm = di * dv[s];
        const float* xs = xwp + (size_t)s * D;
#pragma unroll
        for (int k = 0; k < 8; k++) acc[k] += nrm * xs[k * 32 + lane];
    }

    float* zp = g_z + (size_t)g * D;
    const float* bp = bs + p * D;
#pragma unroll
    for (int k = 0; k < 8; k++) zp[k * 32 + lane] = acc[k] + bp[k * 32 + lane];
}

// ---------------- attention tail -------------------------------------------
__global__ void k_dot(const float* __restrict__ w2) {
    int row = blockIdx.x * 8 + (threadIdx.x >> 5);
    if (row >= NROWS) return;
    int lane = threadIdx.x & 31;
    const float* h = g_h + (size_t)row * DH;
    float s = h[lane]      * w2[lane]
            + h[lane + 32] * w2[lane + 32]
            + h[lane + 64] * w2[lane + 64]
            + h[lane + 96] * w2[lane + 96];
#pragma unroll
    for (int o = 16; o; o >>= 1) s += __shfl_xor_sync(0xffffffffu, s, o);
    if (lane == 0) g_wlog[row] = s;
}

__global__ void k_combine(float* __restrict__ out) {
    int i = blockIdx.x * 256 + threadIdx.x;
    if (i >= NND) return;
    int node = i >> 8;
    float w0 = g_wlog[node];
    float w1 = g_wlog[NN + node];
    float w2 = g_wlog[2 * NN + node];
    float w3 = g_wlog[3 * NN + node];
    float m = fmaxf(fmaxf(w0, w1), fmaxf(w2, w3));
    float e0 = __expf(w0 - m), e1 = __expf(w1 - m), e2 = __expf(w2 - m), e3 = __expf(w3 - m);
    float inv = 1.0f / (e0 + e1 + e2 + e3);
    out[i] = (e0 * g_z[i] + e1 * g_z[NND + i] + e2 * g_z[2 * NND + i] + e3 * g_z[3 * NND + i]) * inv;
}

// ---------------- launch ----------------------------------------------------
extern "C" void kernel_launch(void* const* d_in, const int* in_sizes, int n_in,
                              void* d_out, int out_size) {
    const float* x    = (const float*)d_in[0];
    const int*   eidx = (const int*)d_in[1];
    const float* Ws   = (const float*)d_in[2];
    const float* bs   = (const float*)d_in[3];
    const float* w1   = (const float*)d_in[4];
    const float* b1   = (const float*)d_in[5];
    const float* w2   = (const float*)d_in[6];
    float* out = (float*)d_out;

    void* p_xw = nullptr; void* p_z = nullptr; void* p_h = nullptr;
    cudaGetSymbolAddress(&p_xw, g_xw);
    cudaGetSymbolAddress(&p_z,  g_z);
    cudaGetSymbolAddress(&p_h,  g_h);

    // xw[p] = x @ W_p  (batched over z; bias added in pull) — tf32 tensor cores
    k_gemm_tc<<<dim3(D / 128, (NN + 127) / 128, NP), 256>>>(
        x, Ws, nullptr, (float*)p_xw, NN, D, D,
        (long long)D * D, (long long)NND, 0);

    // CSR build for all 4 paths at once
    k_deg_init<<<(NG + 255) / 256, 256>>>();
    k_hist<<<(NP * NE + 255) / 256, 256>>>(eidx);
    k_scan1<<<SCAN_BLK, 256>>>();
    k_scan2<<<1, 512>>>();
    k_scan3<<<SCAN_BLK, 256>>>();
    k_fill<<<(NP * NE + 255) / 256, 256>>>(eidx);
    k_pull<<<(NG + 7) / 8, 256>>>(bs);

    // H = tanh(Z @ W1 + b1)   [200000 x 128] — tf32 tensor cores
    k_gemm_tc<<<dim3(DH / 128, (NROWS + 127) / 128, 1), 256>>>(
        (const float*)p_z, w1, b1, (float*)p_h, NROWS, DH, D, 0, 0, 1);

    k_dot<<<(NROWS + 7) / 8, 256>>>(w2);
    k_combine<<<(NND + 255) / 256, 256>>>(out);
}

// round 6
// speedup vs baseline: 2.8383x; 1.1881x over previous
#include <cuda_runtime.h>
#include <cuda_fp16.h>
#include <math.h>
#include <stdint.h>

#define NN 50000
#define NP 4
#define NE 800000
#define D 256
#define DH 128
#define NND (NN * D)
#define NROWS (NP * NN)
#define NG (NP * NN)              // total (path,node) rows = 200000
#define SCAN_BLK 391              // ceil(200000/512)

// ---------------- scratch (device globals; no allocation allowed) ----------
__device__ __half g_xwh[NP * NND];     // [p][node][256] x@W_p, fp16 (pull-only)
__device__ float g_z[NP * NND];        // GCN outputs [p][node][256]
__device__ float g_wlog[NROWS];        // attention logits
__device__ int   g_deg[NG];
__device__ float g_dinv[NG];
__device__ int   g_rowoff[NG + 1];
__device__ int   g_rowcur[NG];
__device__ int   g_srcs[NP * NE];
__device__ int   g_part[SCAN_BLK];

// ---------------- tf32 helpers ---------------------------------------------
__device__ __forceinline__ uint32_t f2tf32(float f) {
    uint32_t u;
    asm("cvt.rna.tf32.f32 %0, %1;" : "=r"(u) : "f"(f));
    return u;
}

__device__ __forceinline__ void mma_tf32(float* d, const uint32_t* a,
                                         const uint32_t* b) {
    asm volatile(
        "mma.sync.aligned.m16n8k8.row.col.f32.tf32.tf32.f32 "
        "{%0,%1,%2,%3}, {%4,%5,%6,%7}, {%8,%9}, {%0,%1,%2,%3};\n"
        : "+f"(d[0]), "+f"(d[1]), "+f"(d[2]), "+f"(d[3])
        : "r"(a[0]), "r"(a[1]), "r"(a[2]), "r"(a[3]),
          "r"(b[0]), "r"(b[1]));
}

// Shared mainloop skeleton: 128x128 block, BK=16, 8 warps (2M x 4N),
// warp tile 64x32, 4x4 frags of m16n8k8. Same layout as R5 (validated).
#define GEMM_PROLOG_AND_MAINLOOP(EXTRA_INIT)                                   \
    __shared__ uint32_t As[2][128][20];                                        \
    __shared__ uint32_t Bs[2][16][136];                                        \
    const int tid  = threadIdx.x;                                              \
    const int lane = tid & 31;                                                 \
    const int warp = tid >> 5;                                                 \
    const int wm = warp & 1;                                                   \
    const int wn = warp >> 1;                                                  \
    const int grp = lane >> 2;                                                 \
    const int tig = lane & 3;                                                  \
    const int bm = blockIdx.y * 128;                                           \
    const int bn = blockIdx.x * 128;                                           \
    const int arow = tid >> 1;                                                 \
    const int akb  = (tid & 1) * 8;                                            \
    const bool aval = (bm + arow) < M;                                         \
    const float* Ap = A + (long long)(bm + arow) * K + akb;                    \
    const int brow = tid >> 4;                                                 \
    const int bnb  = (tid & 15) * 8;                                           \
    const float* Bp = B + (long long)brow * N + bn + bnb;                      \
    float acc[4][4][4] = {};                                                   \
    float4 av0 = make_float4(0.f,0.f,0.f,0.f), av1 = av0, bv0, bv1;            \
    if (aval) { av0 = *(const float4*)Ap; av1 = *(const float4*)(Ap + 4); }    \
    bv0 = *(const float4*)Bp;                                                  \
    bv1 = *(const float4*)(Bp + 4);                                            \
    {                                                                          \
        uint4 ua0 = make_uint4(f2tf32(av0.x), f2tf32(av0.y), f2tf32(av0.z), f2tf32(av0.w)); \
        uint4 ua1 = make_uint4(f2tf32(av1.x), f2tf32(av1.y), f2tf32(av1.z), f2tf32(av1.w)); \
        *(uint4*)&As[0][arow][akb]     = ua0;                                  \
        *(uint4*)&As[0][arow][akb + 4] = ua1;                                  \
        uint4 ub0 = make_uint4(f2tf32(bv0.x), f2tf32(bv0.y), f2tf32(bv0.z), f2tf32(bv0.w)); \
        uint4 ub1 = make_uint4(f2tf32(bv1.x), f2tf32(bv1.y), f2tf32(bv1.z), f2tf32(bv1.w)); \
        *(uint4*)&Bs[0][brow][bnb]     = ub0;                                  \
        *(uint4*)&Bs[0][brow][bnb + 4] = ub1;                                  \
    }                                                                          \
    EXTRA_INIT                                                                 \
    __syncthreads();                                                           \
    const int ntiles = K >> 4;                                                 \
    for (int t = 0; t < ntiles; t++) {                                         \
        const int buf = t & 1;                                                 \
        if (t + 1 < ntiles) {                                                  \
            const float* Ap2 = Ap + (t + 1) * 16;                              \
            if (aval) { av0 = *(const float4*)Ap2; av1 = *(const float4*)(Ap2 + 4); } \
            const float* Bp2 = Bp + (long long)(t + 1) * 16 * N;               \
            bv0 = *(const float4*)Bp2;                                         \
            bv1 = *(const float4*)(Bp2 + 4);                                   \
        }                                                                      \
        _Pragma("unroll")                                                      \
        for (int kb = 0; kb < 16; kb += 8) {                                   \
            uint32_t afr[4][4], bfr[4][2];                                     \
            _Pragma("unroll")                                                  \
            for (int mi = 0; mi < 4; mi++) {                                   \
                const int mb = wm * 64 + mi * 16;                              \
                afr[mi][0] = As[buf][mb + grp][kb + tig];                      \
                afr[mi][1] = As[buf][mb + grp + 8][kb + tig];                  \
                afr[mi][2] = As[buf][mb + grp][kb + tig + 4];                  \
                afr[mi][3] = As[buf][mb + grp + 8][kb + tig + 4];              \
            }                                                                  \
            _Pragma("unroll")                                                  \
            for (int ni = 0; ni < 4; ni++) {                                   \
                const int nb2 = wn * 32 + ni * 8;                              \
                bfr[ni][0] = Bs[buf][kb + tig][nb2 + grp];                     \
                bfr[ni][1] = Bs[buf][kb + tig + 4][nb2 + grp];                 \
            }                                                                  \
            _Pragma("unroll")                                                  \
            for (int mi = 0; mi < 4; mi++)                                     \
                _Pragma("unroll")                                              \
                for (int ni = 0; ni < 4; ni++)                                 \
                    mma_tf32(acc[mi][ni], afr[mi], bfr[ni]);                   \
        }                                                                      \
        if (t + 1 < ntiles) {                                                  \
            const int nbuf = buf ^ 1;                                          \
            uint4 ua0 = make_uint4(f2tf32(av0.x), f2tf32(av0.y), f2tf32(av0.z), f2tf32(av0.w)); \
            uint4 ua1 = make_uint4(f2tf32(av1.x), f2tf32(av1.y), f2tf32(av1.z), f2tf32(av1.w)); \
            *(uint4*)&As[nbuf][arow][akb]     = ua0;                           \
            *(uint4*)&As[nbuf][arow][akb + 4] = ua1;                           \
            uint4 ub0 = make_uint4(f2tf32(bv0.x), f2tf32(bv0.y), f2tf32(bv0.z), f2tf32(bv0.w)); \
            uint4 ub1 = make_uint4(f2tf32(bv1.x), f2tf32(bv1.y), f2tf32(bv1.z), f2tf32(bv1.w)); \
            *(uint4*)&Bs[nbuf][brow][bnb]     = ub0;                           \
            *(uint4*)&Bs[nbuf][brow][bnb + 4] = ub1;                           \
            __syncthreads();                                                   \
        }                                                                      \
    }

// ---- GEMM1: xw[p] = x @ W_p, half output (pull-only consumer) -------------
__global__ void __launch_bounds__(256, 2) k_gemm_xw(
    const float* __restrict__ A, const float* __restrict__ B,
    __half* __restrict__ C, int M, int N, int K, long long sB, long long sC)
{
    B += (long long)blockIdx.z * sB;
    C += (long long)blockIdx.z * sC;

    GEMM_PROLOG_AND_MAINLOOP()

#pragma unroll
    for (int mi = 0; mi < 4; mi++) {
        const int r0 = bm + wm * 64 + mi * 16 + grp;
#pragma unroll
        for (int ni = 0; ni < 4; ni++) {
            const int c0 = bn + wn * 32 + ni * 8 + 2 * tig;
            if (r0 < M)
                *(__half2*)&C[(long long)r0 * N + c0] =
                    __floats2half2_rn(acc[mi][ni][0], acc[mi][ni][1]);
            if (r0 + 8 < M)
                *(__half2*)&C[(long long)(r0 + 8) * N + c0] =
                    __floats2half2_rn(acc[mi][ni][2], acc[mi][ni][3]);
        }
    }
}

// ---- GEMM2 fused with attention dot: wlog = tanh(Z@W1+b1) @ w2 ------------
// N == 128 == full width per block; reduce per row in-block, no H written.
__global__ void __launch_bounds__(256, 2) k_gemm_attn(
    const float* __restrict__ A, const float* __restrict__ B,
    const float* __restrict__ bias, const float* __restrict__ w2v,
    int M, int N, int K)
{
    __shared__ float rowsum[128];
    __shared__ float w2s[128];
    __shared__ float b1s[128];

    GEMM_PROLOG_AND_MAINLOOP(
        if (tid < 128) { rowsum[tid] = 0.f; w2s[tid] = w2v[tid]; b1s[tid] = bias[tid]; }
    )

#pragma unroll
    for (int mi = 0; mi < 4; mi++) {
        float p0 = 0.f, p1 = 0.f;
#pragma unroll
        for (int ni = 0; ni < 4; ni++) {
            const int c0 = wn * 32 + ni * 8 + 2 * tig;   // bn == 0
            float t;
            t = tanhf(acc[mi][ni][0] + b1s[c0]);     p0 += t * w2s[c0];
            t = tanhf(acc[mi][ni][1] + b1s[c0 + 1]); p0 += t * w2s[c0 + 1];
            t = tanhf(acc[mi][ni][2] + b1s[c0]);     p1 += t * w2s[c0];
            t = tanhf(acc[mi][ni][3] + b1s[c0 + 1]); p1 += t * w2s[c0 + 1];
        }
        // reduce over tig (lanes xor 1,2 share the same rows)
        p0 += __shfl_xor_sync(0xffffffffu, p0, 1);
        p0 += __shfl_xor_sync(0xffffffffu, p0, 2);
        p1 += __shfl_xor_sync(0xffffffffu, p1, 1);
        p1 += __shfl_xor_sync(0xffffffffu, p1, 2);
        if (tig == 0) {
            atomicAdd(&rowsum[wm * 64 + mi * 16 + grp], p0);
            atomicAdd(&rowsum[wm * 64 + mi * 16 + grp + 8], p1);
        }
    }
    __syncthreads();
    if (tid < 128 && bm + tid < M) g_wlog[bm + tid] = rowsum[tid];
}

// ---------------- GCN aggregation pipeline (all 4 paths batched) -----------
__global__ void k_deg_init() {
    int i = blockIdx.x * 256 + threadIdx.x;
    if (i < NG) g_deg[i] = 1;   // self loop
}

__global__ void k_hist(const int* __restrict__ eidx) {
    int e = blockIdx.x * 256 + threadIdx.x;
    if (e < NP * NE) {
        int p = e / NE, i = e - p * NE;
        int dst = eidx[(size_t)p * 2 * NE + NE + i];
        atomicAdd(&g_deg[p * NN + dst], 1);
    }
}

__global__ void k_scan1() {
    __shared__ int red[8];
    int b = blockIdx.x, tid = threadIdx.x;
    int lane = tid & 31, warp = tid >> 5;
    int i0 = b * 512 + tid * 2;
    int s = 0;
    if (i0 < NG)     s += g_deg[i0] - 1;
    if (i0 + 1 < NG) s += g_deg[i0 + 1] - 1;
#pragma unroll
    for (int o = 16; o; o >>= 1) s += __shfl_xor_sync(0xffffffffu, s, o);
    if (lane == 0) red[warp] = s;
    __syncthreads();
    if (tid == 0) {
        int t = 0;
#pragma unroll
        for (int w = 0; w < 8; w++) t += red[w];
        g_part[b] = t;
    }
}

__global__ void k_scan2() {
    __shared__ int s[512];
    int tid = threadIdx.x;
    int v = (tid < SCAN_BLK) ? g_part[tid] : 0;
    s[tid] = v;
    __syncthreads();
    for (int off = 1; off < 512; off <<= 1) {
        int u = (tid >= off) ? s[tid - off] : 0;
        __syncthreads();
        s[tid] += u;
        __syncthreads();
    }
    if (tid < SCAN_BLK) g_part[tid] = s[tid] - v;   // exclusive
}

__global__ void k_scan3() {
    __shared__ int wsum[8];
    int b = blockIdx.x, tid = threadIdx.x;
    int lane = tid & 31, warp = tid >> 5;
    int i0 = b * 512 + tid * 2;
    int d0 = (i0 < NG) ? g_deg[i0] : 1;
    int d1 = (i0 + 1 < NG) ? g_deg[i0 + 1] : 1;
    int v0 = d0 - 1, v1 = d1 - 1;
    int s = v0 + v1;
    int sc = s;
#pragma unroll
    for (int o = 1; o < 32; o <<= 1) {
        int u = __shfl_up_sync(0xffffffffu, sc, o);
        if (lane >= o) sc += u;
    }
    if (lane == 31) wsum[warp] = sc;
    __syncthreads();
    int wbase = 0;
    for (int w = 0; w < warp; w++) wbase += wsum[w];
    int base = g_part[b] + wbase + (sc - s);
    if (i0 < NG) {
        g_rowoff[i0] = base; g_rowcur[i0] = base;
        g_dinv[i0] = rsqrtf((float)d0);
    }
    if (i0 + 1 < NG) {
        g_rowoff[i0 + 1] = base + v0; g_rowcur[i0 + 1] = base + v0;
        g_dinv[i0 + 1] = rsqrtf((float)d1);
    }
    if (b == 0 && tid == 0) g_rowoff[NG] = NP * NE;
}

__global__ void k_fill(const int* __restrict__ eidx) {
    int e = blockIdx.x * 256 + threadIdx.x;
    if (e < NP * NE) {
        int p = e / NE, i = e - p * NE;
        int src = eidx[(size_t)p * 2 * NE + i];
        int dst = eidx[(size_t)p * 2 * NE + NE + i];
        int pos = atomicAdd(&g_rowcur[p * NN + dst], 1);
        g_srcs[pos] = src;
    }
}

// pull: one warp per (path,node); fp16 gather, fp32 accumulate
__global__ void k_pull(const float* __restrict__ bs) {
    int g = blockIdx.x * 8 + (threadIdx.x >> 5);
    if (g >= NG) return;
    int lane = threadIdx.x & 31;
    int p = g / NN, node = g - p * NN;

    float di = g_dinv[g];
    const __half2* base = (const __half2*)g_xwh + (size_t)p * (NND / 2);
    const __half2* xn = base + (size_t)node * (D / 2);
    float acc[8];
#pragma unroll
    for (int j = 0; j < 4; j++) {
        float2 v = __half22float2(xn[lane + 32 * j]);
        acc[2 * j]     = di * di * v.x;
        acc[2 * j + 1] = di * di * v.y;
    }

    int beg = g_rowoff[g];
    int end = g_rowoff[g + 1];
    const float* dv = g_dinv + p * NN;
    for (int e = beg; e < end; e++) {
        int s = g_srcs[e];
        float nrm = di * dv[s];
        const __half2* xs = base + (size_t)s * (D / 2);
#pragma unroll
        for (int j = 0; j < 4; j++) {
            float2 v = __half22float2(xs[lane + 32 * j]);
            acc[2 * j]     = fmaf(nrm, v.x, acc[2 * j]);
            acc[2 * j + 1] = fmaf(nrm, v.y, acc[2 * j + 1]);
        }
    }

    float* zp = g_z + (size_t)g * D;
    const float* bp = bs + p * D;
#pragma unroll
    for (int j = 0; j < 4; j++) {
        int c = (lane + 32 * j) * 2;
        float2 o;
        o.x = acc[2 * j] + bp[c];
        o.y = acc[2 * j + 1] + bp[c + 1];
        *(float2*)&zp[c] = o;
    }
}

// ---------------- softmax combine ------------------------------------------
__global__ void k_combine(float* __restrict__ out) {
    int i = blockIdx.x * 256 + threadIdx.x;
    if (i >= NND) return;
    int node = i >> 8;
    float w0 = g_wlog[node];
    float w1 = g_wlog[NN + node];
    float w2 = g_wlog[2 * NN + node];
    float w3 = g_wlog[3 * NN + node];
    float m = fmaxf(fmaxf(w0, w1), fmaxf(w2, w3));
    float e0 = __expf(w0 - m), e1 = __expf(w1 - m), e2 = __expf(w2 - m), e3 = __expf(w3 - m);
    float inv = 1.0f / (e0 + e1 + e2 + e3);
    out[i] = (e0 * g_z[i] + e1 * g_z[NND + i] + e2 * g_z[2 * NND + i] + e3 * g_z[3 * NND + i]) * inv;
}

// ---------------- launch ----------------------------------------------------
extern "C" void kernel_launch(void* const* d_in, const int* in_sizes, int n_in,
                              void* d_out, int out_size) {
    const float* x    = (const float*)d_in[0];
    const int*   eidx = (const int*)d_in[1];
    const float* Ws   = (const float*)d_in[2];
    const float* bs   = (const float*)d_in[3];
    const float* w1   = (const float*)d_in[4];
    const float* b1   = (const float*)d_in[5];
    const float* w2   = (const float*)d_in[6];
    float* out = (float*)d_out;

    void* p_xwh = nullptr; void* p_z = nullptr;
    cudaGetSymbolAddress(&p_xwh, g_xwh);
    cudaGetSymbolAddress(&p_z,   g_z);

    // xw[p] = x @ W_p  -> fp16 (batched over z; bias added in pull)
    k_gemm_xw<<<dim3(D / 128, (NN + 127) / 128, NP), 256>>>(
        x, Ws, (__half*)p_xwh, NN, D, D,
        (long long)D * D, (long long)NND);

    // CSR build for all 4 paths at once
    k_deg_init<<<(NG + 255) / 256, 256>>>();
    k_hist<<<(NP * NE + 255) / 256, 256>>>(eidx);
    k_scan1<<<SCAN_BLK, 256>>>();
    k_scan2<<<1, 512>>>();
    k_scan3<<<SCAN_BLK, 256>>>();
    k_fill<<<(NP * NE + 255) / 256, 256>>>(eidx);
    k_pull<<<(NG + 7) / 8, 256>>>(bs);

    // wlog = tanh(Z @ W1 + b1) @ w2   (fused; no H materialized)
    k_gemm_attn<<<dim3(1, (NROWS + 127) / 128), 256>>>(
        (const float*)p_z, w1, b1, w2, NROWS, DH, D);

    k_combine<<<(NND + 255) / 256, 256>>>(out);
}

// round 7
// speedup vs baseline: 2.9657x; 1.0449x over previous
#include <cuda_runtime.h>
#include <cuda_fp16.h>
#include <math.h>
#include <stdint.h>

#define NN 50000
#define NP 4
#define NE 800000
#define D 256
#define DH 128
#define NND (NN * D)
#define NROWS (NP * NN)
#define NG (NP * NN)              // total (path,node) rows = 200000
#define SCAN_BLK 391              // ceil(200000/512)

// ---------------- scratch (device globals; no allocation allowed) ----------
__device__ __half g_xwh[NP * NND];     // [p][node][256] x@W_p, fp16 (pull-only)
__device__ __half g_zh[NP * NND];      // z interleaved [node][path][256], fp16
__device__ int   g_deg[NG];
__device__ float g_dinv[NG];
__device__ int   g_rowoff[NG + 1];
__device__ int   g_rowcur[NG];
__device__ int   g_srcs[NP * NE];
__device__ int   g_part[SCAN_BLK];

// ---------------- tf32 helpers ---------------------------------------------
__device__ __forceinline__ uint32_t f2tf32(float f) {
    uint32_t u;
    asm("cvt.rna.tf32.f32 %0, %1;" : "=r"(u) : "f"(f));
    return u;
}

__device__ __forceinline__ void mma_tf32(float* d, const uint32_t* a,
                                         const uint32_t* b) {
    asm volatile(
        "mma.sync.aligned.m16n8k8.row.col.f32.tf32.tf32.f32 "
        "{%0,%1,%2,%3}, {%4,%5,%6,%7}, {%8,%9}, {%0,%1,%2,%3};\n"
        : "+f"(d[0]), "+f"(d[1]), "+f"(d[2]), "+f"(d[3])
        : "r"(a[0]), "r"(a[1]), "r"(a[2]), "r"(a[3]),
          "r"(b[0]), "r"(b[1]));
}

// ---- GEMM1: xw[p] = x @ W_p (fp32 in, half out). 128x128 blk, BK=16 -------
__global__ void __launch_bounds__(256, 2) k_gemm_xw(
    const float* __restrict__ A, const float* __restrict__ B,
    __half* __restrict__ C, int M, int N, int K, long long sB, long long sC)
{
    B += (long long)blockIdx.z * sB;
    C += (long long)blockIdx.z * sC;

    __shared__ uint32_t As[2][128][20];
    __shared__ uint32_t Bs[2][16][136];

    const int tid  = threadIdx.x;
    const int lane = tid & 31;
    const int warp = tid >> 5;
    const int wm = warp & 1;
    const int wn = warp >> 1;
    const int grp = lane >> 2;
    const int tig = lane & 3;
    const int bm = blockIdx.y * 128;
    const int bn = blockIdx.x * 128;

    const int arow = tid >> 1;
    const int akb  = (tid & 1) * 8;
    const bool aval = (bm + arow) < M;
    const float* Ap = A + (long long)(bm + arow) * K + akb;
    const int brow = tid >> 4;
    const int bnb  = (tid & 15) * 8;
    const float* Bp = B + (long long)brow * N + bn + bnb;

    float acc[4][4][4] = {};
    float4 av0 = make_float4(0.f,0.f,0.f,0.f), av1 = av0, bv0, bv1;

    if (aval) { av0 = *(const float4*)Ap; av1 = *(const float4*)(Ap + 4); }
    bv0 = *(const float4*)Bp;
    bv1 = *(const float4*)(Bp + 4);
    {
        uint4 ua0 = make_uint4(f2tf32(av0.x), f2tf32(av0.y), f2tf32(av0.z), f2tf32(av0.w));
        uint4 ua1 = make_uint4(f2tf32(av1.x), f2tf32(av1.y), f2tf32(av1.z), f2tf32(av1.w));
        *(uint4*)&As[0][arow][akb]     = ua0;
        *(uint4*)&As[0][arow][akb + 4] = ua1;
        uint4 ub0 = make_uint4(f2tf32(bv0.x), f2tf32(bv0.y), f2tf32(bv0.z), f2tf32(bv0.w));
        uint4 ub1 = make_uint4(f2tf32(bv1.x), f2tf32(bv1.y), f2tf32(bv1.z), f2tf32(bv1.w));
        *(uint4*)&Bs[0][brow][bnb]     = ub0;
        *(uint4*)&Bs[0][brow][bnb + 4] = ub1;
    }
    __syncthreads();

    const int ntiles = K >> 4;
    for (int t = 0; t < ntiles; t++) {
        const int buf = t & 1;
        if (t + 1 < ntiles) {
            const float* Ap2 = Ap + (t + 1) * 16;
            if (aval) { av0 = *(const float4*)Ap2; av1 = *(const float4*)(Ap2 + 4); }
            const float* Bp2 = Bp + (long long)(t + 1) * 16 * N;
            bv0 = *(const float4*)Bp2;
            bv1 = *(const float4*)(Bp2 + 4);
        }
#pragma unroll
        for (int kb = 0; kb < 16; kb += 8) {
            uint32_t afr[4][4], bfr[4][2];
#pragma unroll
            for (int mi = 0; mi < 4; mi++) {
                const int mb = wm * 64 + mi * 16;
                afr[mi][0] = As[buf][mb + grp][kb + tig];
                afr[mi][1] = As[buf][mb + grp + 8][kb + tig];
                afr[mi][2] = As[buf][mb + grp][kb + tig + 4];
                afr[mi][3] = As[buf][mb + grp + 8][kb + tig + 4];
            }
#pragma unroll
            for (int ni = 0; ni < 4; ni++) {
                const int nb2 = wn * 32 + ni * 8;
                bfr[ni][0] = Bs[buf][kb + tig][nb2 + grp];
                bfr[ni][1] = Bs[buf][kb + tig + 4][nb2 + grp];
            }
#pragma unroll
            for (int mi = 0; mi < 4; mi++)
#pragma unroll
                for (int ni = 0; ni < 4; ni++)
                    mma_tf32(acc[mi][ni], afr[mi], bfr[ni]);
        }
        if (t + 1 < ntiles) {
            const int nbuf = buf ^ 1;
            uint4 ua0 = make_uint4(f2tf32(av0.x), f2tf32(av0.y), f2tf32(av0.z), f2tf32(av0.w));
            uint4 ua1 = make_uint4(f2tf32(av1.x), f2tf32(av1.y), f2tf32(av1.z), f2tf32(av1.w));
            *(uint4*)&As[nbuf][arow][akb]     = ua0;
            *(uint4*)&As[nbuf][arow][akb + 4] = ua1;
            uint4 ub0 = make_uint4(f2tf32(bv0.x), f2tf32(bv0.y), f2tf32(bv0.z), f2tf32(bv0.w));
            uint4 ub1 = make_uint4(f2tf32(bv1.x), f2tf32(bv1.y), f2tf32(bv1.z), f2tf32(bv1.w));
            *(uint4*)&Bs[nbuf][brow][bnb]     = ub0;
            *(uint4*)&Bs[nbuf][brow][bnb + 4] = ub1;
            __syncthreads();
        }
    }

#pragma unroll
    for (int mi = 0; mi < 4; mi++) {
        const int r0 = bm + wm * 64 + mi * 16 + grp;
#pragma unroll
        for (int ni = 0; ni < 4; ni++) {
            const int c0 = bn + wn * 32 + ni * 8 + 2 * tig;
            if (r0 < M)
                *(__half2*)&C[(long long)r0 * N + c0] =
                    __floats2half2_rn(acc[mi][ni][0], acc[mi][ni][1]);
            if (r0 + 8 < M)
                *(__half2*)&C[(long long)(r0 + 8) * N + c0] =
                    __floats2half2_rn(acc[mi][ni][2], acc[mi][ni][3]);
        }
    }
}

// ---- GEMM2 fully fused: logits + softmax + combine ------------------------
// A = g_zh (fp16, rows interleaved g = node*4 + p), B = W1 (fp32 256x128).
// Block = 128 rows = 32 nodes x 4 paths; grid.x = 1 (N == 128).
// Epilogue: wlog row-reduce -> per-node softmax -> out[node] = sum_p beta*z.
__global__ void __launch_bounds__(256, 2) k_gemm_attn(
    const __half* __restrict__ A, const float* __restrict__ B,
    const float* __restrict__ b1v, const float* __restrict__ w2v,
    float* __restrict__ out, int M, int N, int K)
{
    __shared__ uint32_t As[2][128][20];
    __shared__ uint32_t Bs[2][16][136];
    __shared__ float rowsum[128];
    __shared__ float w2s[128];
    __shared__ float b1s[128];

    const int tid  = threadIdx.x;
    const int lane = tid & 31;
    const int warp = tid >> 5;
    const int wm = warp & 1;
    const int wn = warp >> 1;
    const int grp = lane >> 2;
    const int tig = lane & 3;
    const int bm = blockIdx.y * 128;

    // A loader: fp16 — thread covers 8 halves (16B) per k-tile
    const int arow = tid >> 1;
    const int akb  = (tid & 1) * 8;
    const bool aval = (bm + arow) < M;
    const __half* Ap = A + (long long)(bm + arow) * K + akb;
    const int brow = tid >> 4;
    const int bnb  = (tid & 15) * 8;
    const float* Bp = B + (long long)brow * N + bnb;

    float acc[4][4][4] = {};
    uint4 ar = make_uint4(0, 0, 0, 0);
    float4 bv0, bv1;

    if (aval) ar = *(const uint4*)Ap;
    bv0 = *(const float4*)Bp;
    bv1 = *(const float4*)(Bp + 4);
    {
        const __half2* h = (const __half2*)&ar;
#pragma unroll
        for (int j = 0; j < 4; j++) {
            float2 f = __half22float2(h[j]);
            As[0][arow][akb + 2 * j]     = f2tf32(f.x);
            As[0][arow][akb + 2 * j + 1] = f2tf32(f.y);
        }
        uint4 ub0 = make_uint4(f2tf32(bv0.x), f2tf32(bv0.y), f2tf32(bv0.z), f2tf32(bv0.w));
        uint4 ub1 = make_uint4(f2tf32(bv1.x), f2tf32(bv1.y), f2tf32(bv1.z), f2tf32(bv1.w));
        *(uint4*)&Bs[0][brow][bnb]     = ub0;
        *(uint4*)&Bs[0][brow][bnb + 4] = ub1;
    }
    if (tid < 128) { rowsum[tid] = 0.f; w2s[tid] = w2v[tid]; b1s[tid] = b1v[tid]; }
    __syncthreads();

    const int ntiles = K >> 4;
    for (int t = 0; t < ntiles; t++) {
        const int buf = t & 1;
        if (t + 1 < ntiles) {
            if (aval) ar = *(const uint4*)(Ap + (t + 1) * 16);
            const float* Bp2 = Bp + (long long)(t + 1) * 16 * N;
            bv0 = *(const float4*)Bp2;
            bv1 = *(const float4*)(Bp2 + 4);
        }
#pragma unroll
        for (int kb = 0; kb < 16; kb += 8) {
            uint32_t afr[4][4], bfr[4][2];
#pragma unroll
            for (int mi = 0; mi < 4; mi++) {
                const int mb = wm * 64 + mi * 16;
                afr[mi][0] = As[buf][mb + grp][kb + tig];
                afr[mi][1] = As[buf][mb + grp + 8][kb + tig];
                afr[mi][2] = As[buf][mb + grp][kb + tig + 4];
                afr[mi][3] = As[buf][mb + grp + 8][kb + tig + 4];
            }
#pragma unroll
            for (int ni = 0; ni < 4; ni++) {
                const int nb2 = wn * 32 + ni * 8;
                bfr[ni][0] = Bs[buf][kb + tig][nb2 + grp];
                bfr[ni][1] = Bs[buf][kb + tig + 4][nb2 + grp];
            }
#pragma unroll
            for (int mi = 0; mi < 4; mi++)
#pragma unroll
                for (int ni = 0; ni < 4; ni++)
                    mma_tf32(acc[mi][ni], afr[mi], bfr[ni]);
        }
        if (t + 1 < ntiles) {
            const int nbuf = buf ^ 1;
            const __half2* h = (const __half2*)&ar;
#pragma unroll
            for (int j = 0; j < 4; j++) {
                float2 f = __half22float2(h[j]);
                As[nbuf][arow][akb + 2 * j]     = f2tf32(f.x);
                As[nbuf][arow][akb + 2 * j + 1] = f2tf32(f.y);
            }
            uint4 ub0 = make_uint4(f2tf32(bv0.x), f2tf32(bv0.y), f2tf32(bv0.z), f2tf32(bv0.w));
            uint4 ub1 = make_uint4(f2tf32(bv1.x), f2tf32(bv1.y), f2tf32(bv1.z), f2tf32(bv1.w));
            *(uint4*)&Bs[nbuf][brow][bnb]     = ub0;
            *(uint4*)&Bs[nbuf][brow][bnb + 4] = ub1;
            __syncthreads();
        }
    }

    // ---- logits: tanh(acc + b1) . w2, reduced per row ----
#pragma unroll
    for (int mi = 0; mi < 4; mi++) {
        float p0 = 0.f, p1 = 0.f;
#pragma unroll
        for (int ni = 0; ni < 4; ni++) {
            const int c0 = wn * 32 + ni * 8 + 2 * tig;
            float t;
            t = tanhf(acc[mi][ni][0] + b1s[c0]);     p0 += t * w2s[c0];
            t = tanhf(acc[mi][ni][1] + b1s[c0 + 1]); p0 += t * w2s[c0 + 1];
            t = tanhf(acc[mi][ni][2] + b1s[c0]);     p1 += t * w2s[c0];
            t = tanhf(acc[mi][ni][3] + b1s[c0 + 1]); p1 += t * w2s[c0 + 1];
        }
        p0 += __shfl_xor_sync(0xffffffffu, p0, 1);
        p0 += __shfl_xor_sync(0xffffffffu, p0, 2);
        p1 += __shfl_xor_sync(0xffffffffu, p1, 1);
        p1 += __shfl_xor_sync(0xffffffffu, p1, 2);
        if (tig == 0) {
            atomicAdd(&rowsum[wm * 64 + mi * 16 + grp], p0);
            atomicAdd(&rowsum[wm * 64 + mi * 16 + grp + 8], p1);
        }
    }
    __syncthreads();

    // ---- per-node softmax over the 4 paths (rows node*4..node*4+3) ----
    const int nodes_in_blk = (M - bm) >> 2 < 32 ? (M - bm) >> 2 : 32;
    if (tid < 32 && tid < nodes_in_blk) {
        float l0 = rowsum[tid * 4], l1 = rowsum[tid * 4 + 1];
        float l2 = rowsum[tid * 4 + 2], l3 = rowsum[tid * 4 + 3];
        float m = fmaxf(fmaxf(l0, l1), fmaxf(l2, l3));
        float e0 = __expf(l0 - m), e1 = __expf(l1 - m);
        float e2 = __expf(l2 - m), e3 = __expf(l3 - m);
        float inv = 1.0f / (e0 + e1 + e2 + e3);
        rowsum[tid * 4]     = e0 * inv;
        rowsum[tid * 4 + 1] = e1 * inv;
        rowsum[tid * 4 + 2] = e2 * inv;
        rowsum[tid * 4 + 3] = e3 * inv;
    }
    __syncthreads();

    // ---- combine: out[node][d] = sum_p beta * z (z tile hot in L1/L2) ----
    const int node0 = bm >> 2;
#pragma unroll
    for (int i = 0; i < 32; i++) {
        int idx = tid + 256 * i;                 // 0..8191
        int nl = idx >> 8;                       // node_local 0..31
        int dd = idx & 255;
        if (nl >= nodes_in_blk) break;
        const __half* zr = A + (long long)(bm + nl * 4) * K + dd;
        float v = rowsum[nl * 4]     * __half2float(zr[0])
                + rowsum[nl * 4 + 1] * __half2float(zr[K])
                + rowsum[nl * 4 + 2] * __half2float(zr[2 * K])
                + rowsum[nl * 4 + 3] * __half2float(zr[3 * K]);
        out[(long long)(node0 + nl) * D + dd] = v;
    }
}

// ---------------- GCN aggregation pipeline (all 4 paths batched) -----------
__global__ void k_deg_init() {
    int i = blockIdx.x * 256 + threadIdx.x;
    if (i < NG) g_deg[i] = 1;   // self loop
}

__global__ void k_hist(const int* __restrict__ eidx) {
    int e = blockIdx.x * 256 + threadIdx.x;
    if (e < NP * NE) {
        int p = e / NE, i = e - p * NE;
        int dst = eidx[(size_t)p * 2 * NE + NE + i];
        atomicAdd(&g_deg[p * NN + dst], 1);
    }
}

__global__ void k_scan1() {
    __shared__ int red[8];
    int b = blockIdx.x, tid = threadIdx.x;
    int lane = tid & 31, warp = tid >> 5;
    int i0 = b * 512 + tid * 2;
    int s = 0;
    if (i0 < NG)     s += g_deg[i0] - 1;
    if (i0 + 1 < NG) s += g_deg[i0 + 1] - 1;
#pragma unroll
    for (int o = 16; o; o >>= 1) s += __shfl_xor_sync(0xffffffffu, s, o);
    if (lane == 0) red[warp] = s;
    __syncthreads();
    if (tid == 0) {
        int t = 0;
#pragma unroll
        for (int w = 0; w < 8; w++) t += red[w];
        g_part[b] = t;
    }
}

__global__ void k_scan2() {
    __shared__ int s[512];
    int tid = threadIdx.x;
    int v = (tid < SCAN_BLK) ? g_part[tid] : 0;
    s[tid] = v;
    __syncthreads();
    for (int off = 1; off < 512; off <<= 1) {
        int u = (tid >= off) ? s[tid - off] : 0;
        __syncthreads();
        s[tid] += u;
        __syncthreads();
    }
    if (tid < SCAN_BLK) g_part[tid] = s[tid] - v;   // exclusive
}

__global__ void k_scan3() {
    __shared__ int wsum[8];
    int b = blockIdx.x, tid = threadIdx.x;
    int lane = tid & 31, warp = tid >> 5;
    int i0 = b * 512 + tid * 2;
    int d0 = (i0 < NG) ? g_deg[i0] : 1;
    int d1 = (i0 + 1 < NG) ? g_deg[i0 + 1] : 1;
    int v0 = d0 - 1, v1 = d1 - 1;
    int s = v0 + v1;
    int sc = s;
#pragma unroll
    for (int o = 1; o < 32; o <<= 1) {
        int u = __shfl_up_sync(0xffffffffu, sc, o);
        if (lane >= o) sc += u;
    }
    if (lane == 31) wsum[warp] = sc;
    __syncthreads();
    int wbase = 0;
    for (int w = 0; w < warp; w++) wbase += wsum[w];
    int base = g_part[b] + wbase + (sc - s);
    if (i0 < NG) {
        g_rowoff[i0] = base; g_rowcur[i0] = base;
        g_dinv[i0] = rsqrtf((float)d0);
    }
    if (i0 + 1 < NG) {
        g_rowoff[i0 + 1] = base + v0; g_rowcur[i0 + 1] = base + v0;
        g_dinv[i0 + 1] = rsqrtf((float)d1);
    }
    if (b == 0 && tid == 0) g_rowoff[NG] = NP * NE;
}

__global__ void k_fill(const int* __restrict__ eidx) {
    int e = blockIdx.x * 256 + threadIdx.x;
    if (e < NP * NE) {
        int p = e / NE, i = e - p * NE;
        int src = eidx[(size_t)p * 2 * NE + i];
        int dst = eidx[(size_t)p * 2 * NE + NE + i];
        int pos = atomicAdd(&g_rowcur[p * NN + dst], 1);
        g_srcs[pos] = src;
    }
}

// pull: one warp per (path,node); fp16 gather (2-way unrolled), fp32 acc.
// z written INTERLEAVED: row (node*4 + p).
__global__ void k_pull(const float* __restrict__ bs) {
    int g = blockIdx.x * 8 + (threadIdx.x >> 5);
    if (g >= NG) return;
    int lane = threadIdx.x & 31;
    int p = g / NN, node = g - p * NN;

    float di = g_dinv[g];
    const __half2* base = (const __half2*)g_xwh + (size_t)p * (NND / 2);
    const __half2* xn = base + (size_t)node * (D / 2);
    float acc[8];
#pragma unroll
    for (int j = 0; j < 4; j++) {
        float2 v = __half22float2(xn[lane + 32 * j]);
        acc[2 * j]     = di * di * v.x;
        acc[2 * j + 1] = di * di * v.y;
    }

    int beg = g_rowoff[g];
    int end = g_rowoff[g + 1];
    const float* dv = g_dinv + p * NN;
    int e = beg;
    for (; e + 2 <= end; e += 2) {
        int s0 = g_srcs[e], s1 = g_srcs[e + 1];
        float n0 = di * dv[s0], n1 = di * dv[s1];
        const __half2* x0 = base + (size_t)s0 * (D / 2);
        const __half2* x1 = base + (size_t)s1 * (D / 2);
#pragma unroll
        for (int j = 0; j < 4; j++) {
            float2 v0 = __half22float2(x0[lane + 32 * j]);
            float2 v1 = __half22float2(x1[lane + 32 * j]);
            acc[2 * j]     = fmaf(n0, v0.x, fmaf(n1, v1.x, acc[2 * j]));
            acc[2 * j + 1] = fmaf(n0, v0.y, fmaf(n1, v1.y, acc[2 * j + 1]));
        }
    }
    if (e < end) {
        int s0 = g_srcs[e];
        float n0 = di * dv[s0];
        const __half2* x0 = base + (size_t)s0 * (D / 2);
#pragma unroll
        for (int j = 0; j < 4; j++) {
            float2 v0 = __half22float2(x0[lane + 32 * j]);
            acc[2 * j]     = fmaf(n0, v0.x, acc[2 * j]);
            acc[2 * j + 1] = fmaf(n0, v0.y, acc[2 * j + 1]);
        }
    }

    __half2* zp = (__half2*)g_zh + ((size_t)node * NP + p) * (D / 2);
    const float* bp = bs + p * D;
#pragma unroll
    for (int j = 0; j < 4; j++) {
        int c = (lane + 32 * j) * 2;
        zp[lane + 32 * j] = __floats2half2_rn(acc[2 * j] + bp[c],
                                              acc[2 * j + 1] + bp[c + 1]);
    }
}

// ---------------- launch ----------------------------------------------------
extern "C" void kernel_launch(void* const* d_in, const int* in_sizes, int n_in,
                              void* d_out, int out_size) {
    const float* x    = (const float*)d_in[0];
    const int*   eidx = (const int*)d_in[1];
    const float* Ws   = (const float*)d_in[2];
    const float* bs   = (const float*)d_in[3];
    const float* w1   = (const float*)d_in[4];
    const float* b1   = (const float*)d_in[5];
    const float* w2   = (const float*)d_in[6];
    float* out = (float*)d_out;

    void* p_xwh = nullptr; void* p_zh = nullptr;
    cudaGetSymbolAddress(&p_xwh, g_xwh);
    cudaGetSymbolAddress(&p_zh,  g_zh);

    // xw[p] = x @ W_p  -> fp16 (batched over z; bias added in pull)
    k_gemm_xw<<<dim3(D / 128, (NN + 127) / 128, NP), 256>>>(
        x, Ws, (__half*)p_xwh, NN, D, D,
        (long long)D * D, (long long)NND);

    // CSR build for all 4 paths at once
    k_deg_init<<<(NG + 255) / 256, 256>>>();
    k_hist<<<(NP * NE + 255) / 256, 256>>>(eidx);
    k_scan1<<<SCAN_BLK, 256>>>();
    k_scan2<<<1, 512>>>();
    k_scan3<<<SCAN_BLK, 256>>>();
    k_fill<<<(NP * NE + 255) / 256, 256>>>(eidx);
    k_pull<<<(NG + 7) / 8, 256>>>(bs);

    // fused: logits + softmax + combine -> out
    k_gemm_attn<<<dim3(1, (NROWS + 127) / 128), 256>>>(
        (const __half*)p_zh, w1, b1, w2, out, NROWS, DH, D);
}

// round 8
// speedup vs baseline: 3.6721x; 1.2382x over previous
#include <cuda_runtime.h>
#include <cuda_fp16.h>
#include <math.h>
#include <stdint.h>

#define NN 50000
#define NP 4
#define NE 800000
#define D 256
#define DH 128
#define NND (NN * D)
#define NROWS (NP * NN)
#define NG (NP * NN)              // total (path,node) rows = 200000
#define SCAN_BLK 391              // ceil(200000/512)

// ---------------- scratch (device globals; no allocation allowed) ----------
__device__ __half g_xh[NND];           // x in fp16 [50000][256]
__device__ __half g_wsT[NP * D * D];   // Ws transposed [p][n][k] fp16
__device__ __half g_w1T[DH * D];       // W1 transposed [n][k] fp16
__device__ __half g_xwh[NP * NND];     // x@W_p fp16 (pull-only)
__device__ __half g_zh[NP * NND];      // z interleaved [node][path][256] fp16
__device__ int   g_deg[NG];
__device__ float g_dinv[NG];
__device__ int   g_rowoff[NG + 1];
__device__ int   g_rowcur[NG];
__device__ int   g_srcs[NP * NE];
__device__ int   g_part[SCAN_BLK];

// ---------------- fp16 mma helper ------------------------------------------
__device__ __forceinline__ void mma_f16(float* d, const uint32_t* a,
                                        const uint32_t* b) {
    asm volatile(
        "mma.sync.aligned.m16n8k16.row.col.f32.f16.f16.f32 "
        "{%0,%1,%2,%3}, {%4,%5,%6,%7}, {%8,%9}, {%0,%1,%2,%3};\n"
        : "+f"(d[0]), "+f"(d[1]), "+f"(d[2]), "+f"(d[3])
        : "r"(a[0]), "r"(a[1]), "r"(a[2]), "r"(a[3]),
          "r"(b[0]), "r"(b[1]));
}

// ---------------- prep: fp32 -> fp16 conversions ---------------------------
__global__ void k_cvt_x(const float* __restrict__ x) {
    int i = blockIdx.x * 256 + threadIdx.x;      // over float4s
    if (i < NND / 4) {
        float4 v = ((const float4*)x)[i];
        __half2* o = (__half2*)g_xh + i * 2;
        o[0] = __floats2half2_rn(v.x, v.y);
        o[1] = __floats2half2_rn(v.z, v.w);
    }
}

// transpose [z][K][N] fp32 -> [z][N][K] fp16 (K,N multiples of 32)
__global__ void k_cvt_wT(const float* __restrict__ in, __half* __restrict__ out,
                         int K, int N) {
    __shared__ float t[32][33];
    int z = blockIdx.z;
    int k0 = blockIdx.x * 32, n0 = blockIdx.y * 32;
    int tx = threadIdx.x, ty = threadIdx.y;      // 32 x 8
    const float* ip = in + (size_t)z * K * N;
    __half* op = out + (size_t)z * K * N;
#pragma unroll
    for (int j = 0; j < 32; j += 8)
        t[ty + j][tx] = ip[(size_t)(k0 + ty + j) * N + n0 + tx];
    __syncthreads();
#pragma unroll
    for (int j = 0; j < 32; j += 8)
        op[(size_t)(n0 + ty + j) * K + k0 + tx] = __float2half(t[tx][ty + j]);
}

// ---- GEMM1: xw[p] = xh @ WsT[p]^T (fp16 in, half out). 128x128, BK=32 -----
// A [M][K] k-major fp16, B [N][K] k-major fp16. 8 warps 2Mx4N, warp 64x32.
__global__ void __launch_bounds__(256, 2) k_gemm_xw(
    const __half* __restrict__ A, const __half* __restrict__ B,
    __half* __restrict__ C, int M, int N, int K, long long sB, long long sC)
{
    B += (long long)blockIdx.z * sB;
    C += (long long)blockIdx.z * sC;

    __shared__ uint32_t As[2][128][20];   // half2, pitch 20 (perfect perm)
    __shared__ uint32_t Bs[2][128][20];

    const int tid  = threadIdx.x;
    const int lane = tid & 31;
    const int warp = tid >> 5;
    const int wm = warp & 1;
    const int wn = warp >> 1;
    const int grp = lane >> 2;
    const int tig = lane & 3;
    const int bm = blockIdx.y * 128;
    const int bn = blockIdx.x * 128;

    const int lrow = tid >> 1;               // 0..127
    const int lkc  = (tid & 1) * 8;          // half2 base 0 or 8
    const bool aval = (bm + lrow) < M;
    const __half* Ap = A + (long long)(bm + lrow) * K + lkc * 2;
    const __half* Bp = B + (long long)(bn + lrow) * K + lkc * 2;

    float acc[4][4][4] = {};
    uint4 av0 = make_uint4(0,0,0,0), av1 = av0, bv0, bv1;

    if (aval) { av0 = *(const uint4*)Ap; av1 = *(const uint4*)(Ap + 8); }
    bv0 = *(const uint4*)Bp;
    bv1 = *(const uint4*)(Bp + 8);
    *(uint4*)&As[0][lrow][lkc]     = av0;
    *(uint4*)&As[0][lrow][lkc + 4] = av1;
    *(uint4*)&Bs[0][lrow][lkc]     = bv0;
    *(uint4*)&Bs[0][lrow][lkc + 4] = bv1;
    __syncthreads();

    const int ntiles = K >> 5;
    for (int t = 0; t < ntiles; t++) {
        const int buf = t & 1;
        if (t + 1 < ntiles) {
            const __half* Ap2 = Ap + (t + 1) * 32;
            const __half* Bp2 = Bp + (t + 1) * 32;
            if (aval) { av0 = *(const uint4*)Ap2; av1 = *(const uint4*)(Ap2 + 8); }
            bv0 = *(const uint4*)Bp2;
            bv1 = *(const uint4*)(Bp2 + 8);
        }
#pragma unroll
        for (int ks = 0; ks < 2; ks++) {
            uint32_t afr[4][4], bfr[4][2];
#pragma unroll
            for (int mi = 0; mi < 4; mi++) {
                const int mb = wm * 64 + mi * 16;
                afr[mi][0] = As[buf][mb + grp][ks * 8 + tig];
                afr[mi][1] = As[buf][mb + grp + 8][ks * 8 + tig];
                afr[mi][2] = As[buf][mb + grp][ks * 8 + tig + 4];
                afr[mi][3] = As[buf][mb + grp + 8][ks * 8 + tig + 4];
            }
#pragma unroll
            for (int ni = 0; ni < 4; ni++) {
                const int nb2 = wn * 32 + ni * 8;
                bfr[ni][0] = Bs[buf][nb2 + grp][ks * 8 + tig];
                bfr[ni][1] = Bs[buf][nb2 + grp][ks * 8 + tig + 4];
            }
#pragma unroll
            for (int mi = 0; mi < 4; mi++)
#pragma unroll
                for (int ni = 0; ni < 4; ni++)
                    mma_f16(acc[mi][ni], afr[mi], bfr[ni]);
        }
        if (t + 1 < ntiles) {
            const int nbuf = buf ^ 1;
            *(uint4*)&As[nbuf][lrow][lkc]     = av0;
            *(uint4*)&As[nbuf][lrow][lkc + 4] = av1;
            *(uint4*)&Bs[nbuf][lrow][lkc]     = bv0;
            *(uint4*)&Bs[nbuf][lrow][lkc + 4] = bv1;
            __syncthreads();
        }
    }

#pragma unroll
    for (int mi = 0; mi < 4; mi++) {
        const int r0 = bm + wm * 64 + mi * 16 + grp;
#pragma unroll
        for (int ni = 0; ni < 4; ni++) {
            const int c0 = bn + wn * 32 + ni * 8 + 2 * tig;
            if (r0 < M)
                *(__half2*)&C[(long long)r0 * N + c0] =
                    __floats2half2_rn(acc[mi][ni][0], acc[mi][ni][1]);
            if (r0 + 8 < M)
                *(__half2*)&C[(long long)(r0 + 8) * N + c0] =
                    __floats2half2_rn(acc[mi][ni][2], acc[mi][ni][3]);
        }
    }
}

// ---- GEMM2 fully fused: logits + softmax + combine ------------------------
// A = g_zh fp16 (rows g = node*4 + p), B = g_w1T fp16 [128][256] k-major.
__global__ void __launch_bounds__(256, 2) k_gemm_attn(
    const __half* __restrict__ A, const __half* __restrict__ B,
    const float* __restrict__ b1v, const float* __restrict__ w2v,
    float* __restrict__ out, int M, int K)
{
    __shared__ uint32_t As[2][128][20];
    __shared__ uint32_t Bs[2][128][20];
    __shared__ float rowsum[128];
    __shared__ float w2s[128];
    __shared__ float b1s[128];

    const int tid  = threadIdx.x;
    const int lane = tid & 31;
    const int warp = tid >> 5;
    const int wm = warp & 1;
    const int wn = warp >> 1;
    const int grp = lane >> 2;
    const int tig = lane & 3;
    const int bm = blockIdx.y * 128;

    const int lrow = tid >> 1;
    const int lkc  = (tid & 1) * 8;
    const bool aval = (bm + lrow) < M;
    const __half* Ap = A + (long long)(bm + lrow) * K + lkc * 2;
    const __half* Bp = B + (long long)lrow * K + lkc * 2;   // N=128 rows

    float acc[4][4][4] = {};
    uint4 av0 = make_uint4(0,0,0,0), av1 = av0, bv0, bv1;

    if (aval) { av0 = *(const uint4*)Ap; av1 = *(const uint4*)(Ap + 8); }
    bv0 = *(const uint4*)Bp;
    bv1 = *(const uint4*)(Bp + 8);
    *(uint4*)&As[0][lrow][lkc]     = av0;
    *(uint4*)&As[0][lrow][lkc + 4] = av1;
    *(uint4*)&Bs[0][lrow][lkc]     = bv0;
    *(uint4*)&Bs[0][lrow][lkc + 4] = bv1;
    if (tid < 128) { rowsum[tid] = 0.f; w2s[tid] = w2v[tid]; b1s[tid] = b1v[tid]; }
    __syncthreads();

    const int ntiles = K >> 5;
    for (int t = 0; t < ntiles; t++) {
        const int buf = t & 1;
        if (t + 1 < ntiles) {
            const __half* Ap2 = Ap + (t + 1) * 32;
            const __half* Bp2 = Bp + (t + 1) * 32;
            if (aval) { av0 = *(const uint4*)Ap2; av1 = *(const uint4*)(Ap2 + 8); }
            bv0 = *(const uint4*)Bp2;
            bv1 = *(const uint4*)(Bp2 + 8);
        }
#pragma unroll
        for (int ks = 0; ks < 2; ks++) {
            uint32_t afr[4][4], bfr[4][2];
#pragma unroll
            for (int mi = 0; mi < 4; mi++) {
                const int mb = wm * 64 + mi * 16;
                afr[mi][0] = As[buf][mb + grp][ks * 8 + tig];
                afr[mi][1] = As[buf][mb + grp + 8][ks * 8 + tig];
                afr[mi][2] = As[buf][mb + grp][ks * 8 + tig + 4];
                afr[mi][3] = As[buf][mb + grp + 8][ks * 8 + tig + 4];
            }
#pragma unroll
            for (int ni = 0; ni < 4; ni++) {
                const int nb2 = wn * 32 + ni * 8;
                bfr[ni][0] = Bs[buf][nb2 + grp][ks * 8 + tig];
                bfr[ni][1] = Bs[buf][nb2 + grp][ks * 8 + tig + 4];
            }
#pragma unroll
            for (int mi = 0; mi < 4; mi++)
#pragma unroll
                for (int ni = 0; ni < 4; ni++)
                    mma_f16(acc[mi][ni], afr[mi], bfr[ni]);
        }
        if (t + 1 < ntiles) {
            const int nbuf = buf ^ 1;
            *(uint4*)&As[nbuf][lrow][lkc]     = av0;
            *(uint4*)&As[nbuf][lrow][lkc + 4] = av1;
            *(uint4*)&Bs[nbuf][lrow][lkc]     = bv0;
            *(uint4*)&Bs[nbuf][lrow][lkc + 4] = bv1;
            __syncthreads();
        }
    }

    // ---- logits: tanh(acc + b1) . w2, reduced per row ----
#pragma unroll
    for (int mi = 0; mi < 4; mi++) {
        float p0 = 0.f, p1 = 0.f;
#pragma unroll
        for (int ni = 0; ni < 4; ni++) {
            const int c0 = wn * 32 + ni * 8 + 2 * tig;
            float t;
            t = tanhf(acc[mi][ni][0] + b1s[c0]);     p0 += t * w2s[c0];
            t = tanhf(acc[mi][ni][1] + b1s[c0 + 1]); p0 += t * w2s[c0 + 1];
            t = tanhf(acc[mi][ni][2] + b1s[c0]);     p1 += t * w2s[c0];
            t = tanhf(acc[mi][ni][3] + b1s[c0 + 1]); p1 += t * w2s[c0 + 1];
        }
        p0 += __shfl_xor_sync(0xffffffffu, p0, 1);
        p0 += __shfl_xor_sync(0xffffffffu, p0, 2);
        p1 += __shfl_xor_sync(0xffffffffu, p1, 1);
        p1 += __shfl_xor_sync(0xffffffffu, p1, 2);
        if (tig == 0) {
            atomicAdd(&rowsum[wm * 64 + mi * 16 + grp], p0);
            atomicAdd(&rowsum[wm * 64 + mi * 16 + grp + 8], p1);
        }
    }
    __syncthreads();

    // ---- per-node softmax over the 4 paths ----
    int nib = (M - bm) >> 2;
    const int nodes_in_blk = nib < 32 ? nib : 32;
    if (tid < 32 && tid < nodes_in_blk) {
        float l0 = rowsum[tid * 4], l1 = rowsum[tid * 4 + 1];
        float l2 = rowsum[tid * 4 + 2], l3 = rowsum[tid * 4 + 3];
        float m = fmaxf(fmaxf(l0, l1), fmaxf(l2, l3));
        float e0 = __expf(l0 - m), e1 = __expf(l1 - m);
        float e2 = __expf(l2 - m), e3 = __expf(l3 - m);
        float inv = 1.0f / (e0 + e1 + e2 + e3);
        rowsum[tid * 4]     = e0 * inv;
        rowsum[tid * 4 + 1] = e1 * inv;
        rowsum[tid * 4 + 2] = e2 * inv;
        rowsum[tid * 4 + 3] = e3 * inv;
    }
    __syncthreads();

    // ---- combine: out[node][d] = sum_p beta * z (z tile hot in L2) ----
    const int node0 = bm >> 2;
#pragma unroll
    for (int i = 0; i < 32; i++) {
        int idx = tid + 256 * i;
        int nl = idx >> 8;
        int dd = idx & 255;
        if (nl >= nodes_in_blk) break;
        const __half* zr = A + (long long)(bm + nl * 4) * K + dd;
        float v = rowsum[nl * 4]     * __half2float(zr[0])
                + rowsum[nl * 4 + 1] * __half2float(zr[K])
                + rowsum[nl * 4 + 2] * __half2float(zr[2 * K])
                + rowsum[nl * 4 + 3] * __half2float(zr[3 * K]);
        out[(long long)(node0 + nl) * D + dd] = v;
    }
}

// ---------------- GCN aggregation pipeline (all 4 paths batched) -----------
__global__ void k_deg_init() {
    int i = blockIdx.x * 256 + threadIdx.x;
    if (i < NG) g_deg[i] = 1;   // self loop
}

__global__ void k_hist(const int* __restrict__ eidx) {
    int e = blockIdx.x * 256 + threadIdx.x;
    if (e < NP * NE) {
        int p = e / NE, i = e - p * NE;
        int dst = eidx[(size_t)p * 2 * NE + NE + i];
        atomicAdd(&g_deg[p * NN + dst], 1);
    }
}

__global__ void k_scan1() {
    __shared__ int red[8];
    int b = blockIdx.x, tid = threadIdx.x;
    int lane = tid & 31, warp = tid >> 5;
    int i0 = b * 512 + tid * 2;
    int s = 0;
    if (i0 < NG)     s += g_deg[i0] - 1;
    if (i0 + 1 < NG) s += g_deg[i0 + 1] - 1;
#pragma unroll
    for (int o = 16; o; o >>= 1) s += __shfl_xor_sync(0xffffffffu, s, o);
    if (lane == 0) red[warp] = s;
    __syncthreads();
    if (tid == 0) {
        int t = 0;
#pragma unroll
        for (int w = 0; w < 8; w++) t += red[w];
        g_part[b] = t;
    }
}

__global__ void k_scan2() {
    __shared__ int s[512];
    int tid = threadIdx.x;
    int v = (tid < SCAN_BLK) ? g_part[tid] : 0;
    s[tid] = v;
    __syncthreads();
    for (int off = 1; off < 512; off <<= 1) {
        int u = (tid >= off) ? s[tid - off] : 0;
        __syncthreads();
        s[tid] += u;
        __syncthreads();
    }
    if (tid < SCAN_BLK) g_part[tid] = s[tid] - v;   // exclusive
}

__global__ void k_scan3() {
    __shared__ int wsum[8];
    int b = blockIdx.x, tid = threadIdx.x;
    int lane = tid & 31, warp = tid >> 5;
    int i0 = b * 512 + tid * 2;
    int d0 = (i0 < NG) ? g_deg[i0] : 1;
    int d1 = (i0 + 1 < NG) ? g_deg[i0 + 1] : 1;
    int v0 = d0 - 1, v1 = d1 - 1;
    int s = v0 + v1;
    int sc = s;
#pragma unroll
    for (int o = 1; o < 32; o <<= 1) {
        int u = __shfl_up_sync(0xffffffffu, sc, o);
        if (lane >= o) sc += u;
    }
    if (lane == 31) wsum[warp] = sc;
    __syncthreads();
    int wbase = 0;
    for (int w = 0; w < warp; w++) wbase += wsum[w];
    int base = g_part[b] + wbase + (sc - s);
    if (i0 < NG) {
        g_rowoff[i0] = base; g_rowcur[i0] = base;
        g_dinv[i0] = rsqrtf((float)d0);
    }
    if (i0 + 1 < NG) {
        g_rowoff[i0 + 1] = base + v0; g_rowcur[i0 + 1] = base + v0;
        g_dinv[i0 + 1] = rsqrtf((float)d1);
    }
    if (b == 0 && tid == 0) g_rowoff[NG] = NP * NE;
}

__global__ void k_fill(const int* __restrict__ eidx) {
    int e = blockIdx.x * 256 + threadIdx.x;
    if (e < NP * NE) {
        int p = e / NE, i = e - p * NE;
        int src = eidx[(size_t)p * 2 * NE + i];
        int dst = eidx[(size_t)p * 2 * NE + NE + i];
        int pos = atomicAdd(&g_rowcur[p * NN + dst], 1);
        g_srcs[pos] = src;
    }
}

// pull: one warp per (path,node); fp16 gather (2-way unrolled), fp32 acc.
// z written INTERLEAVED: row (node*4 + p).
__global__ void k_pull(const float* __restrict__ bs) {
    int g = blockIdx.x * 8 + (threadIdx.x >> 5);
    if (g >= NG) return;
    int lane = threadIdx.x & 31;
    int p = g / NN, node = g - p * NN;

    float di = g_dinv[g];
    const __half2* base = (const __half2*)g_xwh + (size_t)p * (NND / 2);
    const __half2* xn = base + (size_t)node * (D / 2);
    float acc[8];
#pragma unroll
    for (int j = 0; j < 4; j++) {
        float2 v = __half22float2(xn[lane + 32 * j]);
        acc[2 * j]     = di * di * v.x;
        acc[2 * j + 1] = di * di * v.y;
    }

    int beg = g_rowoff[g];
    int end = g_rowoff[g + 1];
    const float* dv = g_dinv + p * NN;
    int e = beg;
    for (; e + 2 <= end; e += 2) {
        int s0 = g_srcs[e], s1 = g_srcs[e + 1];
        float n0 = di * dv[s0], n1 = di * dv[s1];
        const __half2* x0 = base + (size_t)s0 * (D / 2);
        const __half2* x1 = base + (size_t)s1 * (D / 2);
#pragma unroll
        for (int j = 0; j < 4; j++) {
            float2 v0 = __half22float2(x0[lane + 32 * j]);
            float2 v1 = __half22float2(x1[lane + 32 * j]);
            acc[2 * j]     = fmaf(n0, v0.x, fmaf(n1, v1.x, acc[2 * j]));
            acc[2 * j + 1] = fmaf(n0, v0.y, fmaf(n1, v1.y, acc[2 * j + 1]));
        }
    }
    if (e < end) {
        int s0 = g_srcs[e];
        float n0 = di * dv[s0];
        const __half2* x0 = base + (size_t)s0 * (D / 2);
#pragma unroll
        for (int j = 0; j < 4; j++) {
            float2 v0 = __half22float2(x0[lane + 32 * j]);
            acc[2 * j]     = fmaf(n0, v0.x, acc[2 * j]);
            acc[2 * j + 1] = fmaf(n0, v0.y, acc[2 * j + 1]);
        }
    }

    __half2* zp = (__half2*)g_zh + ((size_t)node * NP + p) * (D / 2);
    const float* bp = bs + p * D;
#pragma unroll
    for (int j = 0; j < 4; j++) {
        int c = (lane + 32 * j) * 2;
        zp[lane + 32 * j] = __floats2half2_rn(acc[2 * j] + bp[c],
                                              acc[2 * j + 1] + bp[c + 1]);
    }
}

// ---------------- launch ----------------------------------------------------
extern "C" void kernel_launch(void* const* d_in, const int* in_sizes, int n_in,
                              void* d_out, int out_size) {
    const float* x    = (const float*)d_in[0];
    const int*   eidx = (const int*)d_in[1];
    const float* Ws   = (const float*)d_in[2];
    const float* bs   = (const float*)d_in[3];
    const float* w1   = (const float*)d_in[4];
    const float* b1   = (const float*)d_in[5];
    const float* w2   = (const float*)d_in[6];
    float* out = (float*)d_out;

    void* p_xh = nullptr; void* p_wsT = nullptr; void* p_w1T = nullptr;
    void* p_xwh = nullptr; void* p_zh = nullptr;
    cudaGetSymbolAddress(&p_xh,  g_xh);
    cudaGetSymbolAddress(&p_wsT, g_wsT);
    cudaGetSymbolAddress(&p_w1T, g_w1T);
    cudaGetSymbolAddress(&p_xwh, g_xwh);
    cudaGetSymbolAddress(&p_zh,  g_zh);

    // prep: fp16 conversions + weight transposes
    k_cvt_x<<<(NND / 4 + 255) / 256, 256>>>(x);
    k_cvt_wT<<<dim3(D / 32, D / 32, NP), dim3(32, 8)>>>(Ws, (__half*)p_wsT, D, D);
    k_cvt_wT<<<dim3(D / 32, DH / 32, 1), dim3(32, 8)>>>(w1, (__half*)p_w1T, D, DH);

    // xw[p] = xh @ WsT[p]^T  -> fp16 (batched over z; bias added in pull)
    k_gemm_xw<<<dim3(D / 128, (NN + 127) / 128, NP), 256>>>(
        (const __half*)p_xh, (const __half*)p_wsT, (__half*)p_xwh, NN, D, D,
        (long long)D * D, (long long)NND);

    // CSR build for all 4 paths at once
    k_deg_init<<<(NG + 255) / 256, 256>>>();
    k_hist<<<(NP * NE + 255) / 256, 256>>>(eidx);
    k_scan1<<<SCAN_BLK, 256>>>();
    k_scan2<<<1, 512>>>();
    k_scan3<<<SCAN_BLK, 256>>>();
    k_fill<<<(NP * NE + 255) / 256, 256>>>(eidx);
    k_pull<<<(NG + 7) / 8, 256>>>(bs);

    // fused: logits + softmax + combine -> out
    k_gemm_attn<<<dim3(1, (NROWS + 127) / 128), 256>>>(
        (const __half*)p_zh, (const __half*)p_w1T, b1, w2, out, NROWS, D);
}

// round 9
// speedup vs baseline: 3.6893x; 1.0047x over previous
#include <cuda_runtime.h>
#include <cuda_fp16.h>
#include <math.h>
#include <stdint.h>

#define NN 50000
#define NP 4
#define NE 800000
#define D 256
#define DH 128
#define NND (NN * D)
#define NROWS (NP * NN)
#define NG (NP * NN)              // total (path,node) rows = 200000
#define SCAN_BLK 391              // ceil(200000/512)

// ---------------- scratch (device globals; no allocation allowed) ----------
__device__ __half g_xh[NND];           // x in fp16 [50000][256]
__device__ __half g_wsT[NP * D * D];   // Ws transposed [p][n][k] fp16
__device__ __half g_w1T[DH * D];       // W1 transposed [n][k] fp16
__device__ __half g_xwh[NP * NND];     // x@W_p fp16 (pull-only)
__device__ __half g_zh[NP * NND];      // z interleaved [node][path][256] fp16
__device__ int   g_deg[NG];
__device__ float g_dinv[NG];
__device__ int   g_rowoff[NG + 1];
__device__ int   g_rowcur[NG];
__device__ int   g_srcs[NP * NE];
__device__ int   g_part[SCAN_BLK];

// ---------------- mma / ldmatrix helpers ------------------------------------
__device__ __forceinline__ void mma_f16(float* d, const uint32_t* a,
                                        const uint32_t* b) {
    asm volatile(
        "mma.sync.aligned.m16n8k16.row.col.f32.f16.f16.f32 "
        "{%0,%1,%2,%3}, {%4,%5,%6,%7}, {%8,%9}, {%0,%1,%2,%3};\n"
        : "+f"(d[0]), "+f"(d[1]), "+f"(d[2]), "+f"(d[3])
        : "r"(a[0]), "r"(a[1]), "r"(a[2]), "r"(a[3]),
          "r"(b[0]), "r"(b[1]));
}

__device__ __forceinline__ void ldsm_x4(uint32_t& r0, uint32_t& r1,
                                        uint32_t& r2, uint32_t& r3,
                                        uint32_t addr) {
    asm volatile("ldmatrix.sync.aligned.m8n8.x4.shared.b16 {%0,%1,%2,%3}, [%4];"
                 : "=r"(r0), "=r"(r1), "=r"(r2), "=r"(r3) : "r"(addr));
}

// ---------------- prep: fp32 -> fp16 conversions ---------------------------
__global__ void k_cvt_x(const float* __restrict__ x) {
    int i = blockIdx.x * 256 + threadIdx.x;      // over float4s
    if (i < NND / 4) {
        float4 v = ((const float4*)x)[i];
        __half2* o = (__half2*)g_xh + i * 2;
        o[0] = __floats2half2_rn(v.x, v.y);
        o[1] = __floats2half2_rn(v.z, v.w);
    }
}

// transpose [z][K][N] fp32 -> [z][N][K] fp16 (K,N multiples of 32)
__global__ void k_cvt_wT(const float* __restrict__ in, __half* __restrict__ out,
                         int K, int N) {
    __shared__ float t[32][33];
    int z = blockIdx.z;
    int k0 = blockIdx.x * 32, n0 = blockIdx.y * 32;
    int tx = threadIdx.x, ty = threadIdx.y;      // 32 x 8
    const float* ip = in + (size_t)z * K * N;
    __half* op = out + (size_t)z * K * N;
#pragma unroll
    for (int j = 0; j < 32; j += 8)
        t[ty + j][tx] = ip[(size_t)(k0 + ty + j) * N + n0 + tx];
    __syncthreads();
#pragma unroll
    for (int j = 0; j < 32; j += 8)
        op[(size_t)(n0 + ty + j) * K + k0 + tx] = __float2half(t[tx][ty + j]);
}

// smem geometry shared by both GEMMs: pitch 20 uint32/row, 128 rows/buffer
#define SPITCH 20
#define BUFBYTES (128 * SPITCH * 4)     // 10240
#define MIBYTES  (16 * SPITCH * 4)      // 1280

// ---- GEMM1: xw[p] = xh @ WsT[p]^T (fp16 in, half out). 128x128, BK=32 -----
__global__ void __launch_bounds__(256, 2) k_gemm_xw(
    const __half* __restrict__ A, const __half* __restrict__ B,
    __half* __restrict__ C, int M, int N, int K, long long sB, long long sC)
{
    B += (long long)blockIdx.z * sB;
    C += (long long)blockIdx.z * sC;

    __shared__ uint32_t As[2][128][SPITCH];   // half2, pitch 20 (perfect perm)
    __shared__ uint32_t Bs[2][128][SPITCH];

    const int tid  = threadIdx.x;
    const int lane = tid & 31;
    const int warp = tid >> 5;
    const int wm = warp & 1;
    const int wn = warp >> 1;
    const int grp = lane >> 2;
    const int tig = lane & 3;
    const int bm = blockIdx.y * 128;
    const int bn = blockIdx.x * 128;

    const int lrow = tid >> 1;               // 0..127
    const int lkc  = (tid & 1) * 8;          // half2 base 0 or 8
    const bool aval = (bm + lrow) < M;
    const __half* Ap = A + (long long)(bm + lrow) * K + lkc * 2;
    const __half* Bp = B + (long long)(bn + lrow) * K + lkc * 2;

    // ldmatrix per-thread source addresses
    const uint32_t asBase = (uint32_t)__cvta_generic_to_shared(&As[0][0][0]);
    const uint32_t bsBase = (uint32_t)__cvta_generic_to_shared(&Bs[0][0][0]);
    const uint32_t aAddr0 = asBase +
        (((wm * 64 + (lane & 15)) * SPITCH + (lane >> 4) * 4) << 2);
    const uint32_t bAddr0 = bsBase +
        (((wn * 32 + ((lane >> 4) << 3) + (lane & 7)) * SPITCH
          + ((lane >> 3) & 1) * 4) << 2);

    float acc[4][4][4] = {};
    uint4 av0 = make_uint4(0,0,0,0), av1 = av0, bv0, bv1;

    if (aval) { av0 = *(const uint4*)Ap; av1 = *(const uint4*)(Ap + 8); }
    bv0 = *(const uint4*)Bp;
    bv1 = *(const uint4*)(Bp + 8);
    *(uint4*)&As[0][lrow][lkc]     = av0;
    *(uint4*)&As[0][lrow][lkc + 4] = av1;
    *(uint4*)&Bs[0][lrow][lkc]     = bv0;
    *(uint4*)&Bs[0][lrow][lkc + 4] = bv1;
    __syncthreads();

    const int ntiles = K >> 5;
    for (int t = 0; t < ntiles; t++) {
        const int buf = t & 1;
        if (t + 1 < ntiles) {
            const __half* Ap2 = Ap + (t + 1) * 32;
            const __half* Bp2 = Bp + (t + 1) * 32;
            if (aval) { av0 = *(const uint4*)Ap2; av1 = *(const uint4*)(Ap2 + 8); }
            bv0 = *(const uint4*)Bp2;
            bv1 = *(const uint4*)(Bp2 + 8);
        }
#pragma unroll
        for (int ks = 0; ks < 2; ks++) {
            uint32_t afr[4][4], bfr[4][2];
            const uint32_t ao = aAddr0 + buf * BUFBYTES + ks * 32;
            const uint32_t bo = bAddr0 + buf * BUFBYTES + ks * 32;
#pragma unroll
            for (int mi = 0; mi < 4; mi++)
                ldsm_x4(afr[mi][0], afr[mi][1], afr[mi][2], afr[mi][3],
                        ao + mi * MIBYTES);
            ldsm_x4(bfr[0][0], bfr[0][1], bfr[1][0], bfr[1][1], bo);
            ldsm_x4(bfr[2][0], bfr[2][1], bfr[3][0], bfr[3][1], bo + MIBYTES);
#pragma unroll
            for (int mi = 0; mi < 4; mi++)
#pragma unroll
                for (int ni = 0; ni < 4; ni++)
                    mma_f16(acc[mi][ni], afr[mi], bfr[ni]);
        }
        if (t + 1 < ntiles) {
            const int nbuf = buf ^ 1;
            *(uint4*)&As[nbuf][lrow][lkc]     = av0;
            *(uint4*)&As[nbuf][lrow][lkc + 4] = av1;
            *(uint4*)&Bs[nbuf][lrow][lkc]     = bv0;
            *(uint4*)&Bs[nbuf][lrow][lkc + 4] = bv1;
            __syncthreads();
        }
    }

#pragma unroll
    for (int mi = 0; mi < 4; mi++) {
        const int r0 = bm + wm * 64 + mi * 16 + grp;
#pragma unroll
        for (int ni = 0; ni < 4; ni++) {
            const int c0 = bn + wn * 32 + ni * 8 + 2 * tig;
            if (r0 < M)
                *(__half2*)&C[(long long)r0 * N + c0] =
                    __floats2half2_rn(acc[mi][ni][0], acc[mi][ni][1]);
            if (r0 + 8 < M)
                *(__half2*)&C[(long long)(r0 + 8) * N + c0] =
                    __floats2half2_rn(acc[mi][ni][2], acc[mi][ni][3]);
        }
    }
}

// ---- GEMM2 fully fused: logits + softmax + combine ------------------------
// A = g_zh fp16 (rows g = node*4 + p), B = g_w1T fp16 [128][256] k-major.
__global__ void __launch_bounds__(256, 2) k_gemm_attn(
    const __half* __restrict__ A, const __half* __restrict__ B,
    const float* __restrict__ b1v, const float* __restrict__ w2v,
    float* __restrict__ out, int M, int K)
{
    __shared__ uint32_t As[2][128][SPITCH];
    __shared__ uint32_t Bs[2][128][SPITCH];
    __shared__ float rowsum[128];
    __shared__ float w2s[128];
    __shared__ float b1s[128];

    const int tid  = threadIdx.x;
    const int lane = tid & 31;
    const int warp = tid >> 5;
    const int wm = warp & 1;
    const int wn = warp >> 1;
    const int grp = lane >> 2;
    const int tig = lane & 3;
    const int bm = blockIdx.y * 128;

    const int lrow = tid >> 1;
    const int lkc  = (tid & 1) * 8;
    const bool aval = (bm + lrow) < M;
    const __half* Ap = A + (long long)(bm + lrow) * K + lkc * 2;
    const __half* Bp = B + (long long)lrow * K + lkc * 2;   // N=128 rows

    const uint32_t asBase = (uint32_t)__cvta_generic_to_shared(&As[0][0][0]);
    const uint32_t bsBase = (uint32_t)__cvta_generic_to_shared(&Bs[0][0][0]);
    const uint32_t aAddr0 = asBase +
        (((wm * 64 + (lane & 15)) * SPITCH + (lane >> 4) * 4) << 2);
    const uint32_t bAddr0 = bsBase +
        (((wn * 32 + ((lane >> 4) << 3) + (lane & 7)) * SPITCH
          + ((lane >> 3) & 1) * 4) << 2);

    float acc[4][4][4] = {};
    uint4 av0 = make_uint4(0,0,0,0), av1 = av0, bv0, bv1;

    if (aval) { av0 = *(const uint4*)Ap; av1 = *(const uint4*)(Ap + 8); }
    bv0 = *(const uint4*)Bp;
    bv1 = *(const uint4*)(Bp + 8);
    *(uint4*)&As[0][lrow][lkc]     = av0;
    *(uint4*)&As[0][lrow][lkc + 4] = av1;
    *(uint4*)&Bs[0][lrow][lkc]     = bv0;
    *(uint4*)&Bs[0][lrow][lkc + 4] = bv1;
    if (tid < 128) { rowsum[tid] = 0.f; w2s[tid] = w2v[tid]; b1s[tid] = b1v[tid]; }
    __syncthreads();

    const int ntiles = K >> 5;
    for (int t = 0; t < ntiles; t++) {
        const int buf = t & 1;
        if (t + 1 < ntiles) {
            const __half* Ap2 = Ap + (t + 1) * 32;
            const __half* Bp2 = Bp + (t + 1) * 32;
            if (aval) { av0 = *(const uint4*)Ap2; av1 = *(const uint4*)(Ap2 + 8); }
            bv0 = *(const uint4*)Bp2;
            bv1 = *(const uint4*)(Bp2 + 8);
        }
#pragma unroll
        for (int ks = 0; ks < 2; ks++) {
            uint32_t afr[4][4], bfr[4][2];
            const uint32_t ao = aAddr0 + buf * BUFBYTES + ks * 32;
            const uint32_t bo = bAddr0 + buf * BUFBYTES + ks * 32;
#pragma unroll
            for (int mi = 0; mi < 4; mi++)
                ldsm_x4(afr[mi][0], afr[mi][1], afr[mi][2], afr[mi][3],
                        ao + mi * MIBYTES);
            ldsm_x4(bfr[0][0], bfr[0][1], bfr[1][0], bfr[1][1], bo);
            ldsm_x4(bfr[2][0], bfr[2][1], bfr[3][0], bfr[3][1], bo + MIBYTES);
#pragma unroll
            for (int mi = 0; mi < 4; mi++)
#pragma unroll
                for (int ni = 0; ni < 4; ni++)
                    mma_f16(acc[mi][ni], afr[mi], bfr[ni]);
        }
        if (t + 1 < ntiles) {
            const int nbuf = buf ^ 1;
            *(uint4*)&As[nbuf][lrow][lkc]     = av0;
            *(uint4*)&As[nbuf][lrow][lkc + 4] = av1;
            *(uint4*)&Bs[nbuf][lrow][lkc]     = bv0;
            *(uint4*)&Bs[nbuf][lrow][lkc + 4] = bv1;
            __syncthreads();
        }
    }

    // ---- logits: tanh(acc + b1) . w2, reduced per row ----
#pragma unroll
    for (int mi = 0; mi < 4; mi++) {
        float p0 = 0.f, p1 = 0.f;
#pragma unroll
        for (int ni = 0; ni < 4; ni++) {
            const int c0 = wn * 32 + ni * 8 + 2 * tig;
            float t;
            t = tanhf(acc[mi][ni][0] + b1s[c0]);     p0 += t * w2s[c0];
            t = tanhf(acc[mi][ni][1] + b1s[c0 + 1]); p0 += t * w2s[c0 + 1];
            t = tanhf(acc[mi][ni][2] + b1s[c0]);     p1 += t * w2s[c0];
            t = tanhf(acc[mi][ni][3] + b1s[c0 + 1]); p1 += t * w2s[c0 + 1];
        }
        p0 += __shfl_xor_sync(0xffffffffu, p0, 1);
        p0 += __shfl_xor_sync(0xffffffffu, p0, 2);
        p1 += __shfl_xor_sync(0xffffffffu, p1, 1);
        p1 += __shfl_xor_sync(0xffffffffu, p1, 2);
        if (tig == 0) {
            atomicAdd(&rowsum[wm * 64 + mi * 16 + grp], p0);
            atomicAdd(&rowsum[wm * 64 + mi * 16 + grp + 8], p1);
        }
    }
    __syncthreads();

    // ---- per-node softmax over the 4 paths ----
    int nib = (M - bm) >> 2;
    const int nodes_in_blk = nib < 32 ? nib : 32;
    if (tid < 32 && tid < nodes_in_blk) {
        float l0 = rowsum[tid * 4], l1 = rowsum[tid * 4 + 1];
        float l2 = rowsum[tid * 4 + 2], l3 = rowsum[tid * 4 + 3];
        float m = fmaxf(fmaxf(l0, l1), fmaxf(l2, l3));
        float e0 = __expf(l0 - m), e1 = __expf(l1 - m);
        float e2 = __expf(l2 - m), e3 = __expf(l3 - m);
        float inv = 1.0f / (e0 + e1 + e2 + e3);
        rowsum[tid * 4]     = e0 * inv;
        rowsum[tid * 4 + 1] = e1 * inv;
        rowsum[tid * 4 + 2] = e2 * inv;
        rowsum[tid * 4 + 3] = e3 * inv;
    }
    __syncthreads();

    // ---- combine: out[node][d] = sum_p beta * z (z tile hot in L2) ----
    const int node0 = bm >> 2;
#pragma unroll
    for (int i = 0; i < 32; i++) {
        int idx = tid + 256 * i;
        int nl = idx >> 8;
        int dd = idx & 255;
        if (nl >= nodes_in_blk) break;
        const __half* zr = A + (long long)(bm + nl * 4) * K + dd;
        float v = rowsum[nl * 4]     * __half2float(zr[0])
                + rowsum[nl * 4 + 1] * __half2float(zr[K])
                + rowsum[nl * 4 + 2] * __half2float(zr[2 * K])
                + rowsum[nl * 4 + 3] * __half2float(zr[3 * K]);
        out[(long long)(node0 + nl) * D + dd] = v;
    }
}

// ---------------- GCN aggregation pipeline (all 4 paths batched) -----------
__global__ void k_deg_init() {
    int i = blockIdx.x * 256 + threadIdx.x;
    if (i < NG) g_deg[i] = 1;   // self loop
}

__global__ void k_hist(const int* __restrict__ eidx) {
    int e = blockIdx.x * 256 + threadIdx.x;
    if (e < NP * NE) {
        int p = e / NE, i = e - p * NE;
        int dst = eidx[(size_t)p * 2 * NE + NE + i];
        atomicAdd(&g_deg[p * NN + dst], 1);
    }
}

__global__ void k_scan1() {
    __shared__ int red[8];
    int b = blockIdx.x, tid = threadIdx.x;
    int lane = tid & 31, warp = tid >> 5;
    int i0 = b * 512 + tid * 2;
    int s = 0;
    if (i0 < NG)     s += g_deg[i0] - 1;
    if (i0 + 1 < NG) s += g_deg[i0 + 1] - 1;
#pragma unroll
    for (int o = 16; o; o >>= 1) s += __shfl_xor_sync(0xffffffffu, s, o);
    if (lane == 0) red[warp] = s;
    __syncthreads();
    if (tid == 0) {
        int t = 0;
#pragma unroll
        for (int w = 0; w < 8; w++) t += red[w];
        g_part[b] = t;
    }
}

__global__ void k_scan2() {
    __shared__ int s[512];
    int tid = threadIdx.x;
    int v = (tid < SCAN_BLK) ? g_part[tid] : 0;
    s[tid] = v;
    __syncthreads();
    for (int off = 1; off < 512; off <<= 1) {
        int u = (tid >= off) ? s[tid - off] : 0;
        __syncthreads();
        s[tid] += u;
        __syncthreads();
    }
    if (tid < SCAN_BLK) g_part[tid] = s[tid] - v;   // exclusive
}

__global__ void k_scan3() {
    __shared__ int wsum[8];
    int b = blockIdx.x, tid = threadIdx.x;
    int lane = tid & 31, warp = tid >> 5;
    int i0 = b * 512 + tid * 2;
    int d0 = (i0 < NG) ? g_deg[i0] : 1;
    int d1 = (i0 + 1 < NG) ? g_deg[i0 + 1] : 1;
    int v0 = d0 - 1, v1 = d1 - 1;
    int s = v0 + v1;
    int sc = s;
#pragma unroll
    for (int o = 1; o < 32; o <<= 1) {
        int u = __shfl_up_sync(0xffffffffu, sc, o);
        if (lane >= o) sc += u;
    }
    if (lane == 31) wsum[warp] = sc;
    __syncthreads();
    int wbase = 0;
    for (int w = 0; w < warp; w++) wbase += wsum[w];
    int base = g_part[b] + wbase + (sc - s);
    if (i0 < NG) {
        g_rowoff[i0] = base; g_rowcur[i0] = base;
        g_dinv[i0] = rsqrtf((float)d0);
    }
    if (i0 + 1 < NG) {
        g_rowoff[i0 + 1] = base + v0; g_rowcur[i0 + 1] = base + v0;
        g_dinv[i0 + 1] = rsqrtf((float)d1);
    }
    if (b == 0 && tid == 0) g_rowoff[NG] = NP * NE;
}

__global__ void k_fill(const int* __restrict__ eidx) {
    int e = blockIdx.x * 256 + threadIdx.x;
    if (e < NP * NE) {
        int p = e / NE, i = e - p * NE;
        int src = eidx[(size_t)p * 2 * NE + i];
        int dst = eidx[(size_t)p * 2 * NE + NE + i];
        int pos = atomicAdd(&g_rowcur[p * NN + dst], 1);
        g_srcs[pos] = src;
    }
}

// pull: one warp per (path,node); fp16 gather (2-way unrolled), fp32 acc.
// z written INTERLEAVED: row (node*4 + p).
__global__ void k_pull(const float* __restrict__ bs) {
    int g = blockIdx.x * 8 + (threadIdx.x >> 5);
    if (g >= NG) return;
    int lane = threadIdx.x & 31;
    int p = g / NN, node = g - p * NN;

    float di = g_dinv[g];
    const __half2* base = (const __half2*)g_xwh + (size_t)p * (NND / 2);
    const __half2* xn = base + (size_t)node * (D / 2);
    float acc[8];
#pragma unroll
    for (int j = 0; j < 4; j++) {
        float2 v = __half22float2(xn[lane + 32 * j]);
        acc[2 * j]     = di * di * v.x;
        acc[2 * j + 1] = di * di * v.y;
    }

    int beg = g_rowoff[g];
    int end = g_rowoff[g + 1];
    const float* dv = g_dinv + p * NN;
    int e = beg;
    for (; e + 2 <= end; e += 2) {
        int s0 = g_srcs[e], s1 = g_srcs[e + 1];
        float n0 = di * dv[s0], n1 = di * dv[s1];
        const __half2* x0 = base + (size_t)s0 * (D / 2);
        const __half2* x1 = base + (size_t)s1 * (D / 2);
#pragma unroll
        for (int j = 0; j < 4; j++) {
            float2 v0 = __half22float2(x0[lane + 32 * j]);
            float2 v1 = __half22float2(x1[lane + 32 * j]);
            acc[2 * j]     = fmaf(n0, v0.x, fmaf(n1, v1.x, acc[2 * j]));
            acc[2 * j + 1] = fmaf(n0, v0.y, fmaf(n1, v1.y, acc[2 * j + 1]));
        }
    }
    if (e < end) {
        int s0 = g_srcs[e];
        float n0 = di * dv[s0];
        const __half2* x0 = base + (size_t)s0 * (D / 2);
#pragma unroll
        for (int j = 0; j < 4; j++) {
            float2 v0 = __half22float2(x0[lane + 32 * j]);
            acc[2 * j]     = fmaf(n0, v0.x, acc[2 * j]);
            acc[2 * j + 1] = fmaf(n0, v0.y, acc[2 * j + 1]);
        }
    }

    __half2* zp = (__half2*)g_zh + ((size_t)node * NP + p) * (D / 2);
    const float* bp = bs + p * D;
#pragma unroll
    for (int j = 0; j < 4; j++) {
        int c = (lane + 32 * j) * 2;
        zp[lane + 32 * j] = __floats2half2_rn(acc[2 * j] + bp[c],
                                              acc[2 * j + 1] + bp[c + 1]);
    }
}

// ---------------- launch ----------------------------------------------------
extern "C" void kernel_launch(void* const* d_in, const int* in_sizes, int n_in,
                              void* d_out, int out_size) {
    const float* x    = (const float*)d_in[0];
    const int*   eidx = (const int*)d_in[1];
    const float* Ws   = (const float*)d_in[2];
    const float* bs   = (const float*)d_in[3];
    const float* w1   = (const float*)d_in[4];
    const float* b1   = (const float*)d_in[5];
    const float* w2   = (const float*)d_in[6];
    float* out = (float*)d_out;

    void* p_xh = nullptr; void* p_wsT = nullptr; void* p_w1T = nullptr;
    void* p_xwh = nullptr; void* p_zh = nullptr;
    cudaGetSymbolAddress(&p_xh,  g_xh);
    cudaGetSymbolAddress(&p_wsT, g_wsT);
    cudaGetSymbolAddress(&p_w1T, g_w1T);
    cudaGetSymbolAddress(&p_xwh, g_xwh);
    cudaGetSymbolAddress(&p_zh,  g_zh);

    // prep: fp16 conversions + weight transposes
    k_cvt_x<<<(NND / 4 + 255) / 256, 256>>>(x);
    k_cvt_wT<<<dim3(D / 32, D / 32, NP), dim3(32, 8)>>>(Ws, (__half*)p_wsT, D, D);
    k_cvt_wT<<<dim3(D / 32, DH / 32, 1), dim3(32, 8)>>>(w1, (__half*)p_w1T, D, DH);

    // xw[p] = xh @ WsT[p]^T  -> fp16 (batched over z; bias added in pull)
    k_gemm_xw<<<dim3(D / 128, (NN + 127) / 128, NP), 256>>>(
        (const __half*)p_xh, (const __half*)p_wsT, (__half*)p_xwh, NN, D, D,
        (long long)D * D, (long long)NND);

    // CSR build for all 4 paths at once
    k_deg_init<<<(NG + 255) / 256, 256>>>();
    k_hist<<<(NP * NE + 255) / 256, 256>>>(eidx);
    k_scan1<<<SCAN_BLK, 256>>>();
    k_scan2<<<1, 512>>>();
    k_scan3<<<SCAN_BLK, 256>>>();
    k_fill<<<(NP * NE + 255) / 256, 256>>>(eidx);
    k_pull<<<(NG + 7) / 8, 256>>>(bs);

    // fused: logits + softmax + combine -> out
    k_gemm_attn<<<dim3(1, (NROWS + 127) / 128), 256>>>(
        (const __half*)p_zh, (const __half*)p_w1T, b1, w2, out, NROWS, D);
}

// round 10
// speedup vs baseline: 4.3366x; 1.1755x over previous
#include <cuda_runtime.h>
#include <cuda_fp16.h>
#include <math.h>
#include <stdint.h>

#define NN 50000
#define NP 4
#define NE 800000
#define D 256
#define DH 128
#define NND (NN * D)
#define NROWS (NP * NN)
#define NG (NP * NN)              // total (path,node) rows = 200000
#define SCAN_BLK 391              // ceil(200000/512)

// ---------------- scratch (device globals; no allocation allowed) ----------
__device__ __half g_xh[NND];           // x in fp16 [50000][256]
__device__ __half g_wsT[NP * D * D];   // Ws transposed [p][n][k] fp16
__device__ __half g_w1T[DH * D];       // W1 transposed [n][k] fp16
__device__ __half g_xwh[NP * NND];     // x@W_p fp16 (pull-only)
__device__ __half g_zh[NP * NND];      // z interleaved [node][path][256] fp16
__device__ int   g_deg[NG];
__device__ float g_dinv[NG];
__device__ int   g_rowoff[NG + 1];
__device__ int   g_rowcur[NG];
__device__ int   g_srcs[NP * NE];
__device__ int   g_part[SCAN_BLK];

// ---------------- mma / ldmatrix / cp.async helpers -------------------------
__device__ __forceinline__ void mma_f16(float* d, const uint32_t* a,
                                        const uint32_t* b) {
    asm volatile(
        "mma.sync.aligned.m16n8k16.row.col.f32.f16.f16.f32 "
        "{%0,%1,%2,%3}, {%4,%5,%6,%7}, {%8,%9}, {%0,%1,%2,%3};\n"
        : "+f"(d[0]), "+f"(d[1]), "+f"(d[2]), "+f"(d[3])
        : "r"(a[0]), "r"(a[1]), "r"(a[2]), "r"(a[3]),
          "r"(b[0]), "r"(b[1]));
}

__device__ __forceinline__ void ldsm_x4(uint32_t& r0, uint32_t& r1,
                                        uint32_t& r2, uint32_t& r3,
                                        uint32_t addr) {
    asm volatile("ldmatrix.sync.aligned.m8n8.x4.shared.b16 {%0,%1,%2,%3}, [%4];"
                 : "=r"(r0), "=r"(r1), "=r"(r2), "=r"(r3) : "r"(addr));
}

__device__ __forceinline__ void cp16(uint32_t dst, const void* src, bool pred) {
    asm volatile("cp.async.cg.shared.global [%0], [%1], 16, %2;"
                 :: "r"(dst), "l"(src), "r"(pred ? 16 : 0) : "memory");
}
#define CP_COMMIT() asm volatile("cp.async.commit_group;" ::: "memory")
#define CP_WAIT1()  asm volatile("cp.async.wait_group 1;" ::: "memory")
#define CP_WAIT0()  asm volatile("cp.async.wait_group 0;" ::: "memory")

// ---------------- prep: fp32 -> fp16 conversions ---------------------------
__global__ void k_cvt_x(const float* __restrict__ x) {
    int i = blockIdx.x * 256 + threadIdx.x;      // over float4s
    if (i < NND / 4) {
        float4 v = ((const float4*)x)[i];
        __half2* o = (__half2*)g_xh + i * 2;
        o[0] = __floats2half2_rn(v.x, v.y);
        o[1] = __floats2half2_rn(v.z, v.w);
    }
}

// transpose [z][K][N] fp32 -> [z][N][K] fp16 (K,N multiples of 32)
__global__ void k_cvt_wT(const float* __restrict__ in, __half* __restrict__ out,
                         int K, int N) {
    __shared__ float t[32][33];
    int z = blockIdx.z;
    int k0 = blockIdx.x * 32, n0 = blockIdx.y * 32;
    int tx = threadIdx.x, ty = threadIdx.y;      // 32 x 8
    const float* ip = in + (size_t)z * K * N;
    __half* op = out + (size_t)z * K * N;
#pragma unroll
    for (int j = 0; j < 32; j += 8)
        t[ty + j][tx] = ip[(size_t)(k0 + ty + j) * N + n0 + tx];
    __syncthreads();
#pragma unroll
    for (int j = 0; j < 32; j += 8)
        op[(size_t)(n0 + ty + j) * K + k0 + tx] = __float2half(t[tx][ty + j]);
}

// smem geometry shared by both GEMMs: pitch 20 uint32/row, 128 rows/buffer
#define SPITCH 20
#define BUFBYTES (128 * SPITCH * 4)     // 10240
#define MIBYTES  (16 * SPITCH * 4)      // 1280
#define NTILES 8                        // K = 256, BK = 32

// ---- GEMM1: xw[p] = xh @ WsT[p]^T (fp16 in, half out). 128x128, BK=32 -----
__global__ void __launch_bounds__(256, 2) k_gemm_xw(
    const __half* __restrict__ A, const __half* __restrict__ B,
    __half* __restrict__ C, int M, int N, long long sB, long long sC)
{
    const int K = 256;
    B += (long long)blockIdx.z * sB;
    C += (long long)blockIdx.z * sC;

    __shared__ uint32_t As[2][128][SPITCH];
    __shared__ uint32_t Bs[2][128][SPITCH];

    const int tid  = threadIdx.x;
    const int lane = tid & 31;
    const int warp = tid >> 5;
    const int wm = warp & 1;
    const int wn = warp >> 1;
    const int grp = lane >> 2;
    const int tig = lane & 3;
    const int bm = blockIdx.y * 128;
    const int bn = blockIdx.x * 128;

    const int lrow = tid >> 1;               // 0..127
    const int lkc  = (tid & 1) * 8;          // half2 base 0 or 8
    const bool aval = (bm + lrow) < M;
    const __half* Ap = A + (long long)(bm + lrow) * K + lkc * 2;
    const __half* Bp = B + (long long)(bn + lrow) * K + lkc * 2;

    const uint32_t asBase = (uint32_t)__cvta_generic_to_shared(&As[0][0][0]);
    const uint32_t bsBase = (uint32_t)__cvta_generic_to_shared(&Bs[0][0][0]);
    const uint32_t aDst = asBase + ((lrow * SPITCH + lkc) << 2);
    const uint32_t bDst = bsBase + ((lrow * SPITCH + lkc) << 2);
    const uint32_t aAddr0 = asBase +
        (((wm * 64 + (lane & 15)) * SPITCH + (lane >> 4) * 4) << 2);
    const uint32_t bAddr0 = bsBase +
        (((wn * 32 + ((lane >> 4) << 3) + (lane & 7)) * SPITCH
          + ((lane >> 3) & 1) * 4) << 2);

    float acc[4][4][4] = {};

    // prologue: tiles 0 and 1
    cp16(aDst, Ap, aval);            cp16(aDst + 16, Ap + 8, aval);
    cp16(bDst, Bp, true);            cp16(bDst + 16, Bp + 8, true);
    CP_COMMIT();
    cp16(aDst + BUFBYTES, Ap + 32, aval); cp16(aDst + BUFBYTES + 16, Ap + 40, aval);
    cp16(bDst + BUFBYTES, Bp + 32, true); cp16(bDst + BUFBYTES + 16, Bp + 40, true);
    CP_COMMIT();
    CP_WAIT1();
    __syncthreads();

    for (int t = 0; t < NTILES; t++) {
        const int buf = t & 1;
#pragma unroll
        for (int ks = 0; ks < 2; ks++) {
            uint32_t afr[4][4], bfr[4][2];
            const uint32_t ao = aAddr0 + buf * BUFBYTES + ks * 32;
            const uint32_t bo = bAddr0 + buf * BUFBYTES + ks * 32;
#pragma unroll
            for (int mi = 0; mi < 4; mi++)
                ldsm_x4(afr[mi][0], afr[mi][1], afr[mi][2], afr[mi][3],
                        ao + mi * MIBYTES);
            ldsm_x4(bfr[0][0], bfr[0][1], bfr[1][0], bfr[1][1], bo);
            ldsm_x4(bfr[2][0], bfr[2][1], bfr[3][0], bfr[3][1], bo + MIBYTES);
#pragma unroll
            for (int mi = 0; mi < 4; mi++)
#pragma unroll
                for (int ni = 0; ni < 4; ni++)
                    mma_f16(acc[mi][ni], afr[mi], bfr[ni]);
        }
        __syncthreads();                     // all warps done reading buf
        if (t + 2 < NTILES) {
            const __half* Ap2 = Ap + (t + 2) * 32;
            const __half* Bp2 = Bp + (t + 2) * 32;
            cp16(aDst + buf * BUFBYTES, Ap2, aval);
            cp16(aDst + buf * BUFBYTES + 16, Ap2 + 8, aval);
            cp16(bDst + buf * BUFBYTES, Bp2, true);
            cp16(bDst + buf * BUFBYTES + 16, Bp2 + 8, true);
            CP_COMMIT();
            CP_WAIT1();
            __syncthreads();
        } else if (t + 1 < NTILES) {
            CP_WAIT0();
            __syncthreads();
        }
    }

#pragma unroll
    for (int mi = 0; mi < 4; mi++) {
        const int r0 = bm + wm * 64 + mi * 16 + grp;
#pragma unroll
        for (int ni = 0; ni < 4; ni++) {
            const int c0 = bn + wn * 32 + ni * 8 + 2 * tig;
            if (r0 < M)
                *(__half2*)&C[(long long)r0 * N + c0] =
                    __floats2half2_rn(acc[mi][ni][0], acc[mi][ni][1]);
            if (r0 + 8 < M)
                *(__half2*)&C[(long long)(r0 + 8) * N + c0] =
                    __floats2half2_rn(acc[mi][ni][2], acc[mi][ni][3]);
        }
    }
}

// ---- GEMM2 fully fused: logits + softmax + combine ------------------------
// A = g_zh fp16 (rows g = node*4 + p), B = g_w1T fp16 [128][256] k-major.
__global__ void __launch_bounds__(256, 2) k_gemm_attn(
    const __half* __restrict__ A, const __half* __restrict__ B,
    const float* __restrict__ b1v, const float* __restrict__ w2v,
    float* __restrict__ out, int M)
{
    const int K = 256;
    __shared__ uint32_t As[2][128][SPITCH];
    __shared__ uint32_t Bs[2][128][SPITCH];
    __shared__ float rowsum[128];
    __shared__ float w2s[128];
    __shared__ float b1s[128];

    const int tid  = threadIdx.x;
    const int lane = tid & 31;
    const int warp = tid >> 5;
    const int wm = warp & 1;
    const int wn = warp >> 1;
    const int grp = lane >> 2;
    const int tig = lane & 3;
    const int bm = blockIdx.y * 128;

    const int lrow = tid >> 1;
    const int lkc  = (tid & 1) * 8;
    const bool aval = (bm + lrow) < M;
    const __half* Ap = A + (long long)(bm + lrow) * K + lkc * 2;
    const __half* Bp = B + (long long)lrow * K + lkc * 2;   // N=128 rows

    const uint32_t asBase = (uint32_t)__cvta_generic_to_shared(&As[0][0][0]);
    const uint32_t bsBase = (uint32_t)__cvta_generic_to_shared(&Bs[0][0][0]);
    const uint32_t aDst = asBase + ((lrow * SPITCH + lkc) << 2);
    const uint32_t bDst = bsBase + ((lrow * SPITCH + lkc) << 2);
    const uint32_t aAddr0 = asBase +
        (((wm * 64 + (lane & 15)) * SPITCH + (lane >> 4) * 4) << 2);
    const uint32_t bAddr0 = bsBase +
        (((wn * 32 + ((lane >> 4) << 3) + (lane & 7)) * SPITCH
          + ((lane >> 3) & 1) * 4) << 2);

    float acc[4][4][4] = {};

    cp16(aDst, Ap, aval);            cp16(aDst + 16, Ap + 8, aval);
    cp16(bDst, Bp, true);            cp16(bDst + 16, Bp + 8, true);
    CP_COMMIT();
    cp16(aDst + BUFBYTES, Ap + 32, aval); cp16(aDst + BUFBYTES + 16, Ap + 40, aval);
    cp16(bDst + BUFBYTES, Bp + 32, true); cp16(bDst + BUFBYTES + 16, Bp + 40, true);
    CP_COMMIT();
    if (tid < 128) { rowsum[tid] = 0.f; w2s[tid] = w2v[tid]; b1s[tid] = b1v[tid]; }
    CP_WAIT1();
    __syncthreads();

    for (int t = 0; t < NTILES; t++) {
        const int buf = t & 1;
#pragma unroll
        for (int ks = 0; ks < 2; ks++) {
            uint32_t afr[4][4], bfr[4][2];
            const uint32_t ao = aAddr0 + buf * BUFBYTES + ks * 32;
            const uint32_t bo = bAddr0 + buf * BUFBYTES + ks * 32;
#pragma unroll
            for (int mi = 0; mi < 4; mi++)
                ldsm_x4(afr[mi][0], afr[mi][1], afr[mi][2], afr[mi][3],
                        ao + mi * MIBYTES);
            ldsm_x4(bfr[0][0], bfr[0][1], bfr[1][0], bfr[1][1], bo);
            ldsm_x4(bfr[2][0], bfr[2][1], bfr[3][0], bfr[3][1], bo + MIBYTES);
#pragma unroll
            for (int mi = 0; mi < 4; mi++)
#pragma unroll
                for (int ni = 0; ni < 4; ni++)
                    mma_f16(acc[mi][ni], afr[mi], bfr[ni]);
        }
        __syncthreads();
        if (t + 2 < NTILES) {
            const __half* Ap2 = Ap + (t + 2) * 32;
            const __half* Bp2 = Bp + (t + 2) * 32;
            cp16(aDst + buf * BUFBYTES, Ap2, aval);
            cp16(aDst + buf * BUFBYTES + 16, Ap2 + 8, aval);
            cp16(bDst + buf * BUFBYTES, Bp2, true);
            cp16(bDst + buf * BUFBYTES + 16, Bp2 + 8, true);
            CP_COMMIT();
            CP_WAIT1();
            __syncthreads();
        } else if (t + 1 < NTILES) {
            CP_WAIT0();
            __syncthreads();
        }
    }

    // ---- logits: tanh(acc + b1) . w2, reduced per row ----
#pragma unroll
    for (int mi = 0; mi < 4; mi++) {
        float p0 = 0.f, p1 = 0.f;
#pragma unroll
        for (int ni = 0; ni < 4; ni++) {
            const int c0 = wn * 32 + ni * 8 + 2 * tig;
            float t;
            t = tanhf(acc[mi][ni][0] + b1s[c0]);     p0 += t * w2s[c0];
            t = tanhf(acc[mi][ni][1] + b1s[c0 + 1]); p0 += t * w2s[c0 + 1];
            t = tanhf(acc[mi][ni][2] + b1s[c0]);     p1 += t * w2s[c0];
            t = tanhf(acc[mi][ni][3] + b1s[c0 + 1]); p1 += t * w2s[c0 + 1];
        }
        p0 += __shfl_xor_sync(0xffffffffu, p0, 1);
        p0 += __shfl_xor_sync(0xffffffffu, p0, 2);
        p1 += __shfl_xor_sync(0xffffffffu, p1, 1);
        p1 += __shfl_xor_sync(0xffffffffu, p1, 2);
        if (tig == 0) {
            atomicAdd(&rowsum[wm * 64 + mi * 16 + grp], p0);
            atomicAdd(&rowsum[wm * 64 + mi * 16 + grp + 8], p1);
        }
    }
    __syncthreads();

    // ---- per-node softmax over the 4 paths ----
    int nib = (M - bm) >> 2;
    const int nodes_in_blk = nib < 32 ? nib : 32;
    if (tid < 32 && tid < nodes_in_blk) {
        float l0 = rowsum[tid * 4], l1 = rowsum[tid * 4 + 1];
        float l2 = rowsum[tid * 4 + 2], l3 = rowsum[tid * 4 + 3];
        float m = fmaxf(fmaxf(l0, l1), fmaxf(l2, l3));
        float e0 = __expf(l0 - m), e1 = __expf(l1 - m);
        float e2 = __expf(l2 - m), e3 = __expf(l3 - m);
        float inv = 1.0f / (e0 + e1 + e2 + e3);
        rowsum[tid * 4]     = e0 * inv;
        rowsum[tid * 4 + 1] = e1 * inv;
        rowsum[tid * 4 + 2] = e2 * inv;
        rowsum[tid * 4 + 3] = e3 * inv;
    }
    __syncthreads();

    // ---- combine: out[node][d] = sum_p beta * z (z tile hot in L2) ----
    const int node0 = bm >> 2;
#pragma unroll
    for (int i = 0; i < 32; i++) {
        int idx = tid + 256 * i;
        int nl = idx >> 8;
        int dd = idx & 255;
        if (nl >= nodes_in_blk) break;
        const __half* zr = A + (long long)(bm + nl * 4) * K + dd;
        float v = rowsum[nl * 4]     * __half2float(zr[0])
                + rowsum[nl * 4 + 1] * __half2float(zr[K])
                + rowsum[nl * 4 + 2] * __half2float(zr[2 * K])
                + rowsum[nl * 4 + 3] * __half2float(zr[3 * K]);
        out[(long long)(node0 + nl) * D + dd] = v;
    }
}

// ---------------- GCN aggregation pipeline (all 4 paths batched) -----------
__global__ void k_deg_init() {
    int i = blockIdx.x * 256 + threadIdx.x;
    if (i < NG) g_deg[i] = 1;   // self loop
}

__global__ void k_hist(const int* __restrict__ eidx) {
    int e = blockIdx.x * 256 + threadIdx.x;
    if (e < NP * NE) {
        int p = e / NE, i = e - p * NE;
        int dst = eidx[(size_t)p * 2 * NE + NE + i];
        atomicAdd(&g_deg[p * NN + dst], 1);
    }
}

__global__ void k_scan1() {
    __shared__ int red[8];
    int b = blockIdx.x, tid = threadIdx.x;
    int lane = tid & 31, warp = tid >> 5;
    int i0 = b * 512 + tid * 2;
    int s = 0;
    if (i0 < NG)     s += g_deg[i0] - 1;
    if (i0 + 1 < NG) s += g_deg[i0 + 1] - 1;
#pragma unroll
    for (int o = 16; o; o >>= 1) s += __shfl_xor_sync(0xffffffffu, s, o);
    if (lane == 0) red[warp] = s;
    __syncthreads();
    if (tid == 0) {
        int t = 0;
#pragma unroll
        for (int w = 0; w < 8; w++) t += red[w];
        g_part[b] = t;
    }
}

__global__ void k_scan2() {
    __shared__ int s[512];
    int tid = threadIdx.x;
    int v = (tid < SCAN_BLK) ? g_part[tid] : 0;
    s[tid] = v;
    __syncthreads();
    for (int off = 1; off < 512; off <<= 1) {
        int u = (tid >= off) ? s[tid - off] : 0;
        __syncthreads();
        s[tid] += u;
        __syncthreads();
    }
    if (tid < SCAN_BLK) g_part[tid] = s[tid] - v;   // exclusive
}

__global__ void k_scan3() {
    __shared__ int wsum[8];
    int b = blockIdx.x, tid = threadIdx.x;
    int lane = tid & 31, warp = tid >> 5;
    int i0 = b * 512 + tid * 2;
    int d0 = (i0 < NG) ? g_deg[i0] : 1;
    int d1 = (i0 + 1 < NG) ? g_deg[i0 + 1] : 1;
    int v0 = d0 - 1, v1 = d1 - 1;
    int s = v0 + v1;
    int sc = s;
#pragma unroll
    for (int o = 1; o < 32; o <<= 1) {
        int u = __shfl_up_sync(0xffffffffu, sc, o);
        if (lane >= o) sc += u;
    }
    if (lane == 31) wsum[warp] = sc;
    __syncthreads();
    int wbase = 0;
    for (int w = 0; w < warp; w++) wbase += wsum[w];
    int base = g_part[b] + wbase + (sc - s);
    if (i0 < NG) {
        g_rowoff[i0] = base; g_rowcur[i0] = base;
        g_dinv[i0] = rsqrtf((float)d0);
    }
    if (i0 + 1 < NG) {
        g_rowoff[i0 + 1] = base + v0; g_rowcur[i0 + 1] = base + v0;
        g_dinv[i0 + 1] = rsqrtf((float)d1);
    }
    if (b == 0 && tid == 0) g_rowoff[NG] = NP * NE;
}

__global__ void k_fill(const int* __restrict__ eidx) {
    int e = blockIdx.x * 256 + threadIdx.x;
    if (e < NP * NE) {
        int p = e / NE, i = e - p * NE;
        int src = eidx[(size_t)p * 2 * NE + i];
        int dst = eidx[(size_t)p * 2 * NE + NE + i];
        int pos = atomicAdd(&g_rowcur[p * NN + dst], 1);
        g_srcs[pos] = src;
    }
}

// pull: one warp per (path,node); LDG.128 gather (lane owns 8 contiguous
// halves), 4-edge unroll, fp32 acc. z written INTERLEAVED row (node*4 + p).
__global__ void k_pull(const float* __restrict__ bs) {
    int g = blockIdx.x * 8 + (threadIdx.x >> 5);
    if (g >= NG) return;
    int lane = threadIdx.x & 31;
    int p = g / NN, node = g - p * NN;

    float di = g_dinv[g];
    const uint4* xw = (const uint4*)g_xwh + (size_t)p * (NND / 8);
    float acc[8];
    {
        uint4 v = xw[(size_t)node * 32 + lane];
        const __half2* h = (const __half2*)&v;
        float dd = di * di;
#pragma unroll
        for (int j = 0; j < 4; j++) {
            float2 f = __half22float2(h[j]);
            acc[2 * j]     = dd * f.x;
            acc[2 * j + 1] = dd * f.y;
        }
    }

    int beg = g_rowoff[g];
    int end = g_rowoff[g + 1];
    const float* dv = g_dinv + p * NN;
    int e = beg;
    for (; e + 4 <= end; e += 4) {
        int s0 = g_srcs[e], s1 = g_srcs[e + 1], s2 = g_srcs[e + 2], s3 = g_srcs[e + 3];
        float n0 = di * dv[s0], n1 = di * dv[s1], n2 = di * dv[s2], n3 = di * dv[s3];
        uint4 v0 = xw[(size_t)s0 * 32 + lane];
        uint4 v1 = xw[(size_t)s1 * 32 + lane];
        uint4 v2 = xw[(size_t)s2 * 32 + lane];
        uint4 v3 = xw[(size_t)s3 * 32 + lane];
        const __half2* h0 = (const __half2*)&v0;
        const __half2* h1 = (const __half2*)&v1;
        const __half2* h2 = (const __half2*)&v2;
        const __half2* h3 = (const __half2*)&v3;
#pragma unroll
        for (int j = 0; j < 4; j++) {
            float2 f0 = __half22float2(h0[j]);
            float2 f1 = __half22float2(h1[j]);
            float2 f2 = __half22float2(h2[j]);
            float2 f3 = __half22float2(h3[j]);
            acc[2 * j]     = fmaf(n0, f0.x, fmaf(n1, f1.x,
                             fmaf(n2, f2.x, fmaf(n3, f3.x, acc[2 * j]))));
            acc[2 * j + 1] = fmaf(n0, f0.y, fmaf(n1, f1.y,
                             fmaf(n2, f2.y, fmaf(n3, f3.y, acc[2 * j + 1]))));
        }
    }
    for (; e < end; e++) {
        int s0 = g_srcs[e];
        float n0 = di * dv[s0];
        uint4 v0 = xw[(size_t)s0 * 32 + lane];
        const __half2* h0 = (const __half2*)&v0;
#pragma unroll
        for (int j = 0; j < 4; j++) {
            float2 f0 = __half22float2(h0[j]);
            acc[2 * j]     = fmaf(n0, f0.x, acc[2 * j]);
            acc[2 * j + 1] = fmaf(n0, f0.y, acc[2 * j + 1]);
        }
    }

    // write: lane owns dims [lane*8, lane*8+8)
    int c = lane * 8;
    const float4* bp4 = (const float4*)(bs + p * D + c);
    float4 b0 = bp4[0], b1 = bp4[1];
    uint4 o;
    __half2* oh = (__half2*)&o;
    oh[0] = __floats2half2_rn(acc[0] + b0.x, acc[1] + b0.y);
    oh[1] = __floats2half2_rn(acc[2] + b0.z, acc[3] + b0.w);
    oh[2] = __floats2half2_rn(acc[4] + b1.x, acc[5] + b1.y);
    oh[3] = __floats2half2_rn(acc[6] + b1.z, acc[7] + b1.w);
    ((uint4*)g_zh)[((size_t)node * NP + p) * 32 + lane] = o;
}

// ---------------- launch ----------------------------------------------------
extern "C" void kernel_launch(void* const* d_in, const int* in_sizes, int n_in,
                              void* d_out, int out_size) {
    const float* x    = (const float*)d_in[0];
    const int*   eidx = (const int*)d_in[1];
    const float* Ws   = (const float*)d_in[2];
    const float* bs   = (const float*)d_in[3];
    const float* w1   = (const float*)d_in[4];
    const float* b1   = (const float*)d_in[5];
    const float* w2   = (const float*)d_in[6];
    float* out = (float*)d_out;

    void* p_xh = nullptr; void* p_wsT = nullptr; void* p_w1T = nullptr;
    void* p_xwh = nullptr; void* p_zh = nullptr;
    cudaGetSymbolAddress(&p_xh,  g_xh);
    cudaGetSymbolAddress(&p_wsT, g_wsT);
    cudaGetSymbolAddress(&p_w1T, g_w1T);
    cudaGetSymbolAddress(&p_xwh, g_xwh);
    cudaGetSymbolAddress(&p_zh,  g_zh);

    // prep: fp16 conversions + weight transposes
    k_cvt_x<<<(NND / 4 + 255) / 256, 256>>>(x);
    k_cvt_wT<<<dim3(D / 32, D / 32, NP), dim3(32, 8)>>>(Ws, (__half*)p_wsT, D, D);
    k_cvt_wT<<<dim3(D / 32, DH / 32, 1), dim3(32, 8)>>>(w1, (__half*)p_w1T, D, DH);

    // xw[p] = xh @ WsT[p]^T  -> fp16 (batched over z; bias added in pull)
    k_gemm_xw<<<dim3(D / 128, (NN + 127) / 128, NP), 256>>>(
        (const __half*)p_xh, (const __half*)p_wsT, (__half*)p_xwh, NN, D,
        (long long)D * D, (long long)NND);

    // CSR build for all 4 paths at once
    k_deg_init<<<(NG + 255) / 256, 256>>>();
    k_hist<<<(NP * NE + 255) / 256, 256>>>(eidx);
    k_scan1<<<SCAN_BLK, 256>>>();
    k_scan2<<<1, 512>>>();
    k_scan3<<<SCAN_BLK, 256>>>();
    k_fill<<<(NP * NE + 255) / 256, 256>>>(eidx);
    k_pull<<<(NG + 7) / 8, 256>>>(bs);

    // fused: logits + softmax + combine -> out
    k_gemm_attn<<<dim3(1, (NROWS + 127) / 128), 256>>>(
        (const __half*)p_zh, (const __half*)p_w1T, b1, w2, out, NROWS);
}

// round 11
// speedup vs baseline: 4.4354x; 1.0228x over previous
#include <cuda_runtime.h>
#include <cuda_fp16.h>
#include <math.h>
#include <stdint.h>

#define NN 50000
#define NP 4
#define NE 800000
#define D 256
#define DH 128
#define NND (NN * D)
#define NROWS (NP * NN)
#define NG (NP * NN)              // total (path,node) rows = 200000
#define SCAN_BLK 391              // ceil(200000/512)

// ---------------- scratch (device globals; no allocation allowed) ----------
__device__ __half g_xh[NND];           // x in fp16 [50000][256]
__device__ __half g_wsT[NP * D * D];   // Ws transposed [p][n][k] fp16
__device__ __half g_w1T[DH * D];       // W1 transposed [n][k] fp16
__device__ __half g_xwh[NP * NND];     // x@W_p fp16 (pull-only)
__device__ __half g_zh[NP * NND];      // z interleaved [node][path][256] fp16
__device__ int   g_deg[NG];
__device__ float g_dinv[NG];
__device__ int   g_rowoff[NG + 1];
__device__ int   g_rowcur[NG];
__device__ int   g_srcs[NP * NE];
__device__ int   g_part[SCAN_BLK];

// ---------------- mma / ldmatrix / cp.async helpers -------------------------
__device__ __forceinline__ void mma_f16(float* d, const uint32_t* a,
                                        const uint32_t* b) {
    asm volatile(
        "mma.sync.aligned.m16n8k16.row.col.f32.f16.f16.f32 "
        "{%0,%1,%2,%3}, {%4,%5,%6,%7}, {%8,%9}, {%0,%1,%2,%3};\n"
        : "+f"(d[0]), "+f"(d[1]), "+f"(d[2]), "+f"(d[3])
        : "r"(a[0]), "r"(a[1]), "r"(a[2]), "r"(a[3]),
          "r"(b[0]), "r"(b[1]));
}

__device__ __forceinline__ void ldsm_x4(uint32_t& r0, uint32_t& r1,
                                        uint32_t& r2, uint32_t& r3,
                                        uint32_t addr) {
    asm volatile("ldmatrix.sync.aligned.m8n8.x4.shared.b16 {%0,%1,%2,%3}, [%4];"
                 : "=r"(r0), "=r"(r1), "=r"(r2), "=r"(r3) : "r"(addr));
}

__device__ __forceinline__ void cp16(uint32_t dst, const void* src, bool pred) {
    asm volatile("cp.async.cg.shared.global [%0], [%1], 16, %2;"
                 :: "r"(dst), "l"(src), "r"(pred ? 16 : 0) : "memory");
}
#define CP_COMMIT() asm volatile("cp.async.commit_group;" ::: "memory")

// smem geometry: pitch 20 uint32/row, 128 rows/stage, 4 stages
#define SPITCH 20
#define BUFBYTES (128 * SPITCH * 4)     // 10240 per stage per operand
#define MIBYTES  (16 * SPITCH * 4)      // 1280
#define NSTAGE 4
#define NTILES 8                        // K = 256, BK = 32
#define DYNBYTES (2 * NSTAGE * BUFBYTES)  // 81920

// ---------------- prep: fp32 -> fp16 conversions ---------------------------
__global__ void k_cvt_x(const float* __restrict__ x) {
    int i = blockIdx.x * 256 + threadIdx.x;      // over float4s
    if (i < NND / 4) {
        float4 v = ((const float4*)x)[i];
        __half2* o = (__half2*)g_xh + i * 2;
        o[0] = __floats2half2_rn(v.x, v.y);
        o[1] = __floats2half2_rn(v.z, v.w);
    }
}

// transpose [z][K][N] fp32 -> [z][N][K] fp16 (K,N multiples of 32)
__global__ void k_cvt_wT(const float* __restrict__ in, __half* __restrict__ out,
                         int K, int N) {
    __shared__ float t[32][33];
    int z = blockIdx.z;
    int k0 = blockIdx.x * 32, n0 = blockIdx.y * 32;
    int tx = threadIdx.x, ty = threadIdx.y;      // 32 x 8
    const float* ip = in + (size_t)z * K * N;
    __half* op = out + (size_t)z * K * N;
#pragma unroll
    for (int j = 0; j < 32; j += 8)
        t[ty + j][tx] = ip[(size_t)(k0 + ty + j) * N + n0 + tx];
    __syncthreads();
#pragma unroll
    for (int j = 0; j < 32; j += 8)
        op[(size_t)(n0 + ty + j) * K + k0 + tx] = __float2half(t[tx][ty + j]);
}

// mainloop body (shared by both GEMMs): 4-stage ring, one sync per tile.
#define GEMM_MAINLOOP()                                                        \
    _Pragma("unroll")                                                          \
    for (int s = 0; s < NSTAGE - 1; s++) {                                     \
        const __half* Ap2 = Ap + s * 32;                                       \
        const __half* Bp2 = Bp + s * 32;                                       \
        cp16(aDstB + s * BUFBYTES, Ap2, aval);                                 \
        cp16(aDstB + s * BUFBYTES + 16, Ap2 + 8, aval);                        \
        cp16(bDstB + s * BUFBYTES, Bp2, true);                                 \
        cp16(bDstB + s * BUFBYTES + 16, Bp2 + 8, true);                        \
        CP_COMMIT();                                                           \
    }                                                                          \
    _Pragma("unroll")                                                          \
    for (int t = 0; t < NTILES; t++) {                                         \
        if (t < NTILES - 2)                                                    \
            asm volatile("cp.async.wait_group 2;" ::: "memory");               \
        else if (t == NTILES - 2)                                              \
            asm volatile("cp.async.wait_group 1;" ::: "memory");               \
        else                                                                   \
            asm volatile("cp.async.wait_group 0;" ::: "memory");               \
        __syncthreads();                                                       \
        if (t + NSTAGE - 1 < NTILES) {                                         \
            const int ws = (t + NSTAGE - 1) & (NSTAGE - 1);                    \
            const __half* Ap2 = Ap + (t + NSTAGE - 1) * 32;                    \
            const __half* Bp2 = Bp + (t + NSTAGE - 1) * 32;                    \
            cp16(aDstB + ws * BUFBYTES, Ap2, aval);                            \
            cp16(aDstB + ws * BUFBYTES + 16, Ap2 + 8, aval);                   \
            cp16(bDstB + ws * BUFBYTES, Bp2, true);                            \
            cp16(bDstB + ws * BUFBYTES + 16, Bp2 + 8, true);                   \
            CP_COMMIT();                                                       \
        }                                                                      \
        const int slot = t & (NSTAGE - 1);                                     \
        _Pragma("unroll")                                                      \
        for (int ks = 0; ks < 2; ks++) {                                       \
            uint32_t afr[4][4], bfr[4][2];                                     \
            const uint32_t ao = aAddrB + slot * BUFBYTES + ks * 32;            \
            const uint32_t bo = bAddrB + slot * BUFBYTES + ks * 32;            \
            _Pragma("unroll")                                                  \
            for (int mi = 0; mi < 4; mi++)                                     \
                ldsm_x4(afr[mi][0], afr[mi][1], afr[mi][2], afr[mi][3],        \
                        ao + mi * MIBYTES);                                    \
            ldsm_x4(bfr[0][0], bfr[0][1], bfr[1][0], bfr[1][1], bo);           \
            ldsm_x4(bfr[2][0], bfr[2][1], bfr[3][0], bfr[3][1], bo + MIBYTES); \
            _Pragma("unroll")                                                  \
            for (int mi = 0; mi < 4; mi++)                                     \
                _Pragma("unroll")                                              \
                for (int ni = 0; ni < 4; ni++)                                 \
                    mma_f16(acc[mi][ni], afr[mi], bfr[ni]);                    \
        }                                                                      \
    }

// ---- GEMM1: xw[p] = xh @ WsT[p]^T (fp16 in, half out). 128x128, BK=32 -----
__global__ void __launch_bounds__(256, 2) k_gemm_xw(
    const __half* __restrict__ A, const __half* __restrict__ B,
    __half* __restrict__ C, int M, int N, long long sB, long long sC)
{
    const int K = 256;
    B += (long long)blockIdx.z * sB;
    C += (long long)blockIdx.z * sC;

    extern __shared__ uint32_t dynSmem[];

    const int tid  = threadIdx.x;
    const int lane = tid & 31;
    const int warp = tid >> 5;
    const int wm = warp & 1;
    const int wn = warp >> 1;
    const int grp = lane >> 2;
    const int tig = lane & 3;
    const int bm = blockIdx.y * 128;
    const int bn = blockIdx.x * 128;

    const int lrow = tid >> 1;               // 0..127
    const int lkc  = (tid & 1) * 8;          // half2 base 0 or 8
    const bool aval = (bm + lrow) < M;
    const __half* Ap = A + (long long)(bm + lrow) * K + lkc * 2;
    const __half* Bp = B + (long long)(bn + lrow) * K + lkc * 2;

    const uint32_t asBase = (uint32_t)__cvta_generic_to_shared(dynSmem);
    const uint32_t bsBase = asBase + NSTAGE * BUFBYTES;
    const uint32_t aDstB = asBase + ((lrow * SPITCH + lkc) << 2);
    const uint32_t bDstB = bsBase + ((lrow * SPITCH + lkc) << 2);
    const uint32_t aAddrB = asBase +
        (((wm * 64 + (lane & 15)) * SPITCH + (lane >> 4) * 4) << 2);
    const uint32_t bAddrB = bsBase +
        (((wn * 32 + ((lane >> 4) << 3) + (lane & 7)) * SPITCH
          + ((lane >> 3) & 1) * 4) << 2);

    float acc[4][4][4] = {};

    GEMM_MAINLOOP()

#pragma unroll
    for (int mi = 0; mi < 4; mi++) {
        const int r0 = bm + wm * 64 + mi * 16 + grp;
#pragma unroll
        for (int ni = 0; ni < 4; ni++) {
            const int c0 = bn + wn * 32 + ni * 8 + 2 * tig;
            if (r0 < M)
                *(__half2*)&C[(long long)r0 * N + c0] =
                    __floats2half2_rn(acc[mi][ni][0], acc[mi][ni][1]);
            if (r0 + 8 < M)
                *(__half2*)&C[(long long)(r0 + 8) * N + c0] =
                    __floats2half2_rn(acc[mi][ni][2], acc[mi][ni][3]);
        }
    }
}

// ---- GEMM2 fully fused: logits + softmax + combine ------------------------
// A = g_zh fp16 (rows g = node*4 + p), B = g_w1T fp16 [128][256] k-major.
__global__ void __launch_bounds__(256, 2) k_gemm_attn(
    const __half* __restrict__ A, const __half* __restrict__ B,
    const float* __restrict__ b1v, const float* __restrict__ w2v,
    float* __restrict__ out, int M)
{
    const int K = 256;
    extern __shared__ uint32_t dynSmem[];
    __shared__ float rowsum[128];
    __shared__ float w2s[128];
    __shared__ float b1s[128];

    const int tid  = threadIdx.x;
    const int lane = tid & 31;
    const int warp = tid >> 5;
    const int wm = warp & 1;
    const int wn = warp >> 1;
    const int grp = lane >> 2;
    const int tig = lane & 3;
    const int bm = blockIdx.y * 128;

    const int lrow = tid >> 1;
    const int lkc  = (tid & 1) * 8;
    const bool aval = (bm + lrow) < M;
    const __half* Ap = A + (long long)(bm + lrow) * K + lkc * 2;
    const __half* Bp = B + (long long)lrow * K + lkc * 2;   // N=128 rows

    const uint32_t asBase = (uint32_t)__cvta_generic_to_shared(dynSmem);
    const uint32_t bsBase = asBase + NSTAGE * BUFBYTES;
    const uint32_t aDstB = asBase + ((lrow * SPITCH + lkc) << 2);
    const uint32_t bDstB = bsBase + ((lrow * SPITCH + lkc) << 2);
    const uint32_t aAddrB = asBase +
        (((wm * 64 + (lane & 15)) * SPITCH + (lane >> 4) * 4) << 2);
    const uint32_t bAddrB = bsBase +
        (((wn * 32 + ((lane >> 4) << 3) + (lane & 7)) * SPITCH
          + ((lane >> 3) & 1) * 4) << 2);

    float acc[4][4][4] = {};

    if (tid < 128) { rowsum[tid] = 0.f; w2s[tid] = w2v[tid]; b1s[tid] = b1v[tid]; }

    GEMM_MAINLOOP()

    // ---- logits: tanh(acc + b1) . w2, reduced per row ----
#pragma unroll
    for (int mi = 0; mi < 4; mi++) {
        float p0 = 0.f, p1 = 0.f;
#pragma unroll
        for (int ni = 0; ni < 4; ni++) {
            const int c0 = wn * 32 + ni * 8 + 2 * tig;
            float t;
            t = tanhf(acc[mi][ni][0] + b1s[c0]);     p0 += t * w2s[c0];
            t = tanhf(acc[mi][ni][1] + b1s[c0 + 1]); p0 += t * w2s[c0 + 1];
            t = tanhf(acc[mi][ni][2] + b1s[c0]);     p1 += t * w2s[c0];
            t = tanhf(acc[mi][ni][3] + b1s[c0 + 1]); p1 += t * w2s[c0 + 1];
        }
        p0 += __shfl_xor_sync(0xffffffffu, p0, 1);
        p0 += __shfl_xor_sync(0xffffffffu, p0, 2);
        p1 += __shfl_xor_sync(0xffffffffu, p1, 1);
        p1 += __shfl_xor_sync(0xffffffffu, p1, 2);
        if (tig == 0) {
            atomicAdd(&rowsum[wm * 64 + mi * 16 + grp], p0);
            atomicAdd(&rowsum[wm * 64 + mi * 16 + grp + 8], p1);
        }
    }
    __syncthreads();

    // ---- per-node softmax over the 4 paths ----
    int nib = (M - bm) >> 2;
    const int nodes_in_blk = nib < 32 ? nib : 32;
    if (tid < 32 && tid < nodes_in_blk) {
        float l0 = rowsum[tid * 4], l1 = rowsum[tid * 4 + 1];
        float l2 = rowsum[tid * 4 + 2], l3 = rowsum[tid * 4 + 3];
        float m = fmaxf(fmaxf(l0, l1), fmaxf(l2, l3));
        float e0 = __expf(l0 - m), e1 = __expf(l1 - m);
        float e2 = __expf(l2 - m), e3 = __expf(l3 - m);
        float inv = 1.0f / (e0 + e1 + e2 + e3);
        rowsum[tid * 4]     = e0 * inv;
        rowsum[tid * 4 + 1] = e1 * inv;
        rowsum[tid * 4 + 2] = e2 * inv;
        rowsum[tid * 4 + 3] = e3 * inv;
    }
    __syncthreads();

    // ---- combine: out[node][d] = sum_p beta * z (z tile hot in L2) ----
    const int node0 = bm >> 2;
#pragma unroll
    for (int i = 0; i < 32; i++) {
        int idx = tid + 256 * i;
        int nl = idx >> 8;
        int dd = idx & 255;
        if (nl >= nodes_in_blk) break;
        const __half* zr = A + (long long)(bm + nl * 4) * K + dd;
        float v = rowsum[nl * 4]     * __half2float(zr[0])
                + rowsum[nl * 4 + 1] * __half2float(zr[K])
                + rowsum[nl * 4 + 2] * __half2float(zr[2 * K])
                + rowsum[nl * 4 + 3] * __half2float(zr[3 * K]);
        out[(long long)(node0 + nl) * D + dd] = v;
    }
}

// ---------------- GCN aggregation pipeline (all 4 paths batched) -----------
__global__ void k_deg_init() {
    int i = blockIdx.x * 256 + threadIdx.x;
    if (i < NG) g_deg[i] = 1;   // self loop
}

__global__ void k_hist(const int* __restrict__ eidx) {
    int e = blockIdx.x * 256 + threadIdx.x;
    if (e < NP * NE) {
        int p = e / NE, i = e - p * NE;
        int dst = eidx[(size_t)p * 2 * NE + NE + i];
        atomicAdd(&g_deg[p * NN + dst], 1);
    }
}

__global__ void k_scan1() {
    __shared__ int red[8];
    int b = blockIdx.x, tid = threadIdx.x;
    int lane = tid & 31, warp = tid >> 5;
    int i0 = b * 512 + tid * 2;
    int s = 0;
    if (i0 < NG)     s += g_deg[i0] - 1;
    if (i0 + 1 < NG) s += g_deg[i0 + 1] - 1;
#pragma unroll
    for (int o = 16; o; o >>= 1) s += __shfl_xor_sync(0xffffffffu, s, o);
    if (lane == 0) red[warp] = s;
    __syncthreads();
    if (tid == 0) {
        int t = 0;
#pragma unroll
        for (int w = 0; w < 8; w++) t += red[w];
        g_part[b] = t;
    }
}

__global__ void k_scan2() {
    __shared__ int s[512];
    int tid = threadIdx.x;
    int v = (tid < SCAN_BLK) ? g_part[tid] : 0;
    s[tid] = v;
    __syncthreads();
    for (int off = 1; off < 512; off <<= 1) {
        int u = (tid >= off) ? s[tid - off] : 0;
        __syncthreads();
        s[tid] += u;
        __syncthreads();
    }
    if (tid < SCAN_BLK) g_part[tid] = s[tid] - v;   // exclusive
}

__global__ void k_scan3() {
    __shared__ int wsum[8];
    int b = blockIdx.x, tid = threadIdx.x;
    int lane = tid & 31, warp = tid >> 5;
    int i0 = b * 512 + tid * 2;
    int d0 = (i0 < NG) ? g_deg[i0] : 1;
    int d1 = (i0 + 1 < NG) ? g_deg[i0 + 1] : 1;
    int v0 = d0 - 1, v1 = d1 - 1;
    int s = v0 + v1;
    int sc = s;
#pragma unroll
    for (int o = 1; o < 32; o <<= 1) {
        int u = __shfl_up_sync(0xffffffffu, sc, o);
        if (lane >= o) sc += u;
    }
    if (lane == 31) wsum[warp] = sc;
    __syncthreads();
    int wbase = 0;
    for (int w = 0; w < warp; w++) wbase += wsum[w];
    int base = g_part[b] + wbase + (sc - s);
    if (i0 < NG) {
        g_rowoff[i0] = base; g_rowcur[i0] = base;
        g_dinv[i0] = rsqrtf((float)d0);
    }
    if (i0 + 1 < NG) {
        g_rowoff[i0 + 1] = base + v0; g_rowcur[i0 + 1] = base + v0;
        g_dinv[i0 + 1] = rsqrtf((float)d1);
    }
    if (b == 0 && tid == 0) g_rowoff[NG] = NP * NE;
}

__global__ void k_fill(const int* __restrict__ eidx) {
    int e = blockIdx.x * 256 + threadIdx.x;
    if (e < NP * NE) {
        int p = e / NE, i = e - p * NE;
        int src = eidx[(size_t)p * 2 * NE + i];
        int dst = eidx[(size_t)p * 2 * NE + NE + i];
        int pos = atomicAdd(&g_rowcur[p * NN + dst], 1);
        g_srcs[pos] = src;
    }
}

// pull: one warp per (path,node); LDG.128 gather (lane owns 8 contiguous
// halves), 4-edge unroll, fp32 acc. z written INTERLEAVED row (node*4 + p).
__global__ void k_pull(const float* __restrict__ bs) {
    int g = blockIdx.x * 8 + (threadIdx.x >> 5);
    if (g >= NG) return;
    int lane = threadIdx.x & 31;
    int p = g / NN, node = g - p * NN;

    float di = g_dinv[g];
    const uint4* xw = (const uint4*)g_xwh + (size_t)p * (NND / 8);
    float acc[8];
    {
        uint4 v = xw[(size_t)node * 32 + lane];
        const __half2* h = (const __half2*)&v;
        float dd = di * di;
#pragma unroll
        for (int j = 0; j < 4; j++) {
            float2 f = __half22float2(h[j]);
            acc[2 * j]     = dd * f.x;
            acc[2 * j + 1] = dd * f.y;
        }
    }

    int beg = g_rowoff[g];
    int end = g_rowoff[g + 1];
    const float* dv = g_dinv + p * NN;
    int e = beg;
    for (; e + 4 <= end; e += 4) {
        int s0 = g_srcs[e], s1 = g_srcs[e + 1], s2 = g_srcs[e + 2], s3 = g_srcs[e + 3];
        float n0 = di * dv[s0], n1 = di * dv[s1], n2 = di * dv[s2], n3 = di * dv[s3];
        uint4 v0 = xw[(size_t)s0 * 32 + lane];
        uint4 v1 = xw[(size_t)s1 * 32 + lane];
        uint4 v2 = xw[(size_t)s2 * 32 + lane];
        uint4 v3 = xw[(size_t)s3 * 32 + lane];
        const __half2* h0 = (const __half2*)&v0;
        const __half2* h1 = (const __half2*)&v1;
        const __half2* h2 = (const __half2*)&v2;
        const __half2* h3 = (const __half2*)&v3;
#pragma unroll
        for (int j = 0; j < 4; j++) {
            float2 f0 = __half22float2(h0[j]);
            float2 f1 = __half22float2(h1[j]);
            float2 f2 = __half22float2(h2[j]);
            float2 f3 = __half22float2(h3[j]);
            acc[2 * j]     = fmaf(n0, f0.x, fmaf(n1, f1.x,
                             fmaf(n2, f2.x, fmaf(n3, f3.x, acc[2 * j]))));
            acc[2 * j + 1] = fmaf(n0, f0.y, fmaf(n1, f1.y,
                             fmaf(n2, f2.y, fmaf(n3, f3.y, acc[2 * j + 1]))));
        }
    }
    for (; e < end; e++) {
        int s0 = g_srcs[e];
        float n0 = di * dv[s0];
        uint4 v0 = xw[(size_t)s0 * 32 + lane];
        const __half2* h0 = (const __half2*)&v0;
#pragma unroll
        for (int j = 0; j < 4; j++) {
            float2 f0 = __half22float2(h0[j]);
            acc[2 * j]     = fmaf(n0, f0.x, acc[2 * j]);
            acc[2 * j + 1] = fmaf(n0, f0.y, acc[2 * j + 1]);
        }
    }

    // write: lane owns dims [lane*8, lane*8+8)
    int c = lane * 8;
    const float4* bp4 = (const float4*)(bs + p * D + c);
    float4 b0 = bp4[0], b1 = bp4[1];
    uint4 o;
    __half2* oh = (__half2*)&o;
    oh[0] = __floats2half2_rn(acc[0] + b0.x, acc[1] + b0.y);
    oh[1] = __floats2half2_rn(acc[2] + b0.z, acc[3] + b0.w);
    oh[2] = __floats2half2_rn(acc[4] + b1.x, acc[5] + b1.y);
    oh[3] = __floats2half2_rn(acc[6] + b1.z, acc[7] + b1.w);
    ((uint4*)g_zh)[((size_t)node * NP + p) * 32 + lane] = o;
}

// ---------------- launch ----------------------------------------------------
extern "C" void kernel_launch(void* const* d_in, const int* in_sizes, int n_in,
                              void* d_out, int out_size) {
    const float* x    = (const float*)d_in[0];
    const int*   eidx = (const int*)d_in[1];
    const float* Ws   = (const float*)d_in[2];
    const float* bs   = (const float*)d_in[3];
    const float* w1   = (const float*)d_in[4];
    const float* b1   = (const float*)d_in[5];
    const float* w2   = (const float*)d_in[6];
    float* out = (float*)d_out;

    void* p_xh = nullptr; void* p_wsT = nullptr; void* p_w1T = nullptr;
    void* p_xwh = nullptr; void* p_zh = nullptr;
    cudaGetSymbolAddress(&p_xh,  g_xh);
    cudaGetSymbolAddress(&p_wsT, g_wsT);
    cudaGetSymbolAddress(&p_w1T, g_w1T);
    cudaGetSymbolAddress(&p_xwh, g_xwh);
    cudaGetSymbolAddress(&p_zh,  g_zh);

    cudaFuncSetAttribute(k_gemm_xw,
        cudaFuncAttributeMaxDynamicSharedMemorySize, DYNBYTES);
    cudaFuncSetAttribute(k_gemm_attn,
        cudaFuncAttributeMaxDynamicSharedMemorySize, DYNBYTES);

    // prep: fp16 conversions + weight transposes
    k_cvt_x<<<(NND / 4 + 255) / 256, 256>>>(x);
    k_cvt_wT<<<dim3(D / 32, D / 32, NP), dim3(32, 8)>>>(Ws, (__half*)p_wsT, D, D);
    k_cvt_wT<<<dim3(D / 32, DH / 32, 1), dim3(32, 8)>>>(w1, (__half*)p_w1T, D, DH);

    // xw[p] = xh @ WsT[p]^T  -> fp16 (batched over z; bias added in pull)
    k_gemm_xw<<<dim3(D / 128, (NN + 127) / 128, NP), 256, DYNBYTES>>>(
        (const __half*)p_xh, (const __half*)p_wsT, (__half*)p_xwh, NN, D,
        (long long)D * D, (long long)NND);

    // CSR build for all 4 paths at once
    k_deg_init<<<(NG + 255) / 256, 256>>>();
    k_hist<<<(NP * NE + 255) / 256, 256>>>(eidx);
    k_scan1<<<SCAN_BLK, 256>>>();
    k_scan2<<<1, 512>>>();
    k_scan3<<<SCAN_BLK, 256>>>();
    k_fill<<<(NP * NE + 255) / 256, 256>>>(eidx);
    k_pull<<<(NG + 7) / 8, 256>>>(bs);

    // fused: logits + softmax + combine -> out
    k_gemm_attn<<<dim3(1, (NROWS + 127) / 128), 256, DYNBYTES>>>(
        (const __half*)p_zh, (const __half*)p_w1T, b1, w2, out, NROWS);
}

// round 12
// speedup vs baseline: 4.5047x; 1.0156x over previous
#include <cuda_runtime.h>
#include <cuda_fp16.h>
#include <math.h>
#include <stdint.h>

#define NN 50000
#define NP 4
#define NE 800000
#define D 256
#define DH 128
#define NND (NN * D)
#define NROWS (NP * NN)
#define NG (NP * NN)              // total (path,node) rows = 200000
#define SCAN_BLK 391              // ceil(200000/512)

// ---------------- scratch (device globals; no allocation allowed) ----------
__device__ __half g_xh[NND];           // x in fp16 [50000][256]
__device__ __half g_wsT[NP * D * D];   // Ws transposed [p][n][k] fp16
__device__ __half g_w1T[DH * D];       // W1 transposed [n][k] fp16
__device__ __half g_xwh[NP * NND];     // x@W_p fp16 (pull-only)
__device__ __half g_zh[NP * NND];      // z interleaved [node][path][256] fp16
__device__ int   g_deg[NG];
__device__ float g_dinv[NG];
__device__ int   g_rowoff[NG + 1];
__device__ int   g_rowcur[NG];
__device__ int   g_srcs[NP * NE];
__device__ int   g_part[SCAN_BLK];

// ---------------- mma / ldmatrix / cp.async helpers -------------------------
__device__ __forceinline__ void mma_f16(float* d, const uint32_t* a,
                                        const uint32_t* b) {
    asm volatile(
        "mma.sync.aligned.m16n8k16.row.col.f32.f16.f16.f32 "
        "{%0,%1,%2,%3}, {%4,%5,%6,%7}, {%8,%9}, {%0,%1,%2,%3};\n"
        : "+f"(d[0]), "+f"(d[1]), "+f"(d[2]), "+f"(d[3])
        : "r"(a[0]), "r"(a[1]), "r"(a[2]), "r"(a[3]),
          "r"(b[0]), "r"(b[1]));
}

__device__ __forceinline__ void ldsm_x4(uint32_t& r0, uint32_t& r1,
                                        uint32_t& r2, uint32_t& r3,
                                        uint32_t addr) {
    asm volatile("ldmatrix.sync.aligned.m8n8.x4.shared.b16 {%0,%1,%2,%3}, [%4];"
                 : "=r"(r0), "=r"(r1), "=r"(r2), "=r"(r3) : "r"(addr));
}

__device__ __forceinline__ void cp16(uint32_t dst, const void* src, bool pred) {
    asm volatile("cp.async.cg.shared.global [%0], [%1], 16, %2;"
                 :: "r"(dst), "l"(src), "r"(pred ? 16 : 0) : "memory");
}
#define CP_COMMIT() asm volatile("cp.async.commit_group;" ::: "memory")

// smem geometry: pitch 20 uint32/row, 128 rows/stage, 4 stages
#define SPITCH 20
#define BUFBYTES (128 * SPITCH * 4)     // 10240 per stage per operand
#define MIBYTES  (16 * SPITCH * 4)      // 1280
#define NSTAGE 4
#define NTILES 8                        // K = 256, BK = 32
#define DYNBYTES (2 * NSTAGE * BUFBYTES)  // 81920

// ---------------- prep: fp32 -> fp16 conversions ---------------------------
__global__ void k_cvt_x(const float* __restrict__ x) {
    int i = blockIdx.x * 256 + threadIdx.x;      // over float4s
    if (i < NND / 4) {
        float4 v = ((const float4*)x)[i];
        __half2* o = (__half2*)g_xh + i * 2;
        o[0] = __floats2half2_rn(v.x, v.y);
        o[1] = __floats2half2_rn(v.z, v.w);
    }
}

// transpose [z][K][N] fp32 -> [z][N][K] fp16 (K,N multiples of 32)
__global__ void k_cvt_wT(const float* __restrict__ in, __half* __restrict__ out,
                         int K, int N) {
    __shared__ float t[32][33];
    int z = blockIdx.z;
    int k0 = blockIdx.x * 32, n0 = blockIdx.y * 32;
    int tx = threadIdx.x, ty = threadIdx.y;      // 32 x 8
    const float* ip = in + (size_t)z * K * N;
    __half* op = out + (size_t)z * K * N;
#pragma unroll
    for (int j = 0; j < 32; j += 8)
        t[ty + j][tx] = ip[(size_t)(k0 + ty + j) * N + n0 + tx];
    __syncthreads();
#pragma unroll
    for (int j = 0; j < 32; j += 8)
        op[(size_t)(n0 + ty + j) * K + k0 + tx] = __float2half(t[tx][ty + j]);
}

// mainloop body (shared by both GEMMs): 4-stage ring, one sync per tile.
#define GEMM_MAINLOOP()                                                        \
    _Pragma("unroll")                                                          \
    for (int s = 0; s < NSTAGE - 1; s++) {                                     \
        const __half* Ap2 = Ap + s * 32;                                       \
        const __half* Bp2 = Bp + s * 32;                                       \
        cp16(aDstB + s * BUFBYTES, Ap2, aval);                                 \
        cp16(aDstB + s * BUFBYTES + 16, Ap2 + 8, aval);                        \
        cp16(bDstB + s * BUFBYTES, Bp2, true);                                 \
        cp16(bDstB + s * BUFBYTES + 16, Bp2 + 8, true);                        \
        CP_COMMIT();                                                           \
    }                                                                          \
    _Pragma("unroll")                                                          \
    for (int t = 0; t < NTILES; t++) {                                         \
        if (t < NTILES - 2)                                                    \
            asm volatile("cp.async.wait_group 2;" ::: "memory");               \
        else if (t == NTILES - 2)                                              \
            asm volatile("cp.async.wait_group 1;" ::: "memory");               \
        else                                                                   \
            asm volatile("cp.async.wait_group 0;" ::: "memory");               \
        __syncthreads();                                                       \
        if (t + NSTAGE - 1 < NTILES) {                                         \
            const int ws = (t + NSTAGE - 1) & (NSTAGE - 1);                    \
            const __half* Ap2 = Ap + (t + NSTAGE - 1) * 32;                    \
            const __half* Bp2 = Bp + (t + NSTAGE - 1) * 32;                    \
            cp16(aDstB + ws * BUFBYTES, Ap2, aval);                            \
            cp16(aDstB + ws * BUFBYTES + 16, Ap2 + 8, aval);                   \
            cp16(bDstB + ws * BUFBYTES, Bp2, true);                            \
            cp16(bDstB + ws * BUFBYTES + 16, Bp2 + 8, true);                   \
            CP_COMMIT();                                                       \
        }                                                                      \
        const int slot = t & (NSTAGE - 1);                                     \
        _Pragma("unroll")                                                      \
        for (int ks = 0; ks < 2; ks++) {                                       \
            uint32_t afr[4][4], bfr[4][2];                                     \
            const uint32_t ao = aAddrB + slot * BUFBYTES + ks * 32;            \
            const uint32_t bo = bAddrB + slot * BUFBYTES + ks * 32;            \
            _Pragma("unroll")                                                  \
            for (int mi = 0; mi < 4; mi++)                                     \
                ldsm_x4(afr[mi][0], afr[mi][1], afr[mi][2], afr[mi][3],        \
                        ao + mi * MIBYTES);                                    \
            ldsm_x4(bfr[0][0], bfr[0][1], bfr[1][0], bfr[1][1], bo);           \
            ldsm_x4(bfr[2][0], bfr[2][1], bfr[3][0], bfr[3][1], bo + MIBYTES); \
            _Pragma("unroll")                                                  \
            for (int mi = 0; mi < 4; mi++)                                     \
                _Pragma("unroll")                                              \
                for (int ni = 0; ni < 4; ni++)                                 \
                    mma_f16(acc[mi][ni], afr[mi], bfr[ni]);                    \
        }                                                                      \
    }

// ---- GEMM1: xw[p] = xh @ WsT[p]^T (fp16 in, half out). 128x128, BK=32 -----
__global__ void __launch_bounds__(256, 2) k_gemm_xw(
    const __half* __restrict__ A, const __half* __restrict__ B,
    __half* __restrict__ C, int M, int N, long long sB, long long sC)
{
    const int K = 256;
    B += (long long)blockIdx.z * sB;
    C += (long long)blockIdx.z * sC;

    extern __shared__ uint32_t dynSmem[];

    const int tid  = threadIdx.x;
    const int lane = tid & 31;
    const int warp = tid >> 5;
    const int wm = warp & 1;
    const int wn = warp >> 1;
    const int grp = lane >> 2;
    const int tig = lane & 3;
    const int bm = blockIdx.y * 128;
    const int bn = blockIdx.x * 128;

    const int lrow = tid >> 1;               // 0..127
    const int lkc  = (tid & 1) * 8;          // half2 base 0 or 8
    const bool aval = (bm + lrow) < M;
    const __half* Ap = A + (long long)(bm + lrow) * K + lkc * 2;
    const __half* Bp = B + (long long)(bn + lrow) * K + lkc * 2;

    const uint32_t asBase = (uint32_t)__cvta_generic_to_shared(dynSmem);
    const uint32_t bsBase = asBase + NSTAGE * BUFBYTES;
    const uint32_t aDstB = asBase + ((lrow * SPITCH + lkc) << 2);
    const uint32_t bDstB = bsBase + ((lrow * SPITCH + lkc) << 2);
    const uint32_t aAddrB = asBase +
        (((wm * 64 + (lane & 15)) * SPITCH + (lane >> 4) * 4) << 2);
    const uint32_t bAddrB = bsBase +
        (((wn * 32 + ((lane >> 4) << 3) + (lane & 7)) * SPITCH
          + ((lane >> 3) & 1) * 4) << 2);

    float acc[4][4][4] = {};

    GEMM_MAINLOOP()

#pragma unroll
    for (int mi = 0; mi < 4; mi++) {
        const int r0 = bm + wm * 64 + mi * 16 + grp;
#pragma unroll
        for (int ni = 0; ni < 4; ni++) {
            const int c0 = bn + wn * 32 + ni * 8 + 2 * tig;
            if (r0 < M)
                *(__half2*)&C[(long long)r0 * N + c0] =
                    __floats2half2_rn(acc[mi][ni][0], acc[mi][ni][1]);
            if (r0 + 8 < M)
                *(__half2*)&C[(long long)(r0 + 8) * N + c0] =
                    __floats2half2_rn(acc[mi][ni][2], acc[mi][ni][3]);
        }
    }
}

// ---- GEMM2 fully fused: logits + softmax + combine ------------------------
// A = g_zh fp16 (rows g = node*4 + p), B = g_w1T fp16 [128][256] k-major.
__global__ void __launch_bounds__(256, 2) k_gemm_attn(
    const __half* __restrict__ A, const __half* __restrict__ B,
    const float* __restrict__ b1v, const float* __restrict__ w2v,
    float* __restrict__ out, int M)
{
    const int K = 256;
    extern __shared__ uint32_t dynSmem[];
    __shared__ float rowsum[128];
    __shared__ float w2s[128];
    __shared__ float b1s[128];

    const int tid  = threadIdx.x;
    const int lane = tid & 31;
    const int warp = tid >> 5;
    const int wm = warp & 1;
    const int wn = warp >> 1;
    const int grp = lane >> 2;
    const int tig = lane & 3;
    const int bm = blockIdx.y * 128;

    const int lrow = tid >> 1;
    const int lkc  = (tid & 1) * 8;
    const bool aval = (bm + lrow) < M;
    const __half* Ap = A + (long long)(bm + lrow) * K + lkc * 2;
    const __half* Bp = B + (long long)lrow * K + lkc * 2;   // N=128 rows

    const uint32_t asBase = (uint32_t)__cvta_generic_to_shared(dynSmem);
    const uint32_t bsBase = asBase + NSTAGE * BUFBYTES;
    const uint32_t aDstB = asBase + ((lrow * SPITCH + lkc) << 2);
    const uint32_t bDstB = bsBase + ((lrow * SPITCH + lkc) << 2);
    const uint32_t aAddrB = asBase +
        (((wm * 64 + (lane & 15)) * SPITCH + (lane >> 4) * 4) << 2);
    const uint32_t bAddrB = bsBase +
        (((wn * 32 + ((lane >> 4) << 3) + (lane & 7)) * SPITCH
          + ((lane >> 3) & 1) * 4) << 2);

    float acc[4][4][4] = {};

    if (tid < 128) { rowsum[tid] = 0.f; w2s[tid] = w2v[tid]; b1s[tid] = b1v[tid]; }

    GEMM_MAINLOOP()

    // ---- logits: tanh(acc + b1) . w2, reduced per row ----
#pragma unroll
    for (int mi = 0; mi < 4; mi++) {
        float p0 = 0.f, p1 = 0.f;
#pragma unroll
        for (int ni = 0; ni < 4; ni++) {
            const int c0 = wn * 32 + ni * 8 + 2 * tig;
            float t;
            t = tanhf(acc[mi][ni][0] + b1s[c0]);     p0 += t * w2s[c0];
            t = tanhf(acc[mi][ni][1] + b1s[c0 + 1]); p0 += t * w2s[c0 + 1];
            t = tanhf(acc[mi][ni][2] + b1s[c0]);     p1 += t * w2s[c0];
            t = tanhf(acc[mi][ni][3] + b1s[c0 + 1]); p1 += t * w2s[c0 + 1];
        }
        p0 += __shfl_xor_sync(0xffffffffu, p0, 1);
        p0 += __shfl_xor_sync(0xffffffffu, p0, 2);
        p1 += __shfl_xor_sync(0xffffffffu, p1, 1);
        p1 += __shfl_xor_sync(0xffffffffu, p1, 2);
        if (tig == 0) {
            atomicAdd(&rowsum[wm * 64 + mi * 16 + grp], p0);
            atomicAdd(&rowsum[wm * 64 + mi * 16 + grp + 8], p1);
        }
    }
    __syncthreads();

    // ---- per-node softmax over the 4 paths ----
    int nib = (M - bm) >> 2;
    const int nodes_in_blk = nib < 32 ? nib : 32;
    if (tid < 32 && tid < nodes_in_blk) {
        float l0 = rowsum[tid * 4], l1 = rowsum[tid * 4 + 1];
        float l2 = rowsum[tid * 4 + 2], l3 = rowsum[tid * 4 + 3];
        float m = fmaxf(fmaxf(l0, l1), fmaxf(l2, l3));
        float e0 = __expf(l0 - m), e1 = __expf(l1 - m);
        float e2 = __expf(l2 - m), e3 = __expf(l3 - m);
        float inv = 1.0f / (e0 + e1 + e2 + e3);
        rowsum[tid * 4]     = e0 * inv;
        rowsum[tid * 4 + 1] = e1 * inv;
        rowsum[tid * 4 + 2] = e2 * inv;
        rowsum[tid * 4 + 3] = e3 * inv;
    }
    __syncthreads();

    // ---- combine: out[node][d] = sum_p beta * z (z tile hot in L2) ----
    const int node0 = bm >> 2;
#pragma unroll
    for (int i = 0; i < 32; i++) {
        int idx = tid + 256 * i;
        int nl = idx >> 8;
        int dd = idx & 255;
        if (nl >= nodes_in_blk) break;
        const __half* zr = A + (long long)(bm + nl * 4) * K + dd;
        float v = rowsum[nl * 4]     * __half2float(zr[0])
                + rowsum[nl * 4 + 1] * __half2float(zr[K])
                + rowsum[nl * 4 + 2] * __half2float(zr[2 * K])
                + rowsum[nl * 4 + 3] * __half2float(zr[3 * K]);
        out[(long long)(node0 + nl) * D + dd] = v;
    }
}

// ---------------- GCN aggregation pipeline (all 4 paths batched) -----------
__global__ void k_deg_init() {
    int i = blockIdx.x * 256 + threadIdx.x;
    if (i < NG) g_deg[i] = 1;   // self loop
}

__global__ void k_hist(const int* __restrict__ eidx) {
    int e = blockIdx.x * 256 + threadIdx.x;
    if (e < NP * NE) {
        int p = e / NE, i = e - p * NE;
        int dst = eidx[(size_t)p * 2 * NE + NE + i];
        atomicAdd(&g_deg[p * NN + dst], 1);
    }
}

__global__ void k_scan1() {
    __shared__ int red[8];
    int b = blockIdx.x, tid = threadIdx.x;
    int lane = tid & 31, warp = tid >> 5;
    int i0 = b * 512 + tid * 2;
    int s = 0;
    if (i0 < NG)     s += g_deg[i0] - 1;
    if (i0 + 1 < NG) s += g_deg[i0 + 1] - 1;
#pragma unroll
    for (int o = 16; o; o >>= 1) s += __shfl_xor_sync(0xffffffffu, s, o);
    if (lane == 0) red[warp] = s;
    __syncthreads();
    if (tid == 0) {
        int t = 0;
#pragma unroll
        for (int w = 0; w < 8; w++) t += red[w];
        g_part[b] = t;
    }
}

__global__ void k_scan2() {
    __shared__ int s[512];
    int tid = threadIdx.x;
    int v = (tid < SCAN_BLK) ? g_part[tid] : 0;
    s[tid] = v;
    __syncthreads();
    for (int off = 1; off < 512; off <<= 1) {
        int u = (tid >= off) ? s[tid - off] : 0;
        __syncthreads();
        s[tid] += u;
        __syncthreads();
    }
    if (tid < SCAN_BLK) g_part[tid] = s[tid] - v;   // exclusive
}

__global__ void k_scan3() {
    __shared__ int wsum[8];
    int b = blockIdx.x, tid = threadIdx.x;
    int lane = tid & 31, warp = tid >> 5;
    int i0 = b * 512 + tid * 2;
    int d0 = (i0 < NG) ? g_deg[i0] : 1;
    int d1 = (i0 + 1 < NG) ? g_deg[i0 + 1] : 1;
    int v0 = d0 - 1, v1 = d1 - 1;
    int s = v0 + v1;
    int sc = s;
#pragma unroll
    for (int o = 1; o < 32; o <<= 1) {
        int u = __shfl_up_sync(0xffffffffu, sc, o);
        if (lane >= o) sc += u;
    }
    if (lane == 31) wsum[warp] = sc;
    __syncthreads();
    int wbase = 0;
    for (int w = 0; w < warp; w++) wbase += wsum[w];
    int base = g_part[b] + wbase + (sc - s);
    if (i0 < NG) {
        g_rowoff[i0] = base; g_rowcur[i0] = base;
        g_dinv[i0] = rsqrtf((float)d0);
    }
    if (i0 + 1 < NG) {
        g_rowoff[i0 + 1] = base + v0; g_rowcur[i0 + 1] = base + v0;
        g_dinv[i0 + 1] = rsqrtf((float)d1);
    }
    if (b == 0 && tid == 0) g_rowoff[NG] = NP * NE;
}

__global__ void k_fill(const int* __restrict__ eidx) {
    int e = blockIdx.x * 256 + threadIdx.x;
    if (e < NP * NE) {
        int p = e / NE, i = e - p * NE;
        int src = eidx[(size_t)p * 2 * NE + i];
        int dst = eidx[(size_t)p * 2 * NE + NE + i];
        int pos = atomicAdd(&g_rowcur[p * NN + dst], 1);
        g_srcs[pos] = src;
    }
}

// pull: one warp per (path,node); LDG.128 gather (lane owns 8 contiguous
// halves), 4-edge unroll, fp32 acc. z written INTERLEAVED row (node*4 + p).
__global__ void k_pull(const float* __restrict__ bs) {
    int g = blockIdx.x * 8 + (threadIdx.x >> 5);
    if (g >= NG) return;
    int lane = threadIdx.x & 31;
    int p = g / NN, node = g - p * NN;

    float di = g_dinv[g];
    const uint4* xw = (const uint4*)g_xwh + (size_t)p * (NND / 8);
    float acc[8];
    {
        uint4 v = xw[(size_t)node * 32 + lane];
        const __half2* h = (const __half2*)&v;
        float dd = di * di;
#pragma unroll
        for (int j = 0; j < 4; j++) {
            float2 f = __half22float2(h[j]);
            acc[2 * j]     = dd * f.x;
            acc[2 * j + 1] = dd * f.y;
        }
    }

    int beg = g_rowoff[g];
    int end = g_rowoff[g + 1];
    const float* dv = g_dinv + p * NN;
    int e = beg;
    for (; e + 4 <= end; e += 4) {
        int s0 = g_srcs[e], s1 = g_srcs[e + 1], s2 = g_srcs[e + 2], s3 = g_srcs[e + 3];
        float n0 = di * dv[s0], n1 = di * dv[s1], n2 = di * dv[s2], n3 = di * dv[s3];
        uint4 v0 = xw[(size_t)s0 * 32 + lane];
        uint4 v1 = xw[(size_t)s1 * 32 + lane];
        uint4 v2 = xw[(size_t)s2 * 32 + lane];
        uint4 v3 = xw[(size_t)s3 * 32 + lane];
        const __half2* h0 = (const __half2*)&v0;
        const __half2* h1 = (const __half2*)&v1;
        const __half2* h2 = (const __half2*)&v2;
        const __half2* h3 = (const __half2*)&v3;
#pragma unroll
        for (int j = 0; j < 4; j++) {
            float2 f0 = __half22float2(h0[j]);
            float2 f1 = __half22float2(h1[j]);
            float2 f2 = __half22float2(h2[j]);
            float2 f3 = __half22float2(h3[j]);
            acc[2 * j]     = fmaf(n0, f0.x, fmaf(n1, f1.x,
                             fmaf(n2, f2.x, fmaf(n3, f3.x, acc[2 * j]))));
            acc[2 * j + 1] = fmaf(n0, f0.y, fmaf(n1, f1.y,
                             fmaf(n2, f2.y, fmaf(n3, f3.y, acc[2 * j + 1]))));
        }
    }
    for (; e < end; e++) {
        int s0 = g_srcs[e];
        float n0 = di * dv[s0];
        uint4 v0 = xw[(size_t)s0 * 32 + lane];
        const __half2* h0 = (const __half2*)&v0;
#pragma unroll
        for (int j = 0; j < 4; j++) {
            float2 f0 = __half22float2(h0[j]);
            acc[2 * j]     = fmaf(n0, f0.x, acc[2 * j]);
            acc[2 * j + 1] = fmaf(n0, f0.y, acc[2 * j + 1]);
        }
    }

    // write: lane owns dims [lane*8, lane*8+8)
    int c = lane * 8;
    const float4* bp4 = (const float4*)(bs + p * D + c);
    float4 b0 = bp4[0], b1 = bp4[1];
    uint4 o;
    __half2* oh = (__half2*)&o;
    oh[0] = __floats2half2_rn(acc[0] + b0.x, acc[1] + b0.y);
    oh[1] = __floats2half2_rn(acc[2] + b0.z, acc[3] + b0.w);
    oh[2] = __floats2half2_rn(acc[4] + b1.x, acc[5] + b1.y);
    oh[3] = __floats2half2_rn(acc[6] + b1.z, acc[7] + b1.w);
    ((uint4*)g_zh)[((size_t)node * NP + p) * 32 + lane] = o;
}

// ---------------- launch ----------------------------------------------------
extern "C" void kernel_launch(void* const* d_in, const int* in_sizes, int n_in,
                              void* d_out, int out_size) {
    const float* x    = (const float*)d_in[0];
    const int*   eidx = (const int*)d_in[1];
    const float* Ws   = (const float*)d_in[2];
    const float* bs   = (const float*)d_in[3];
    const float* w1   = (const float*)d_in[4];
    const float* b1   = (const float*)d_in[5];
    const float* w2   = (const float*)d_in[6];
    float* out = (float*)d_out;

    void* p_xh = nullptr; void* p_wsT = nullptr; void* p_w1T = nullptr;
    void* p_xwh = nullptr; void* p_zh = nullptr;
    cudaGetSymbolAddress(&p_xh,  g_xh);
    cudaGetSymbolAddress(&p_wsT, g_wsT);
    cudaGetSymbolAddress(&p_w1T, g_w1T);
    cudaGetSymbolAddress(&p_xwh, g_xwh);
    cudaGetSymbolAddress(&p_zh,  g_zh);

    cudaFuncSetAttribute(k_gemm_xw,
        cudaFuncAttributeMaxDynamicSharedMemorySize, DYNBYTES);
    cudaFuncSetAttribute(k_gemm_attn,
        cudaFuncAttributeMaxDynamicSharedMemorySize, DYNBYTES);

    // one-time side stream + fork/join events (no device memory involved;
    // every call performs the identical launch sequence)
    static cudaStream_t s_side = nullptr;
    static cudaEvent_t  s_fork = nullptr, s_join = nullptr;
    if (s_side == nullptr) {
        cudaStreamCreateWithFlags(&s_side, cudaStreamNonBlocking);
        cudaEventCreateWithFlags(&s_fork, cudaEventDisableTiming);
        cudaEventCreateWithFlags(&s_join, cudaEventDisableTiming);
    }

    // ---- fork: CSR build (depends only on eidx) on side stream ----
    cudaEventRecord(s_fork, 0);
    cudaStreamWaitEvent(s_side, s_fork, 0);
    k_deg_init<<<(NG + 255) / 256, 256, 0, s_side>>>();
    k_hist<<<(NP * NE + 255) / 256, 256, 0, s_side>>>(eidx);
    k_scan1<<<SCAN_BLK, 256, 0, s_side>>>();
    k_scan2<<<1, 512, 0, s_side>>>();
    k_scan3<<<SCAN_BLK, 256, 0, s_side>>>();
    k_fill<<<(NP * NE + 255) / 256, 256, 0, s_side>>>(eidx);
    cudaEventRecord(s_join, s_side);

    // ---- main: fp16 prep + feature GEMM ----
    k_cvt_x<<<(NND / 4 + 255) / 256, 256>>>(x);
    k_cvt_wT<<<dim3(D / 32, D / 32, NP), dim3(32, 8)>>>(Ws, (__half*)p_wsT, D, D);
    k_cvt_wT<<<dim3(D / 32, DH / 32, 1), dim3(32, 8)>>>(w1, (__half*)p_w1T, D, DH);
    k_gemm_xw<<<dim3(D / 128, (NN + 127) / 128, NP), 256, DYNBYTES>>>(
        (const __half*)p_xh, (const __half*)p_wsT, (__half*)p_xwh, NN, D,
        (long long)D * D, (long long)NND);

    // ---- join: pull needs both chains ----
    cudaStreamWaitEvent(0, s_join, 0);
    k_pull<<<(NG + 7) / 8, 256>>>(bs);

    // fused: logits + softmax + combine -> out
    k_gemm_attn<<<dim3(1, (NROWS + 127) / 128), 256, DYNBYTES>>>(
        (const __half*)p_zh, (const __half*)p_w1T, b1, w2, out, NROWS);
}